// round 7
// baseline (speedup 1.0000x reference)
#include <cuda_runtime.h>
#include <math.h>

// Problem constants
#define BB   512
#define LL   71
#define DD   512
#define HH   8
#define DHH  64
#define MROWS (BB * LL)          // 36352
#define NHEADS (BB * HH)         // 4096
#define HEAD_ELEMS (LL * DHH)    // 4544
#define MM (NHEADS * LL)         // 290816 = 2272 * 128  (flat score rows)

// ---------------------------------------------------------------------------
// Scratch (static device globals)
// ---------------------------------------------------------------------------
__device__ float g_Tq[DD * MROWS];         // transposed tf32 activations [512][M]
__device__ float g_Tk[DD * MROWS];
__device__ float g_Tv[DD * MROWS];
__device__ float g_Q[NHEADS * HEAD_ELEMS]; // [bh][l][dh], Q pre-scaled by 1/8
__device__ float g_K[NHEADS * HEAD_ELEMS]; // [bh][l][dh]
__device__ float g_V[NHEADS * HEAD_ELEMS]; // [bh][l][dh]
__device__ float g_St[72 * MM];            // scores k-major [key][bh*71+q] (row 71 = 0)
__device__ float g_Ht[128 * MM];           // gelu hidden k-major [ff][bh*71+q]
__device__ float g_attnT[DD * MROWS];      // [d][m] tf32 (k-major for out proj)

__device__ __forceinline__ float to_tf32(float x) {
    float y;
    asm("cvt.rna.tf32.f32 %0, %1;" : "=f"(y) : "f"(x));
    return y;
}

__device__ __forceinline__ void mma_tf32(float* c, const unsigned* a, const unsigned* b) {
    asm volatile(
        "mma.sync.aligned.m16n8k8.row.col.f32.tf32.tf32.f32 "
        "{%0,%1,%2,%3}, {%4,%5,%6,%7}, {%8,%9}, {%0,%1,%2,%3};"
        : "+f"(c[0]), "+f"(c[1]), "+f"(c[2]), "+f"(c[3])
        : "r"(a[0]), "r"(a[1]), "r"(a[2]), "r"(a[3]), "r"(b[0]), "r"(b[1]));
}

__device__ __forceinline__ float gelu_exact(float x) {
    return 0.5f * x * (1.f + erff(x * 0.70710678118654752f));
}

// ---------------------------------------------------------------------------
// Transpose + tf32 convert: in [M][512] fp32 -> out [512][M] tf32.
// ---------------------------------------------------------------------------
__global__ void __launch_bounds__(256) transpose_cvt_kernel(
    const float* __restrict__ in0, const float* __restrict__ in1,
    const float* __restrict__ in2,
    float* __restrict__ out0, float* __restrict__ out1, float* __restrict__ out2)
{
    __shared__ float sm[32][33];
    const float* in = (blockIdx.z == 0) ? in0 : (blockIdx.z == 1 ? in1 : in2);
    float* out      = (blockIdx.z == 0) ? out0 : (blockIdx.z == 1 ? out1 : out2);
    const int m0 = blockIdx.x * 32, k0 = blockIdx.y * 32;
    const int tx = threadIdx.x & 31, ty = threadIdx.x >> 5;
    #pragma unroll
    for (int j = 0; j < 4; j++)
        sm[ty + 8 * j][tx] = in[(size_t)(m0 + ty + 8 * j) * 512 + k0 + tx];
    __syncthreads();
    #pragma unroll
    for (int j = 0; j < 4; j++)
        out[(size_t)(k0 + ty + 8 * j) * MROWS + m0 + tx] = to_tf32(sm[tx][ty + 8 * j]);
}

// ---------------------------------------------------------------------------
// tf32 GEMM core: CTA 128x128, K=512, KC=32, double-buffered smem.
// ---------------------------------------------------------------------------
__device__ __forceinline__ void gemm_tf32_ctile(
    const float* __restrict__ AT, const float* __restrict__ W,
    float (&c)[4][4][4])
{
    extern __shared__ float sm[];
    float* As = sm;            // [2][32][136]
    float* Bs = sm + 8704;

    const int tid  = threadIdx.x;
    const int lane = tid & 31;
    const int warp = tid >> 5;
    const int mBase = blockIdx.y * 128;
    const int nBase = blockIdx.x * 128;

    #pragma unroll
    for (int im = 0; im < 4; im++)
        #pragma unroll
        for (int in = 0; in < 4; in++)
            #pragma unroll
            for (int q = 0; q < 4; q++) c[im][in][q] = 0.f;

    auto ldgA = [&](int kt, float4 (&ra)[4]) {
        #pragma unroll
        for (int it = 0; it < 4; it++) {
            int idx = it * 256 + tid;
            int k = idx >> 5, m4 = (idx & 31) << 2;
            ra[it] = *(const float4*)(AT + (size_t)(kt * 32 + k) * MROWS + mBase + m4);
        }
    };
    auto ldgB = [&](int kt, float4 (&rb)[4]) {
        #pragma unroll
        for (int it = 0; it < 4; it++) {
            int idx = it * 256 + tid;
            int k = idx >> 5, n4 = (idx & 31) << 2;
            rb[it] = *(const float4*)(W + (size_t)(kt * 32 + k) * 512 + nBase + n4);
        }
    };
    auto stsA = [&](int buf, float4 (&ra)[4]) {
        #pragma unroll
        for (int it = 0; it < 4; it++) {
            int idx = it * 256 + tid;
            int k = idx >> 5, m4 = (idx & 31) << 2;
            *(float4*)&As[buf * 4352 + k * 136 + m4] = ra[it];
        }
    };
    auto stsB = [&](int buf, float4 (&rb)[4]) {
        #pragma unroll
        for (int it = 0; it < 4; it++) {
            int idx = it * 256 + tid;
            int k = idx >> 5, n4 = (idx & 31) << 2;
            float4 v = rb[it];
            v.x = to_tf32(v.x); v.y = to_tf32(v.y);
            v.z = to_tf32(v.z); v.w = to_tf32(v.w);
            *(float4*)&Bs[buf * 4352 + k * 136 + n4] = v;
        }
    };
    auto compute = [&](int buf) {
        const float* Asb = As + buf * 4352;
        const float* Bsb = Bs + buf * 4352;
        const int r0 = (warp & 1) * 64 + (lane >> 2);
        const int n0 = (warp >> 1) * 32 + (lane >> 2);
        #pragma unroll
        for (int s = 0; s < 4; s++) {
            const int kk = s * 8 + (lane & 3);
            unsigned a[4][4], b[4][2];
            #pragma unroll
            for (int im = 0; im < 4; im++) {
                a[im][0] = __float_as_uint(Asb[kk * 136 + r0 + im * 16]);
                a[im][1] = __float_as_uint(Asb[kk * 136 + r0 + im * 16 + 8]);
                a[im][2] = __float_as_uint(Asb[(kk + 4) * 136 + r0 + im * 16]);
                a[im][3] = __float_as_uint(Asb[(kk + 4) * 136 + r0 + im * 16 + 8]);
            }
            #pragma unroll
            for (int in = 0; in < 4; in++) {
                b[in][0] = __float_as_uint(Bsb[kk * 136 + n0 + in * 8]);
                b[in][1] = __float_as_uint(Bsb[(kk + 4) * 136 + n0 + in * 8]);
            }
            #pragma unroll
            for (int im = 0; im < 4; im++)
                #pragma unroll
                for (int in = 0; in < 4; in++)
                    mma_tf32(c[im][in], a[im], b[in]);
        }
    };

    float4 ra[4], rb[4];
    ldgA(0, ra); ldgB(0, rb);
    stsA(0, ra); stsB(0, rb);
    __syncthreads();
    #pragma unroll 1
    for (int kt = 0; kt < 16; kt++) {
        const int cur = kt & 1;
        if (kt < 15) { ldgA(kt + 1, ra); ldgB(kt + 1, rb); }
        compute(cur);
        if (kt < 15) { stsA(cur ^ 1, ra); stsB(cur ^ 1, rb); }
        __syncthreads();
    }
}

// ---------------------------------------------------------------------------
// QKV projection: grid (4, 284, 3). Coalesced float2 epilogue to [b,h,l,dh].
// ---------------------------------------------------------------------------
__global__ void __launch_bounds__(256) qkv_gemm_kernel(
    const float* __restrict__ Wq, const float* __restrict__ bq,
    const float* __restrict__ Wk, const float* __restrict__ bk,
    const float* __restrict__ Wv, const float* __restrict__ bv)
{
    const float* AT; const float* W; const float* bias; float* out; float scale;
    if (blockIdx.z == 0)      { AT = g_Tq; W = Wq; bias = bq; out = g_Q; scale = 0.125f; }
    else if (blockIdx.z == 1) { AT = g_Tk; W = Wk; bias = bk; out = g_K; scale = 1.0f; }
    else                      { AT = g_Tv; W = Wv; bias = bv; out = g_V; scale = 1.0f; }

    float c[4][4][4];
    gemm_tf32_ctile(AT, W, c);

    const int lane = threadIdx.x & 31, warp = threadIdx.x >> 5;
    const int mBase = blockIdx.y * 128, nBase = blockIdx.x * 128;

    float bv2[4][2];
    #pragma unroll
    for (int in = 0; in < 4; in++) {
        int cg = nBase + (warp >> 1) * 32 + in * 8 + 2 * (lane & 3);
        bv2[in][0] = bias[cg]; bv2[in][1] = bias[cg + 1];
    }
    #pragma unroll
    for (int im = 0; im < 4; im++) {
        int rg0 = mBase + (warp & 1) * 64 + im * 16 + (lane >> 2);
        int rg1 = rg0 + 8;
        int b0 = rg0 / 71, l0 = rg0 - b0 * 71;
        int b1 = rg1 / 71, l1 = rg1 - b1 * 71;
        #pragma unroll
        for (int in = 0; in < 4; in++) {
            int cg = nBase + (warp >> 1) * 32 + in * 8 + 2 * (lane & 3);
            int h = cg >> 6, dh = cg & 63;
            float2 v0 = make_float2((c[im][in][0] + bv2[in][0]) * scale,
                                    (c[im][in][1] + bv2[in][1]) * scale);
            float2 v1 = make_float2((c[im][in][2] + bv2[in][0]) * scale,
                                    (c[im][in][3] + bv2[in][1]) * scale);
            *(float2*)&out[(((size_t)(b0 * 8 + h) * 71 + l0) << 6) + dh] = v0;
            *(float2*)&out[(((size_t)(b1 * 8 + h) * 71 + l1) << 6) + dh] = v1;
        }
    }
}

// ---------------------------------------------------------------------------
// Output projection: grid (4, 284).
// ---------------------------------------------------------------------------
__global__ void __launch_bounds__(256) out_gemm_kernel(
    float* __restrict__ out, const float* __restrict__ Wo,
    const float* __restrict__ bo)
{
    float c[4][4][4];
    gemm_tf32_ctile(g_attnT, Wo, c);

    const int lane = threadIdx.x & 31, warp = threadIdx.x >> 5;
    const int mBase = blockIdx.y * 128, nBase = blockIdx.x * 128;

    float bv2[4][2];
    #pragma unroll
    for (int in = 0; in < 4; in++) {
        int cg = nBase + (warp >> 1) * 32 + in * 8 + 2 * (lane & 3);
        bv2[in][0] = bo[cg]; bv2[in][1] = bo[cg + 1];
    }
    #pragma unroll
    for (int im = 0; im < 4; im++) {
        int rg0 = mBase + (warp & 1) * 64 + im * 16 + (lane >> 2);
        int rg1 = rg0 + 8;
        #pragma unroll
        for (int in = 0; in < 4; in++) {
            int cg = nBase + (warp >> 1) * 32 + in * 8 + 2 * (lane & 3);
            float2 v0 = make_float2(c[im][in][0] + bv2[in][0], c[im][in][1] + bv2[in][1]);
            float2 v1 = make_float2(c[im][in][2] + bv2[in][0], c[im][in][3] + bv2[in][1]);
            *(float2*)&out[(size_t)rg0 * 512 + cg] = v0;
            *(float2*)&out[(size_t)rg1 * 512 + cg] = v1;
        }
    }
}

// ---------------------------------------------------------------------------
// 1) Batched QK^T: one head per CTA, 256 threads (8 warps).
//    S[key][m] = (Q/8) @ K^T, written tf32 to g_St (key row 71 -> 0).
// ---------------------------------------------------------------------------
template<int NS>
__device__ __forceinline__ void qk_warp(
    const float* __restrict__ sQ, const float* __restrict__ sK,
    int w, int lane, size_t mb)
{
    float acc[NS][5][4] = {};
    #pragma unroll
    for (int ks = 0; ks < 8; ks++) {
        const int cc = ks * 8 + (lane & 3);
        unsigned bfr[NS][2];
        #pragma unroll
        for (int s = 0; s < NS; s++) {
            const int n = (w + s * 8) * 8 + (lane >> 2);
            bfr[s][0] = __float_as_uint(sK[n * 72 + cc]);
            bfr[s][1] = __float_as_uint(sK[n * 72 + cc + 4]);
        }
        #pragma unroll
        for (int mt = 0; mt < 5; mt++) {
            const int r = mt * 16 + (lane >> 2);
            unsigned afr[4];
            afr[0] = __float_as_uint(sQ[r * 72 + cc]);
            afr[1] = __float_as_uint(sQ[(r + 8) * 72 + cc]);
            afr[2] = __float_as_uint(sQ[r * 72 + cc + 4]);
            afr[3] = __float_as_uint(sQ[(r + 8) * 72 + cc + 4]);
            #pragma unroll
            for (int s = 0; s < NS; s++) mma_tf32(acc[s][mt], afr, bfr[s]);
        }
    }
    #pragma unroll
    for (int s = 0; s < NS; s++) {
        const int n0 = (w + s * 8) * 8 + 2 * (lane & 3);
        #pragma unroll
        for (int mt = 0; mt < 5; mt++) {
            const int r = mt * 16 + (lane >> 2);
            if (r < 71) {
                g_St[(size_t)n0 * MM + mb + r]       = to_tf32(acc[s][mt][0]);
                g_St[(size_t)(n0 + 1) * MM + mb + r] = to_tf32(acc[s][mt][1]);
            }
            if (r + 8 < 71) {
                g_St[(size_t)n0 * MM + mb + r + 8]       = to_tf32(acc[s][mt][2]);
                g_St[(size_t)(n0 + 1) * MM + mb + r + 8] = to_tf32(acc[s][mt][3]);
            }
        }
    }
}

__global__ void __launch_bounds__(256) qk_kernel()
{
    __shared__ float sQ[80 * 72];
    __shared__ float sK[72 * 72];
    const int tid = threadIdx.x;
    const int lane = tid & 31, w = tid >> 5;
    const int bh = blockIdx.x;
    const size_t mb = (size_t)bh * 71;

    const float* Qg = g_Q + (size_t)bh * HEAD_ELEMS;
    const float* Kg = g_K + (size_t)bh * HEAD_ELEMS;
    for (int i = tid; i < HEAD_ELEMS; i += 256) {
        int l = i >> 6, dh = i & 63;
        sQ[l * 72 + dh] = to_tf32(Qg[i]);
        sK[l * 72 + dh] = to_tf32(Kg[i]);
    }
    for (int i = tid; i < 9 * 72; i += 256) sQ[71 * 72 + i] = 0.f;
    if (tid < 72) sK[71 * 72 + tid] = 0.f;
    __syncthreads();

    if (w == 0) qk_warp<2>(sQ, sK, w, lane, mb);
    else        qk_warp<1>(sQ, sK, w, lane, mb);
}

// ---------------------------------------------------------------------------
// 2) MLP1 flat GEMM: H = gelu(S @ w1 + b1).  M=290816 (tiles of 128), K=72,
//    N=128.  A = g_St (k-major), B = w1 (tf32-cvt, row 71 zero).
//    Output transposed tf32 to g_Ht[ff][m].  Grid 2272, 256 thr.
// ---------------------------------------------------------------------------
__global__ void __launch_bounds__(256) mlp1_kernel(
    const float* __restrict__ w1, const float* __restrict__ b1)
{
    extern __shared__ float smem[];
    float* As = smem;          // [72][136]
    float* Bs = smem + 9792;   // [72][136]

    const int tid = threadIdx.x;
    const int lane = tid & 31, warp = tid >> 5;
    const int mBase = blockIdx.x * 128;

    #pragma unroll
    for (int it = 0; it < 9; it++) {
        int idx = it * 256 + tid;
        int k = idx >> 5, c4 = (idx & 31) << 2;
        *(float4*)&As[k * 136 + c4] = *(const float4*)(g_St + (size_t)k * MM + mBase + c4);
        float4 bvec;
        if (k < 71) {
            bvec = *(const float4*)(w1 + k * 128 + c4);
            bvec.x = to_tf32(bvec.x); bvec.y = to_tf32(bvec.y);
            bvec.z = to_tf32(bvec.z); bvec.w = to_tf32(bvec.w);
        } else bvec = make_float4(0.f, 0.f, 0.f, 0.f);
        *(float4*)&Bs[k * 136 + c4] = bvec;
    }
    __syncthreads();

    float c[4][4][4] = {};
    const int r0 = (warp & 1) * 64 + (lane >> 2);
    const int n0 = (warp >> 1) * 32 + (lane >> 2);
    #pragma unroll
    for (int s = 0; s < 9; s++) {
        const int kk = s * 8 + (lane & 3);
        unsigned a[4][4], b[4][2];
        #pragma unroll
        for (int im = 0; im < 4; im++) {
            a[im][0] = __float_as_uint(As[kk * 136 + r0 + im * 16]);
            a[im][1] = __float_as_uint(As[kk * 136 + r0 + im * 16 + 8]);
            a[im][2] = __float_as_uint(As[(kk + 4) * 136 + r0 + im * 16]);
            a[im][3] = __float_as_uint(As[(kk + 4) * 136 + r0 + im * 16 + 8]);
        }
        #pragma unroll
        for (int in = 0; in < 4; in++) {
            b[in][0] = __float_as_uint(Bs[kk * 136 + n0 + in * 8]);
            b[in][1] = __float_as_uint(Bs[(kk + 4) * 136 + n0 + in * 8]);
        }
        #pragma unroll
        for (int im = 0; im < 4; im++)
            #pragma unroll
            for (int in = 0; in < 4; in++)
                mma_tf32(c[im][in], a[im], b[in]);
    }

    #pragma unroll
    for (int in = 0; in < 4; in++) {
        const int cg = (warp >> 1) * 32 + in * 8 + 2 * (lane & 3);
        const float bb0 = __ldg(b1 + cg), bb1 = __ldg(b1 + cg + 1);
        #pragma unroll
        for (int im = 0; im < 4; im++) {
            const int rg0 = mBase + (warp & 1) * 64 + im * 16 + (lane >> 2);
            g_Ht[(size_t)cg * MM + rg0]           = to_tf32(gelu_exact(c[im][in][0] + bb0));
            g_Ht[(size_t)(cg + 1) * MM + rg0]     = to_tf32(gelu_exact(c[im][in][1] + bb1));
            g_Ht[(size_t)cg * MM + rg0 + 8]       = to_tf32(gelu_exact(c[im][in][2] + bb0));
            g_Ht[(size_t)(cg + 1) * MM + rg0 + 8] = to_tf32(gelu_exact(c[im][in][3] + bb1));
        }
    }
}

// ---------------------------------------------------------------------------
// 3) MLP2 flat GEMM + residual: S += H @ w2 + b2 (in place on g_St).
//    M tiles of 128, K=128, N=72 (col 71 zero).  Grid 2272, 256 thr.
//    Warp (mh, nq): covers n-tiles {2nq, 2nq+1} (+ tile 8 for nq==0).
// ---------------------------------------------------------------------------
template<int NS>
__device__ __forceinline__ void mlp2_warp(
    const float* __restrict__ As, const float* __restrict__ Bs,
    const float* __restrict__ b2, int mh, int nq, int lane, int mBase)
{
    float acc[NS][4][4] = {};
    const int r0 = mh * 64 + (lane >> 2);
    int tiles[3];
    tiles[0] = nq * 2; tiles[1] = nq * 2 + 1; if (NS == 3) tiles[2] = 8;

    #pragma unroll
    for (int ks = 0; ks < 16; ks++) {
        const int kk = ks * 8 + (lane & 3);
        unsigned b[NS][2];
        #pragma unroll
        for (int s = 0; s < NS; s++) {
            const int n = tiles[s] * 8 + (lane >> 2);
            b[s][0] = __float_as_uint(Bs[kk * 72 + n]);
            b[s][1] = __float_as_uint(Bs[(kk + 4) * 72 + n]);
        }
        #pragma unroll
        for (int im = 0; im < 4; im++) {
            unsigned a[4];
            const float* p = As + kk * 136 + r0 + im * 16;
            a[0] = __float_as_uint(p[0]);
            a[1] = __float_as_uint(p[8]);
            a[2] = __float_as_uint(p[136 * 4]);
            a[3] = __float_as_uint(p[136 * 4 + 8]);
            #pragma unroll
            for (int s = 0; s < NS; s++) mma_tf32(acc[s][im], a, b[s]);
        }
    }
    #pragma unroll
    for (int s = 0; s < NS; s++) {
        const int cg = tiles[s] * 8 + 2 * (lane & 3);
        const float bb0 = __ldg(b2 + cg);                       // cg <= 70 always
        const float bb1 = (cg + 1 < 71) ? __ldg(b2 + cg + 1) : 0.f;
        #pragma unroll
        for (int im = 0; im < 4; im++) {
            const int rg0 = mBase + mh * 64 + im * 16 + (lane >> 2);
            float* p0 = g_St + (size_t)cg * MM + rg0;
            float* p1 = g_St + (size_t)(cg + 1) * MM + rg0;
            p0[0] += acc[s][im][0] + bb0;
            p1[0] += acc[s][im][1] + bb1;
            p0[8] += acc[s][im][2] + bb0;
            p1[8] += acc[s][im][3] + bb1;
        }
    }
}

__global__ void __launch_bounds__(256) mlp2_kernel(
    const float* __restrict__ w2, const float* __restrict__ b2)
{
    extern __shared__ float smem[];
    float* As = smem;           // [128][136]
    float* Bs = smem + 17408;   // [128][72]

    const int tid = threadIdx.x;
    const int lane = tid & 31, warp = tid >> 5;
    const int mBase = blockIdx.x * 128;

    #pragma unroll
    for (int it = 0; it < 16; it++) {
        int idx = it * 256 + tid;
        int k = idx >> 5, c4 = (idx & 31) << 2;
        *(float4*)&As[k * 136 + c4] = *(const float4*)(g_Ht + (size_t)k * MM + mBase + c4);
    }
    for (int i = tid; i < 128 * 72; i += 256) {
        int k = i / 72, n = i - k * 72;
        Bs[i] = (n < 71) ? to_tf32(__ldg(w2 + k * 71 + n)) : 0.f;
    }
    __syncthreads();

    const int mh = warp & 1, nq = warp >> 1;
    if (nq == 0) mlp2_warp<3>(As, Bs, b2, mh, nq, lane, mBase);
    else         mlp2_warp<2>(As, Bs, b2, mh, nq, lane, mBase);
}

// ---------------------------------------------------------------------------
// 4) Softmax + PV: one head per CTA, 256 threads.
//    sP [72 keys][88 q] from g_St; warp-parallel softmax over key dim per q;
//    attn = P @ V -> g_attnT[d][m].
// ---------------------------------------------------------------------------
__global__ void __launch_bounds__(256) pv_kernel()
{
    __shared__ float sP[72 * 88];
    __shared__ float sV[72 * 72];
    const int tid = threadIdx.x;
    const int lane = tid & 31, w = tid >> 5;
    const int bh = blockIdx.x;
    const int bidx = bh >> 3, hidx = bh & 7;
    const size_t mb = (size_t)bh * 71;

    // load scores tile (rows = key, cols = q; pad q cols with 0)
    for (int k = w; k < 72; k += 8)
        for (int q = lane; q < 88; q += 32)
            sP[k * 88 + q] = (q < 71) ? g_St[(size_t)k * MM + mb + q] : 0.f;
    // load V (row 71 zero)
    {
        const float* Vg = g_V + (size_t)bh * HEAD_ELEMS;
        for (int i = tid; i < HEAD_ELEMS; i += 256) {
            int l = i >> 6, dh = i & 63;
            sV[l * 72 + dh] = to_tf32(Vg[i]);
        }
        if (tid < 72) sV[71 * 72 + tid] = 0.f;
    }
    __syncthreads();

    // softmax over keys (71) for each q column; warp per column
    for (int col = w; col < 71; col += 8) {
        float v0 = sP[lane * 88 + col];
        float v1 = (lane + 32 < 71) ? sP[(lane + 32) * 88 + col] : -1e30f;
        float v2 = (lane < 7)       ? sP[(lane + 64) * 88 + col] : -1e30f;
        float m = fmaxf(v0, fmaxf(v1, v2));
        #pragma unroll
        for (int o = 16; o > 0; o >>= 1) m = fmaxf(m, __shfl_xor_sync(0xffffffffu, m, o));
        float e0 = __expf(v0 - m);
        float e1 = (lane + 32 < 71) ? __expf(v1 - m) : 0.f;
        float e2 = (lane < 7)       ? __expf(v2 - m) : 0.f;
        float s = e0 + e1 + e2;
        #pragma unroll
        for (int o = 16; o > 0; o >>= 1) s += __shfl_xor_sync(0xffffffffu, s, o);
        float inv = 1.f / s;
        sP[lane * 88 + col] = to_tf32(e0 * inv);
        if (lane + 32 < 71) sP[(lane + 32) * 88 + col] = to_tf32(e1 * inv);
        if (lane < 7)       sP[(lane + 64) * 88 + col] = to_tf32(e2 * inv);
    }
    __syncthreads();

    // PV: M=80 (q), N=64 (dh tile per warp), K=72 (keys)
    float acc[5][4] = {};
    #pragma unroll
    for (int ks = 0; ks < 9; ks++) {
        const int kk = ks * 8 + (lane & 3);
        unsigned bfr[2];
        const int n = w * 8 + (lane >> 2);
        bfr[0] = __float_as_uint(sV[kk * 72 + n]);
        bfr[1] = __float_as_uint(sV[(kk + 4) * 72 + n]);
        #pragma unroll
        for (int mt = 0; mt < 5; mt++) {
            const float* p = sP + kk * 88 + mt * 16 + (lane >> 2);
            unsigned afr[4];
            afr[0] = __float_as_uint(p[0]);
            afr[1] = __float_as_uint(p[8]);
            afr[2] = __float_as_uint(p[88 * 4]);
            afr[3] = __float_as_uint(p[88 * 4 + 8]);
            mma_tf32(acc[mt], afr, bfr);
        }
    }
    const int n0 = w * 8 + 2 * (lane & 3);
    const size_t d0 = (size_t)(hidx * 64 + n0);
    #pragma unroll
    for (int mt = 0; mt < 5; mt++) {
        int r = mt * 16 + (lane >> 2);
        if (r < 71) {
            size_t mg = (size_t)bidx * 71 + r;
            g_attnT[d0 * MROWS + mg]       = to_tf32(acc[mt][0]);
            g_attnT[(d0 + 1) * MROWS + mg] = to_tf32(acc[mt][1]);
        }
        if (r + 8 < 71) {
            size_t mg = (size_t)bidx * 71 + r + 8;
            g_attnT[d0 * MROWS + mg]       = to_tf32(acc[mt][2]);
            g_attnT[(d0 + 1) * MROWS + mg] = to_tf32(acc[mt][3]);
        }
    }
}

// ---------------------------------------------------------------------------
extern "C" void kernel_launch(void* const* d_in, const int* in_sizes, int n_in,
                              void* d_out, int out_size)
{
    const float* query = (const float*)d_in[0];
    const float* key   = (const float*)d_in[1];
    const float* value = (const float*)d_in[2];
    const float* Wq = (const float*)d_in[3];
    const float* bq = (const float*)d_in[4];
    const float* Wk = (const float*)d_in[5];
    const float* bk = (const float*)d_in[6];
    const float* Wv = (const float*)d_in[7];
    const float* bv = (const float*)d_in[8];
    const float* Wo = (const float*)d_in[9];
    const float* bo = (const float*)d_in[10];
    const float* sf_w1 = (const float*)d_in[11];
    const float* sf_b1 = (const float*)d_in[12];
    const float* sf_w2 = (const float*)d_in[13];
    const float* sf_b2 = (const float*)d_in[14];
    float* out = (float*)d_out;

    float *dTq, *dTk, *dTv;
    cudaGetSymbolAddress((void**)&dTq, g_Tq);
    cudaGetSymbolAddress((void**)&dTk, g_Tk);
    cudaGetSymbolAddress((void**)&dTv, g_Tv);

    const int gemm_smem = 17408 * sizeof(float);    // 69632 B
    cudaFuncSetAttribute(qkv_gemm_kernel, cudaFuncAttributeMaxDynamicSharedMemorySize, gemm_smem);
    cudaFuncSetAttribute(out_gemm_kernel, cudaFuncAttributeMaxDynamicSharedMemorySize, gemm_smem);
    const int mlp1_smem = 19584 * sizeof(float);    // 78336 B
    cudaFuncSetAttribute(mlp1_kernel, cudaFuncAttributeMaxDynamicSharedMemorySize, mlp1_smem);
    const int mlp2_smem = 26624 * sizeof(float);    // 106496 B
    cudaFuncSetAttribute(mlp2_kernel, cudaFuncAttributeMaxDynamicSharedMemorySize, mlp2_smem);

    // 1) transpose+cvt activations
    dim3 gt(MROWS / 32, 16, 3);
    transpose_cvt_kernel<<<gt, 256>>>(query, key, value, dTq, dTk, dTv);

    // 2) QKV projections
    dim3 g1(4, 284, 3);
    qkv_gemm_kernel<<<g1, 256, gemm_smem>>>(Wq, bq, Wk, bk, Wv, bv);

    // 3) attention core, decomposed
    qk_kernel<<<NHEADS, 256>>>();
    mlp1_kernel<<<MM / 128, 256, mlp1_smem>>>(sf_w1, sf_b1);
    mlp2_kernel<<<MM / 128, 256, mlp2_smem>>>(sf_w2, sf_b2);
    pv_kernel<<<NHEADS, 256>>>();

    // 4) output projection
    dim3 g3(4, 284);
    out_gemm_kernel<<<g3, 256, gemm_smem>>>(out, Wo, bo);
}

// round 9
// speedup vs baseline: 1.6112x; 1.6112x over previous
#include <cuda_runtime.h>
#include <math.h>

// Problem constants
#define BB   512
#define LL   71
#define DD   512
#define HH   8
#define DHH  64
#define MROWS (BB * LL)          // 36352
#define NHEADS (BB * HH)         // 4096
#define HEAD_ELEMS (LL * DHH)    // 4544

// ---------------------------------------------------------------------------
// Scratch (static device globals)
// ---------------------------------------------------------------------------
__device__ float g_Tq[DD * MROWS];          // transposed tf32 activations [512][M]
__device__ float g_Tk[DD * MROWS];
__device__ float g_Tv[DD * MROWS];
__device__ float g_Qt[NHEADS * HEAD_ELEMS]; // [bh][dh][l], Q pre-scaled by 1/8
__device__ float g_Kt[NHEADS * HEAD_ELEMS]; // [bh][dh][l]
__device__ float g_V [NHEADS * HEAD_ELEMS]; // [bh][l][dh]
__device__ float g_attnT[DD * MROWS];       // [d][m] tf32 (k-major for out proj)
__device__ float g_w1p[72 * 128];           // padded tf32 w1 (row 71 = 0)
__device__ float g_w2p[128 * 72];           // padded tf32 w2 (col 71 = 0)

__device__ __forceinline__ float to_tf32(float x) {
    float y;
    asm("cvt.rna.tf32.f32 %0, %1;" : "=f"(y) : "f"(x));
    return y;
}

__device__ __forceinline__ void mma_tf32(float* c, const unsigned* a, const unsigned* b) {
    asm volatile(
        "mma.sync.aligned.m16n8k8.row.col.f32.tf32.tf32.f32 "
        "{%0,%1,%2,%3}, {%4,%5,%6,%7}, {%8,%9}, {%0,%1,%2,%3};"
        : "+f"(c[0]), "+f"(c[1]), "+f"(c[2]), "+f"(c[3])
        : "r"(a[0]), "r"(a[1]), "r"(a[2]), "r"(a[3]), "r"(b[0]), "r"(b[1]));
}

__device__ __forceinline__ float gelu_exact(float x) {
    return 0.5f * x * (1.f + erff(x * 0.70710678118654752f));
}

// A fragment: A[m][k] stored k-major base[k*stride + m]
#define LDA(frag, base, stride, mt, kk) { \
    const float* p_ = (base) + (kk) * (stride) + (mt) * 16 + (lane >> 2); \
    frag[0] = __float_as_uint(p_[0]); \
    frag[1] = __float_as_uint(p_[8]); \
    frag[2] = __float_as_uint(p_[(stride) * 4]); \
    frag[3] = __float_as_uint(p_[(stride) * 4 + 8]); }

// B fragment: B[k][n] k-major base[k*stride + n]
#define LDB(frag, base, stride, nt, kk) { \
    const float* p_ = (base) + (kk) * (stride) + (nt) * 8 + (lane >> 2); \
    frag[0] = __float_as_uint(p_[0]); \
    frag[1] = __float_as_uint(p_[(stride) * 4]); }

// ---------------------------------------------------------------------------
// Transpose + tf32 convert: in [M][512] fp32 -> out [512][M] tf32.
// ---------------------------------------------------------------------------
__global__ void __launch_bounds__(256) transpose_cvt_kernel(
    const float* __restrict__ in0, const float* __restrict__ in1,
    const float* __restrict__ in2,
    float* __restrict__ out0, float* __restrict__ out1, float* __restrict__ out2)
{
    __shared__ float sm[32][33];
    const float* in = (blockIdx.z == 0) ? in0 : (blockIdx.z == 1 ? in1 : in2);
    float* out      = (blockIdx.z == 0) ? out0 : (blockIdx.z == 1 ? out1 : out2);
    const int m0 = blockIdx.x * 32, k0 = blockIdx.y * 32;
    const int tx = threadIdx.x & 31, ty = threadIdx.x >> 5;
    #pragma unroll
    for (int j = 0; j < 4; j++)
        sm[ty + 8 * j][tx] = in[(size_t)(m0 + ty + 8 * j) * 512 + k0 + tx];
    __syncthreads();
    #pragma unroll
    for (int j = 0; j < 4; j++)
        out[(size_t)(k0 + ty + 8 * j) * MROWS + m0 + tx] = to_tf32(sm[tx][ty + 8 * j]);
}

// ---------------------------------------------------------------------------
// Weight pad + cvt for softmax-resnet MLP.
// ---------------------------------------------------------------------------
__global__ void __launch_bounds__(256) wprep_kernel(
    const float* __restrict__ w1, const float* __restrict__ w2)
{
    int i = blockIdx.x * 256 + threadIdx.x;
    if (i < 72 * 128) {
        int k = i >> 7, n = i & 127;
        g_w1p[i] = (k < 71) ? to_tf32(w1[k * 128 + n]) : 0.f;
    }
    if (i < 128 * 72) {
        int k = i / 72, n = i - k * 72;
        g_w2p[i] = (n < 71) ? to_tf32(w2[k * 71 + n]) : 0.f;
    }
}

// ---------------------------------------------------------------------------
// tf32 GEMM core: CTA 128x128, K=512, KC=32, double-buffered smem.
// ---------------------------------------------------------------------------
__device__ __forceinline__ void gemm_tf32_ctile(
    const float* __restrict__ AT, const float* __restrict__ W,
    float (&c)[4][4][4])
{
    extern __shared__ float sm[];
    float* As = sm;            // [2][32][136]
    float* Bs = sm + 8704;

    const int tid  = threadIdx.x;
    const int lane = tid & 31;
    const int warp = tid >> 5;
    const int mBase = blockIdx.y * 128;
    const int nBase = blockIdx.x * 128;

    #pragma unroll
    for (int im = 0; im < 4; im++)
        #pragma unroll
        for (int in = 0; in < 4; in++)
            #pragma unroll
            for (int q = 0; q < 4; q++) c[im][in][q] = 0.f;

    auto ldgA = [&](int kt, float4 (&ra)[4]) {
        #pragma unroll
        for (int it = 0; it < 4; it++) {
            int idx = it * 256 + tid;
            int k = idx >> 5, m4 = (idx & 31) << 2;
            ra[it] = *(const float4*)(AT + (size_t)(kt * 32 + k) * MROWS + mBase + m4);
        }
    };
    auto ldgB = [&](int kt, float4 (&rb)[4]) {
        #pragma unroll
        for (int it = 0; it < 4; it++) {
            int idx = it * 256 + tid;
            int k = idx >> 5, n4 = (idx & 31) << 2;
            rb[it] = *(const float4*)(W + (size_t)(kt * 32 + k) * 512 + nBase + n4);
        }
    };
    auto stsA = [&](int buf, float4 (&ra)[4]) {
        #pragma unroll
        for (int it = 0; it < 4; it++) {
            int idx = it * 256 + tid;
            int k = idx >> 5, m4 = (idx & 31) << 2;
            *(float4*)&As[buf * 4352 + k * 136 + m4] = ra[it];
        }
    };
    auto stsB = [&](int buf, float4 (&rb)[4]) {
        #pragma unroll
        for (int it = 0; it < 4; it++) {
            int idx = it * 256 + tid;
            int k = idx >> 5, n4 = (idx & 31) << 2;
            float4 v = rb[it];
            v.x = to_tf32(v.x); v.y = to_tf32(v.y);
            v.z = to_tf32(v.z); v.w = to_tf32(v.w);
            *(float4*)&Bs[buf * 4352 + k * 136 + n4] = v;
        }
    };
    auto compute = [&](int buf) {
        const float* Asb = As + buf * 4352;
        const float* Bsb = Bs + buf * 4352;
        const int r0 = (warp & 1) * 64 + (lane >> 2);
        const int n0 = (warp >> 1) * 32 + (lane >> 2);
        #pragma unroll
        for (int s = 0; s < 4; s++) {
            const int kk = s * 8 + (lane & 3);
            unsigned a[4][4], b[4][2];
            #pragma unroll
            for (int im = 0; im < 4; im++) {
                a[im][0] = __float_as_uint(Asb[kk * 136 + r0 + im * 16]);
                a[im][1] = __float_as_uint(Asb[kk * 136 + r0 + im * 16 + 8]);
                a[im][2] = __float_as_uint(Asb[(kk + 4) * 136 + r0 + im * 16]);
                a[im][3] = __float_as_uint(Asb[(kk + 4) * 136 + r0 + im * 16 + 8]);
            }
            #pragma unroll
            for (int in = 0; in < 4; in++) {
                b[in][0] = __float_as_uint(Bsb[kk * 136 + n0 + in * 8]);
                b[in][1] = __float_as_uint(Bsb[(kk + 4) * 136 + n0 + in * 8]);
            }
            #pragma unroll
            for (int im = 0; im < 4; im++)
                #pragma unroll
                for (int in = 0; in < 4; in++)
                    mma_tf32(c[im][in], a[im], b[in]);
        }
    };

    float4 ra[4], rb[4];
    ldgA(0, ra); ldgB(0, rb);
    stsA(0, ra); stsB(0, rb);
    __syncthreads();
    #pragma unroll 1
    for (int kt = 0; kt < 16; kt++) {
        const int cur = kt & 1;
        if (kt < 15) { ldgA(kt + 1, ra); ldgB(kt + 1, rb); }
        compute(cur);
        if (kt < 15) { stsA(cur ^ 1, ra); stsB(cur ^ 1, rb); }
        __syncthreads();
    }
}

// ---------------------------------------------------------------------------
// QKV projection: grid (4, 284, 3). Q/K scatter transposed [bh][dh][l];
// V in [bh][l][dh].
// ---------------------------------------------------------------------------
__global__ void __launch_bounds__(256) qkv_gemm_kernel(
    const float* __restrict__ Wq, const float* __restrict__ bq,
    const float* __restrict__ Wk, const float* __restrict__ bk,
    const float* __restrict__ Wv, const float* __restrict__ bv)
{
    const float* AT; const float* W; const float* bias; float* out; float scale;
    if (blockIdx.z == 0)      { AT = g_Tq; W = Wq; bias = bq; out = g_Qt; scale = 0.125f; }
    else if (blockIdx.z == 1) { AT = g_Tk; W = Wk; bias = bk; out = g_Kt; scale = 1.0f; }
    else                      { AT = g_Tv; W = Wv; bias = bv; out = g_V;  scale = 1.0f; }

    float c[4][4][4];
    gemm_tf32_ctile(AT, W, c);

    const int lane = threadIdx.x & 31, warp = threadIdx.x >> 5;
    const int mBase = blockIdx.y * 128, nBase = blockIdx.x * 128;

    float bv2[4][2];
    #pragma unroll
    for (int in = 0; in < 4; in++) {
        int cg = nBase + (warp >> 1) * 32 + in * 8 + 2 * (lane & 3);
        bv2[in][0] = bias[cg]; bv2[in][1] = bias[cg + 1];
    }

    if (blockIdx.z <= 1) {
        // transposed per-head store: [bh][dh][l]
        #pragma unroll
        for (int im = 0; im < 4; im++) {
            int rg0 = mBase + (warp & 1) * 64 + im * 16 + (lane >> 2);
            int rg1 = rg0 + 8;
            int b0 = rg0 / 71, l0 = rg0 - b0 * 71;
            int b1 = rg1 / 71, l1 = rg1 - b1 * 71;
            #pragma unroll
            for (int in = 0; in < 4; in++) {
                int cg = nBase + (warp >> 1) * 32 + in * 8 + 2 * (lane & 3);
                int h = cg >> 6, dh = cg & 63;
                size_t base0 = ((size_t)((b0 * 8 + h) * 64 + dh)) * 71 + l0;
                size_t base1 = ((size_t)((b1 * 8 + h) * 64 + dh)) * 71 + l1;
                out[base0]      = (c[im][in][0] + bv2[in][0]) * scale;
                out[base0 + 71] = (c[im][in][1] + bv2[in][1]) * scale;
                out[base1]      = (c[im][in][2] + bv2[in][0]) * scale;
                out[base1 + 71] = (c[im][in][3] + bv2[in][1]) * scale;
            }
        }
    } else {
        #pragma unroll
        for (int im = 0; im < 4; im++) {
            int rg0 = mBase + (warp & 1) * 64 + im * 16 + (lane >> 2);
            int rg1 = rg0 + 8;
            int b0 = rg0 / 71, l0 = rg0 - b0 * 71;
            int b1 = rg1 / 71, l1 = rg1 - b1 * 71;
            #pragma unroll
            for (int in = 0; in < 4; in++) {
                int cg = nBase + (warp >> 1) * 32 + in * 8 + 2 * (lane & 3);
                int h = cg >> 6, dh = cg & 63;
                float2 v0 = make_float2(c[im][in][0] + bv2[in][0], c[im][in][1] + bv2[in][1]);
                float2 v1 = make_float2(c[im][in][2] + bv2[in][0], c[im][in][3] + bv2[in][1]);
                *(float2*)&out[(((size_t)(b0 * 8 + h) * 71 + l0) << 6) + dh] = v0;
                *(float2*)&out[(((size_t)(b1 * 8 + h) * 71 + l1) << 6) + dh] = v1;
            }
        }
    }
}

// ---------------------------------------------------------------------------
// Output projection: grid (4, 284).
// ---------------------------------------------------------------------------
__global__ void __launch_bounds__(256) out_gemm_kernel(
    float* __restrict__ out, const float* __restrict__ Wo,
    const float* __restrict__ bo)
{
    float c[4][4][4];
    gemm_tf32_ctile(g_attnT, Wo, c);

    const int lane = threadIdx.x & 31, warp = threadIdx.x >> 5;
    const int mBase = blockIdx.y * 128, nBase = blockIdx.x * 128;

    float bv2[4][2];
    #pragma unroll
    for (int in = 0; in < 4; in++) {
        int cg = nBase + (warp >> 1) * 32 + in * 8 + 2 * (lane & 3);
        bv2[in][0] = bo[cg]; bv2[in][1] = bo[cg + 1];
    }
    #pragma unroll
    for (int im = 0; im < 4; im++) {
        int rg0 = mBase + (warp & 1) * 64 + im * 16 + (lane >> 2);
        int rg1 = rg0 + 8;
        #pragma unroll
        for (int in = 0; in < 4; in++) {
            int cg = nBase + (warp >> 1) * 32 + in * 8 + 2 * (lane & 3);
            float2 v0 = make_float2(c[im][in][0] + bv2[in][0], c[im][in][1] + bv2[in][1]);
            float2 v1 = make_float2(c[im][in][2] + bv2[in][0], c[im][in][3] + bv2[in][1]);
            *(float2*)&out[(size_t)rg0 * 512 + cg] = v0;
            *(float2*)&out[(size_t)rg1 * 512 + cg] = v1;
        }
    }
}

// ---------------------------------------------------------------------------
// Attention core stages (one head per CTA, 8 warps; weights via __ldg).
// ---------------------------------------------------------------------------
template<int NS>
__device__ __forceinline__ void run_stage1(
    float* __restrict__ sS, const float* __restrict__ sQt,
    const float* __restrict__ sKt, int w, int lane)
{
    float acc[NS][5][4] = {};
    #pragma unroll
    for (int ks = 0; ks < 8; ks++) {
        int kk = ks * 8 + (lane & 3);
        unsigned bfr[NS][2];
        #pragma unroll
        for (int s = 0; s < NS; s++) { LDB(bfr[s], sKt, 88, w + s * 8, kk); }
        #pragma unroll
        for (int mt = 0; mt < 5; mt++) {
            unsigned afr[4];
            LDA(afr, sQt, 88, mt, kk);
            #pragma unroll
            for (int s = 0; s < NS; s++) mma_tf32(acc[s][mt], afr, bfr[s]);
        }
    }
    #pragma unroll
    for (int s = 0; s < NS; s++) {
        int n0 = (w + s * 8) * 8 + 2 * (lane & 3);
        #pragma unroll
        for (int mt = 0; mt < 5; mt++) {
            int r = mt * 16 + (lane >> 2);
            sS[n0 * 88 + r]           = to_tf32(acc[s][mt][0]);
            sS[(n0 + 1) * 88 + r]     = to_tf32(acc[s][mt][1]);
            sS[n0 * 88 + r + 8]       = to_tf32(acc[s][mt][2]);
            sS[(n0 + 1) * 88 + r + 8] = to_tf32(acc[s][mt][3]);
        }
    }
}

__device__ __forceinline__ void run_stage2(
    float* __restrict__ sH, const float* __restrict__ sS,
    const float* __restrict__ b1, int w, int lane)
{
    float acc[2][5][4] = {};
    #pragma unroll
    for (int ks = 0; ks < 9; ks++) {
        const int kk = ks * 8 + (lane & 3);
        unsigned bfr[2][2];
        #pragma unroll
        for (int s = 0; s < 2; s++) {
            const int n = (w + s * 8) * 8 + (lane >> 2);
            bfr[s][0] = __float_as_uint(__ldg(&g_w1p[kk * 128 + n]));
            bfr[s][1] = __float_as_uint(__ldg(&g_w1p[(kk + 4) * 128 + n]));
        }
        #pragma unroll
        for (int mt = 0; mt < 5; mt++) {
            unsigned afr[4];
            LDA(afr, sS, 88, mt, kk);
            mma_tf32(acc[0][mt], afr, bfr[0]);
            mma_tf32(acc[1][mt], afr, bfr[1]);
        }
    }
    #pragma unroll
    for (int s = 0; s < 2; s++) {
        const int n0 = (w + s * 8) * 8 + 2 * (lane & 3);
        const float bb0 = __ldg(b1 + n0), bb1 = __ldg(b1 + n0 + 1);
        #pragma unroll
        for (int mt = 0; mt < 5; mt++) {
            const int r = mt * 16 + (lane >> 2);
            sH[n0 * 88 + r]           = to_tf32(gelu_exact(acc[s][mt][0] + bb0));
            sH[(n0 + 1) * 88 + r]     = to_tf32(gelu_exact(acc[s][mt][1] + bb1));
            sH[n0 * 88 + r + 8]       = to_tf32(gelu_exact(acc[s][mt][2] + bb0));
            sH[(n0 + 1) * 88 + r + 8] = to_tf32(gelu_exact(acc[s][mt][3] + bb1));
        }
    }
}

template<int NS>
__device__ __forceinline__ void run_stage3(
    float* __restrict__ sS, const float* __restrict__ sH,
    const float* __restrict__ b2, int w, int lane)
{
    float acc[NS][5][4] = {};
    #pragma unroll
    for (int ks = 0; ks < 16; ks++) {
        const int kk = ks * 8 + (lane & 3);
        unsigned bfr[NS][2];
        #pragma unroll
        for (int s = 0; s < NS; s++) {
            const int n = (w + s * 8) * 8 + (lane >> 2);
            bfr[s][0] = __float_as_uint(__ldg(&g_w2p[kk * 72 + n]));
            bfr[s][1] = __float_as_uint(__ldg(&g_w2p[(kk + 4) * 72 + n]));
        }
        #pragma unroll
        for (int mt = 0; mt < 5; mt++) {
            unsigned afr[4];
            LDA(afr, sH, 88, mt, kk);
            #pragma unroll
            for (int s = 0; s < NS; s++) mma_tf32(acc[s][mt], afr, bfr[s]);
        }
    }
    #pragma unroll
    for (int s = 0; s < NS; s++) {
        const int n0 = (w + s * 8) * 8 + 2 * (lane & 3);
        const float bb0 = __ldg(b2 + n0);
        const float bb1 = (n0 + 1 < 71) ? __ldg(b2 + n0 + 1) : 0.f;
        #pragma unroll
        for (int mt = 0; mt < 5; mt++) {
            const int r = mt * 16 + (lane >> 2);
            sS[n0 * 88 + r]           += acc[s][mt][0] + bb0;
            sS[(n0 + 1) * 88 + r]     += acc[s][mt][1] + bb1;
            sS[n0 * 88 + r + 8]       += acc[s][mt][2] + bb0;
            sS[(n0 + 1) * 88 + r + 8] += acc[s][mt][3] + bb1;
        }
    }
}

// ---------------------------------------------------------------------------
// Attention core: ONE head per CTA, 256 threads. Grid = 4096.
// smem (17600 floats = 70400 B): sS [72][88] at +0; union U at +6336:
//   stage0-1: sQt [64][88] + sKt [64][88] (11264); stage2-3: sH [128][88];
//   stage5: sV [72][72].
// ---------------------------------------------------------------------------
__global__ void __launch_bounds__(256, 3) attn_kernel(
    const float* __restrict__ b1, const float* __restrict__ b2)
{
    extern __shared__ float smf[];
    float* sS = smf;          // 6336
    float* U  = smf + 6336;   // 11264

    const int tid  = threadIdx.x;
    const int lane = tid & 31;
    const int w    = tid >> 5;      // 0..7
    const int bh   = blockIdx.x;
    const int bidx = bh >> 3, hidx = bh & 7;

    // ---- load Q^T, K^T [dh][l] with stride 88, zero-pad cols 71..87 ----
    {
        float* sQt = U;
        float* sKt = U + 5632;
        const float* Qg = g_Qt + (size_t)bh * HEAD_ELEMS;
        const float* Kg = g_Kt + (size_t)bh * HEAD_ELEMS;
        for (int i = tid; i < HEAD_ELEMS; i += 256) {
            int dh = i / 71, l = i - dh * 71;
            sQt[dh * 88 + l] = to_tf32(Qg[i]);
            sKt[dh * 88 + l] = to_tf32(Kg[i]);
        }
        for (int i = tid; i < 64 * 17; i += 256) {
            int dh = i / 17, c = 71 + (i - dh * 17);
            sQt[dh * 88 + c] = 0.f;
            sKt[dh * 88 + c] = 0.f;
        }
    }
    __syncthreads();

    // ---- stage 1: S = Q @ K^T -> sS[key][query] ----
    if (w == 0) run_stage1<2>(sS, U, U + 5632, w, lane);
    else        run_stage1<1>(sS, U, U + 5632, w, lane);
    __syncthreads();

    // ---- stage 2: H = gelu(S @ w1 + b1) -> sH[ff][query] ----
    run_stage2(U, sS, b1, w, lane);
    __syncthreads();

    // ---- stage 3: S += H @ w2 + b2 ----
    if (w == 0) run_stage3<2>(sS, U, b2, w, lane);
    else        run_stage3<1>(sS, U, b2, w, lane);
    __syncthreads();

    // ---- V into U + softmax over sS columns ----
    {
        float* sV = U;           // [72][72]
        const float* Vg = g_V + (size_t)bh * HEAD_ELEMS;
        for (int i = tid; i < HEAD_ELEMS; i += 256) {
            int l = i >> 6, dh = i & 63;
            sV[l * 72 + dh] = to_tf32(Vg[i]);
        }
        if (tid < 72) sV[71 * 72 + tid] = 0.f;
    }
    if (tid < 71) {
        const int q = tid;
        float mx = -1e30f;
        #pragma unroll 1
        for (int k = 0; k < 71; k++) mx = fmaxf(mx, sS[k * 88 + q]);
        float ssum = 0.f;
        #pragma unroll 1
        for (int k = 0; k < 71; k++) {
            float e = __expf(sS[k * 88 + q] - mx);
            sS[k * 88 + q] = e;
            ssum += e;
        }
        float inv = 1.f / ssum;
        #pragma unroll 1
        for (int k = 0; k < 71; k++) sS[k * 88 + q] = to_tf32(sS[k * 88 + q] * inv);
    }
    __syncthreads();

    // ---- stage 5: attn = P @ V -> g_attnT[d][m] ----
    {
        const float* sV = U;
        float acc[5][4] = {};
        #pragma unroll
        for (int ks = 0; ks < 9; ks++) {
            const int kk = ks * 8 + (lane & 3);
            unsigned bfr[2];
            const int n = w * 8 + (lane >> 2);
            bfr[0] = __float_as_uint(sV[kk * 72 + n]);
            bfr[1] = __float_as_uint(sV[(kk + 4) * 72 + n]);
            #pragma unroll
            for (int mt = 0; mt < 5; mt++) {
                unsigned afr[4];
                LDA(afr, sS, 88, mt, kk);
                mma_tf32(acc[mt], afr, bfr);
            }
        }
        const int n0 = w * 8 + 2 * (lane & 3);
        const size_t d0 = (size_t)(hidx * 64 + n0);
        #pragma unroll
        for (int mt = 0; mt < 5; mt++) {
            int r = mt * 16 + (lane >> 2);
            if (r < 71) {
                size_t mg = (size_t)bidx * 71 + r;
                g_attnT[d0 * MROWS + mg]       = to_tf32(acc[mt][0]);
                g_attnT[(d0 + 1) * MROWS + mg] = to_tf32(acc[mt][1]);
            }
            if (r + 8 < 71) {
                size_t mg = (size_t)bidx * 71 + r + 8;
                g_attnT[d0 * MROWS + mg]       = to_tf32(acc[mt][2]);
                g_attnT[(d0 + 1) * MROWS + mg] = to_tf32(acc[mt][3]);
            }
        }
    }
}

// ---------------------------------------------------------------------------
extern "C" void kernel_launch(void* const* d_in, const int* in_sizes, int n_in,
                              void* d_out, int out_size)
{
    const float* query = (const float*)d_in[0];
    const float* key   = (const float*)d_in[1];
    const float* value = (const float*)d_in[2];
    const float* Wq = (const float*)d_in[3];
    const float* bq = (const float*)d_in[4];
    const float* Wk = (const float*)d_in[5];
    const float* bk = (const float*)d_in[6];
    const float* Wv = (const float*)d_in[7];
    const float* bv = (const float*)d_in[8];
    const float* Wo = (const float*)d_in[9];
    const float* bo = (const float*)d_in[10];
    const float* sf_w1 = (const float*)d_in[11];
    const float* sf_b1 = (const float*)d_in[12];
    const float* sf_w2 = (const float*)d_in[13];
    const float* sf_b2 = (const float*)d_in[14];
    float* out = (float*)d_out;

    float *dTq, *dTk, *dTv;
    cudaGetSymbolAddress((void**)&dTq, g_Tq);
    cudaGetSymbolAddress((void**)&dTk, g_Tk);
    cudaGetSymbolAddress((void**)&dTv, g_Tv);

    const int gemm_smem = 17408 * sizeof(float);    // 69632 B
    cudaFuncSetAttribute(qkv_gemm_kernel, cudaFuncAttributeMaxDynamicSharedMemorySize, gemm_smem);
    cudaFuncSetAttribute(out_gemm_kernel, cudaFuncAttributeMaxDynamicSharedMemorySize, gemm_smem);
    const int attn_smem = 17600 * sizeof(float);    // 70400 B
    cudaFuncSetAttribute(attn_kernel, cudaFuncAttributeMaxDynamicSharedMemorySize, attn_smem);

    // 1) transpose+cvt activations; pad+cvt MLP weights
    dim3 gt(MROWS / 32, 16, 3);
    transpose_cvt_kernel<<<gt, 256>>>(query, key, value, dTq, dTk, dTv);
    wprep_kernel<<<36, 256>>>(sf_w1, sf_w2);

    // 2) QKV projections (tf32 tensor cores)
    dim3 g1(4, 284, 3);
    qkv_gemm_kernel<<<g1, 256, gemm_smem>>>(Wq, bq, Wk, bk, Wv, bv);

    // 3) attention core (1 head per CTA, 3 CTAs/SM)
    attn_kernel<<<NHEADS, 256, attn_smem>>>(sf_b1, sf_b2);

    // 4) output projection
    dim3 g3(4, 284);
    out_gemm_kernel<<<g3, 256, gemm_smem>>>(out, Wo, bo);
}

// round 10
// speedup vs baseline: 2.3630x; 1.4666x over previous
#include <cuda_runtime.h>
#include <cuda_fp16.h>
#include <math.h>

// Problem constants
#define BB   512
#define LL   71
#define DD   512
#define HH   8
#define DHH  64
#define MROWS (BB * LL)          // 36352 = 284*128
#define NHEADS (BB * HH)         // 4096
#define HEAD_ELEMS (LL * DHH)    // 4544

// ---------------------------------------------------------------------------
// Scratch (static device globals)
// ---------------------------------------------------------------------------
__device__ __half g_WT16[4][DD * DD];       // fp16 transposed weights [n][k]: q,k,v,o
__device__ float g_Qt[NHEADS * HEAD_ELEMS]; // [bh][dh][l], Q pre-scaled by 1/8
__device__ float g_Kt[NHEADS * HEAD_ELEMS]; // [bh][dh][l]
__device__ float g_V [NHEADS * HEAD_ELEMS]; // [bh][l][dh]
__device__ __half g_attnH[MROWS * DD];      // attn output [m][512] fp16 row-major
__device__ float g_w1p[72 * 128];           // padded tf32 w1 (row 71 = 0)
__device__ float g_w2p[128 * 72];           // padded tf32 w2 (col 71 = 0)

__device__ __forceinline__ float to_tf32(float x) {
    float y;
    asm("cvt.rna.tf32.f32 %0, %1;" : "=f"(y) : "f"(x));
    return y;
}

__device__ __forceinline__ void mma_tf32(float* c, const unsigned* a, const unsigned* b) {
    asm volatile(
        "mma.sync.aligned.m16n8k8.row.col.f32.tf32.tf32.f32 "
        "{%0,%1,%2,%3}, {%4,%5,%6,%7}, {%8,%9}, {%0,%1,%2,%3};"
        : "+f"(c[0]), "+f"(c[1]), "+f"(c[2]), "+f"(c[3])
        : "r"(a[0]), "r"(a[1]), "r"(a[2]), "r"(a[3]), "r"(b[0]), "r"(b[1]));
}

__device__ __forceinline__ void mma_f16(float* c, const unsigned* a, const unsigned* b) {
    asm volatile(
        "mma.sync.aligned.m16n8k16.row.col.f32.f16.f16.f32 "
        "{%0,%1,%2,%3}, {%4,%5,%6,%7}, {%8,%9}, {%0,%1,%2,%3};"
        : "+f"(c[0]), "+f"(c[1]), "+f"(c[2]), "+f"(c[3])
        : "r"(a[0]), "r"(a[1]), "r"(a[2]), "r"(a[3]), "r"(b[0]), "r"(b[1]));
}

__device__ __forceinline__ float gelu_exact(float x) {
    return 0.5f * x * (1.f + erff(x * 0.70710678118654752f));
}

// A fragment (tf32): A[m][k] stored k-major base[k*stride + m]
#define LDA(frag, base, stride, mt, kk) { \
    const float* p_ = (base) + (kk) * (stride) + (mt) * 16 + (lane >> 2); \
    frag[0] = __float_as_uint(p_[0]); \
    frag[1] = __float_as_uint(p_[8]); \
    frag[2] = __float_as_uint(p_[(stride) * 4]); \
    frag[3] = __float_as_uint(p_[(stride) * 4 + 8]); }

// B fragment (tf32): B[k][n] k-major base[k*stride + n]
#define LDB(frag, base, stride, nt, kk) { \
    const float* p_ = (base) + (kk) * (stride) + (nt) * 8 + (lane >> 2); \
    frag[0] = __float_as_uint(p_[0]); \
    frag[1] = __float_as_uint(p_[(stride) * 4]); }

// ---------------------------------------------------------------------------
// Weight transpose + fp16 cvt: W[k][n] fp32 -> g_WT16[z][n][k] fp16.
// ---------------------------------------------------------------------------
__global__ void __launch_bounds__(256) wt16_kernel(
    const float* __restrict__ w0, const float* __restrict__ w1,
    const float* __restrict__ w2, const float* __restrict__ w3)
{
    __shared__ float t[32][33];
    const float* in = (blockIdx.z == 0) ? w0 : (blockIdx.z == 1) ? w1
                    : (blockIdx.z == 2) ? w2 : w3;
    __half* out = g_WT16[blockIdx.z];
    const int k0 = blockIdx.x * 32, n0 = blockIdx.y * 32;
    const int tx = threadIdx.x & 31, ty = threadIdx.x >> 5;
    #pragma unroll
    for (int j = 0; j < 4; j++)
        t[ty + 8 * j][tx] = in[(size_t)(k0 + ty + 8 * j) * 512 + n0 + tx];
    __syncthreads();
    #pragma unroll
    for (int j = 0; j < 4; j++)
        out[(size_t)(n0 + ty + 8 * j) * 512 + k0 + tx] = __float2half_rn(t[tx][ty + 8 * j]);
}

// ---------------------------------------------------------------------------
// MLP weight pad + tf32 cvt (unchanged from R9).
// ---------------------------------------------------------------------------
__global__ void __launch_bounds__(256) wprep_kernel(
    const float* __restrict__ w1, const float* __restrict__ w2)
{
    int i = blockIdx.x * 256 + threadIdx.x;
    if (i < 72 * 128) {
        int k = i >> 7, n = i & 127;
        g_w1p[i] = (k < 71) ? to_tf32(w1[k * 128 + n]) : 0.f;
    }
    if (i < 128 * 72) {
        int k = i / 72, n = i - k * 72;
        g_w2p[i] = (n < 71) ? to_tf32(w2[k * 71 + n]) : 0.f;
    }
}

// ---------------------------------------------------------------------------
// fp16 GEMM core: CTA 128x128, K=512, KC=32, double-buffered smem.
// A row-major [M][512] (fp32 or fp16); BT fp16 [n][k].
// smem halfs: As[2][128][40], Bs[2][128][40]; 40960 B total.
// ---------------------------------------------------------------------------
template<typename TA>
__device__ __forceinline__ void gemm_f16_ctile(
    const TA* __restrict__ A, const __half* __restrict__ BT,
    float (&c)[4][4][4])
{
    extern __shared__ __align__(16) __half smh[];
    __half* As = smh;            // [2][5120]
    __half* Bs = smh + 10240;    // [2][5120]

    const int tid  = threadIdx.x;
    const int lane = tid & 31;
    const int warp = tid >> 5;
    const int mBase = blockIdx.y * 128;
    const int nBase = blockIdx.x * 128;

    #pragma unroll
    for (int im = 0; im < 4; im++)
        #pragma unroll
        for (int in = 0; in < 4; in++)
            #pragma unroll
            for (int q = 0; q < 4; q++) c[im][in][q] = 0.f;

    float4 raf[4];
    uint4  rah[2];
    uint4  rbh[2];

    auto ldgA = [&](int kt) {
        if constexpr (sizeof(TA) == 4) {
            #pragma unroll
            for (int it = 0; it < 4; it++) {
                int idx = it * 256 + tid;
                int row = idx >> 3, c4 = idx & 7;
                raf[it] = *(const float4*)((const float*)A +
                    (size_t)(mBase + row) * 512 + kt * 32 + c4 * 4);
            }
        } else {
            #pragma unroll
            for (int it = 0; it < 2; it++) {
                int idx = it * 256 + tid;
                int row = idx >> 2, g = idx & 3;
                rah[it] = *(const uint4*)((const __half*)A +
                    (size_t)(mBase + row) * 512 + kt * 32 + g * 8);
            }
        }
    };
    auto ldgB = [&](int kt) {
        #pragma unroll
        for (int it = 0; it < 2; it++) {
            int idx = it * 256 + tid;
            int row = idx >> 2, g = idx & 3;
            rbh[it] = *(const uint4*)(BT + (size_t)(nBase + row) * 512 + kt * 32 + g * 8);
        }
    };
    auto stsA = [&](int buf) {
        if constexpr (sizeof(TA) == 4) {
            #pragma unroll
            for (int it = 0; it < 4; it++) {
                int idx = it * 256 + tid;
                int row = idx >> 3, c4 = idx & 7;
                __half2 h0 = __floats2half2_rn(raf[it].x, raf[it].y);
                __half2 h1 = __floats2half2_rn(raf[it].z, raf[it].w);
                *(__half2*)&As[buf * 5120 + row * 40 + c4 * 4]     = h0;
                *(__half2*)&As[buf * 5120 + row * 40 + c4 * 4 + 2] = h1;
            }
        } else {
            #pragma unroll
            for (int it = 0; it < 2; it++) {
                int idx = it * 256 + tid;
                int row = idx >> 2, g = idx & 3;
                *(uint4*)&As[buf * 5120 + row * 40 + g * 8] = rah[it];
            }
        }
    };
    auto stsB = [&](int buf) {
        #pragma unroll
        for (int it = 0; it < 2; it++) {
            int idx = it * 256 + tid;
            int row = idx >> 2, g = idx & 3;
            *(uint4*)&Bs[buf * 5120 + row * 40 + g * 8] = rbh[it];
        }
    };
    auto compute = [&](int buf) {
        const __half* Asb = As + buf * 5120;
        const __half* Bsb = Bs + buf * 5120;
        const int r0 = (warp & 1) * 64 + (lane >> 2);
        const int n0 = (warp >> 1) * 32 + (lane >> 2);
        #pragma unroll
        for (int ks = 0; ks < 2; ks++) {
            const int kb = ks * 16 + (lane & 3) * 2;
            unsigned a[4][4], b[4][2];
            #pragma unroll
            for (int mt = 0; mt < 4; mt++) {
                a[mt][0] = *(const unsigned*)&Asb[(r0 + mt * 16) * 40 + kb];
                a[mt][1] = *(const unsigned*)&Asb[(r0 + mt * 16 + 8) * 40 + kb];
                a[mt][2] = *(const unsigned*)&Asb[(r0 + mt * 16) * 40 + kb + 8];
                a[mt][3] = *(const unsigned*)&Asb[(r0 + mt * 16 + 8) * 40 + kb + 8];
            }
            #pragma unroll
            for (int nt = 0; nt < 4; nt++) {
                b[nt][0] = *(const unsigned*)&Bsb[(n0 + nt * 8) * 40 + kb];
                b[nt][1] = *(const unsigned*)&Bsb[(n0 + nt * 8) * 40 + kb + 8];
            }
            #pragma unroll
            for (int im = 0; im < 4; im++)
                #pragma unroll
                for (int in = 0; in < 4; in++)
                    mma_f16(c[im][in], a[im], b[in]);
        }
    };

    ldgA(0); ldgB(0);
    stsA(0); stsB(0);
    __syncthreads();
    #pragma unroll 1
    for (int kt = 0; kt < 16; kt++) {
        const int cur = kt & 1;
        if (kt < 15) { ldgA(kt + 1); ldgB(kt + 1); }
        compute(cur);
        if (kt < 15) { stsA(cur ^ 1); stsB(cur ^ 1); }
        __syncthreads();
    }
}

// ---------------------------------------------------------------------------
// QKV projection (fp16 mma, A = raw inputs): grid (4, 284, 3).
// Q/K scatter transposed fp32 [bh][dh][l]; V fp32 [bh][l][dh].
// ---------------------------------------------------------------------------
__global__ void __launch_bounds__(256) qkv_gemm_kernel(
    const float* __restrict__ q_in, const float* __restrict__ k_in,
    const float* __restrict__ v_in,
    const float* __restrict__ bq, const float* __restrict__ bk,
    const float* __restrict__ bv)
{
    const float* A; const float* bias; float* out; float scale;
    if (blockIdx.z == 0)      { A = q_in; bias = bq; out = g_Qt; scale = 0.125f; }
    else if (blockIdx.z == 1) { A = k_in; bias = bk; out = g_Kt; scale = 1.0f; }
    else                      { A = v_in; bias = bv; out = g_V;  scale = 1.0f; }

    float c[4][4][4];
    gemm_f16_ctile<float>(A, g_WT16[blockIdx.z], c);

    const int lane = threadIdx.x & 31, warp = threadIdx.x >> 5;
    const int mBase = blockIdx.y * 128, nBase = blockIdx.x * 128;

    float bv2[4][2];
    #pragma unroll
    for (int in = 0; in < 4; in++) {
        int cg = nBase + (warp >> 1) * 32 + in * 8 + 2 * (lane & 3);
        bv2[in][0] = bias[cg]; bv2[in][1] = bias[cg + 1];
    }

    if (blockIdx.z <= 1) {
        #pragma unroll
        for (int im = 0; im < 4; im++) {
            int rg0 = mBase + (warp & 1) * 64 + im * 16 + (lane >> 2);
            int rg1 = rg0 + 8;
            int b0 = rg0 / 71, l0 = rg0 - b0 * 71;
            int b1 = rg1 / 71, l1 = rg1 - b1 * 71;
            #pragma unroll
            for (int in = 0; in < 4; in++) {
                int cg = nBase + (warp >> 1) * 32 + in * 8 + 2 * (lane & 3);
                int h = cg >> 6, dh = cg & 63;
                size_t base0 = ((size_t)((b0 * 8 + h) * 64 + dh)) * 71 + l0;
                size_t base1 = ((size_t)((b1 * 8 + h) * 64 + dh)) * 71 + l1;
                out[base0]      = (c[im][in][0] + bv2[in][0]) * scale;
                out[base0 + 71] = (c[im][in][1] + bv2[in][1]) * scale;
                out[base1]      = (c[im][in][2] + bv2[in][0]) * scale;
                out[base1 + 71] = (c[im][in][3] + bv2[in][1]) * scale;
            }
        }
    } else {
        #pragma unroll
        for (int im = 0; im < 4; im++) {
            int rg0 = mBase + (warp & 1) * 64 + im * 16 + (lane >> 2);
            int rg1 = rg0 + 8;
            int b0 = rg0 / 71, l0 = rg0 - b0 * 71;
            int b1 = rg1 / 71, l1 = rg1 - b1 * 71;
            #pragma unroll
            for (int in = 0; in < 4; in++) {
                int cg = nBase + (warp >> 1) * 32 + in * 8 + 2 * (lane & 3);
                int h = cg >> 6, dh = cg & 63;
                float2 v0 = make_float2(c[im][in][0] + bv2[in][0], c[im][in][1] + bv2[in][1]);
                float2 v1 = make_float2(c[im][in][2] + bv2[in][0], c[im][in][3] + bv2[in][1]);
                *(float2*)&out[(((size_t)(b0 * 8 + h) * 71 + l0) << 6) + dh] = v0;
                *(float2*)&out[(((size_t)(b1 * 8 + h) * 71 + l1) << 6) + dh] = v1;
            }
        }
    }
}

// ---------------------------------------------------------------------------
// Output projection (fp16 mma, A = g_attnH): grid (4, 284).
// ---------------------------------------------------------------------------
__global__ void __launch_bounds__(256) out_gemm_kernel(
    float* __restrict__ out, const float* __restrict__ bo)
{
    float c[4][4][4];
    gemm_f16_ctile<__half>(g_attnH, g_WT16[3], c);

    const int lane = threadIdx.x & 31, warp = threadIdx.x >> 5;
    const int mBase = blockIdx.y * 128, nBase = blockIdx.x * 128;

    float bv2[4][2];
    #pragma unroll
    for (int in = 0; in < 4; in++) {
        int cg = nBase + (warp >> 1) * 32 + in * 8 + 2 * (lane & 3);
        bv2[in][0] = bo[cg]; bv2[in][1] = bo[cg + 1];
    }
    #pragma unroll
    for (int im = 0; im < 4; im++) {
        int rg0 = mBase + (warp & 1) * 64 + im * 16 + (lane >> 2);
        int rg1 = rg0 + 8;
        #pragma unroll
        for (int in = 0; in < 4; in++) {
            int cg = nBase + (warp >> 1) * 32 + in * 8 + 2 * (lane & 3);
            float2 v0 = make_float2(c[im][in][0] + bv2[in][0], c[im][in][1] + bv2[in][1]);
            float2 v1 = make_float2(c[im][in][2] + bv2[in][0], c[im][in][3] + bv2[in][1]);
            *(float2*)&out[(size_t)rg0 * 512 + cg] = v0;
            *(float2*)&out[(size_t)rg1 * 512 + cg] = v1;
        }
    }
}

// ---------------------------------------------------------------------------
// Attention core stages (tf32 legacy mma; weights via __ldg) — as R9.
// ---------------------------------------------------------------------------
template<int NS>
__device__ __forceinline__ void run_stage1(
    float* __restrict__ sS, const float* __restrict__ sQt,
    const float* __restrict__ sKt, int w, int lane)
{
    float acc[NS][5][4] = {};
    #pragma unroll
    for (int ks = 0; ks < 8; ks++) {
        int kk = ks * 8 + (lane & 3);
        unsigned bfr[NS][2];
        #pragma unroll
        for (int s = 0; s < NS; s++) { LDB(bfr[s], sKt, 88, w + s * 8, kk); }
        #pragma unroll
        for (int mt = 0; mt < 5; mt++) {
            unsigned afr[4];
            LDA(afr, sQt, 88, mt, kk);
            #pragma unroll
            for (int s = 0; s < NS; s++) mma_tf32(acc[s][mt], afr, bfr[s]);
        }
    }
    #pragma unroll
    for (int s = 0; s < NS; s++) {
        int n0 = (w + s * 8) * 8 + 2 * (lane & 3);
        #pragma unroll
        for (int mt = 0; mt < 5; mt++) {
            int r = mt * 16 + (lane >> 2);
            sS[n0 * 88 + r]           = to_tf32(acc[s][mt][0]);
            sS[(n0 + 1) * 88 + r]     = to_tf32(acc[s][mt][1]);
            sS[n0 * 88 + r + 8]       = to_tf32(acc[s][mt][2]);
            sS[(n0 + 1) * 88 + r + 8] = to_tf32(acc[s][mt][3]);
        }
    }
}

__device__ __forceinline__ void run_stage2(
    float* __restrict__ sH, const float* __restrict__ sS,
    const float* __restrict__ b1, int w, int lane)
{
    float acc[2][5][4] = {};
    #pragma unroll
    for (int ks = 0; ks < 9; ks++) {
        const int kk = ks * 8 + (lane & 3);
        unsigned bfr[2][2];
        #pragma unroll
        for (int s = 0; s < 2; s++) {
            const int n = (w + s * 8) * 8 + (lane >> 2);
            bfr[s][0] = __float_as_uint(__ldg(&g_w1p[kk * 128 + n]));
            bfr[s][1] = __float_as_uint(__ldg(&g_w1p[(kk + 4) * 128 + n]));
        }
        #pragma unroll
        for (int mt = 0; mt < 5; mt++) {
            unsigned afr[4];
            LDA(afr, sS, 88, mt, kk);
            mma_tf32(acc[0][mt], afr, bfr[0]);
            mma_tf32(acc[1][mt], afr, bfr[1]);
        }
    }
    #pragma unroll
    for (int s = 0; s < 2; s++) {
        const int n0 = (w + s * 8) * 8 + 2 * (lane & 3);
        const float bb0 = __ldg(b1 + n0), bb1 = __ldg(b1 + n0 + 1);
        #pragma unroll
        for (int mt = 0; mt < 5; mt++) {
            const int r = mt * 16 + (lane >> 2);
            sH[n0 * 88 + r]           = to_tf32(gelu_exact(acc[s][mt][0] + bb0));
            sH[(n0 + 1) * 88 + r]     = to_tf32(gelu_exact(acc[s][mt][1] + bb1));
            sH[n0 * 88 + r + 8]       = to_tf32(gelu_exact(acc[s][mt][2] + bb0));
            sH[(n0 + 1) * 88 + r + 8] = to_tf32(gelu_exact(acc[s][mt][3] + bb1));
        }
    }
}

template<int NS>
__device__ __forceinline__ void run_stage3(
    float* __restrict__ sS, const float* __restrict__ sH,
    const float* __restrict__ b2, int w, int lane)
{
    float acc[NS][5][4] = {};
    #pragma unroll
    for (int ks = 0; ks < 16; ks++) {
        const int kk = ks * 8 + (lane & 3);
        unsigned bfr[NS][2];
        #pragma unroll
        for (int s = 0; s < NS; s++) {
            const int n = (w + s * 8) * 8 + (lane >> 2);
            bfr[s][0] = __float_as_uint(__ldg(&g_w2p[kk * 72 + n]));
            bfr[s][1] = __float_as_uint(__ldg(&g_w2p[(kk + 4) * 72 + n]));
        }
        #pragma unroll
        for (int mt = 0; mt < 5; mt++) {
            unsigned afr[4];
            LDA(afr, sH, 88, mt, kk);
            #pragma unroll
            for (int s = 0; s < NS; s++) mma_tf32(acc[s][mt], afr, bfr[s]);
        }
    }
    #pragma unroll
    for (int s = 0; s < NS; s++) {
        const int n0 = (w + s * 8) * 8 + 2 * (lane & 3);
        const float bb0 = __ldg(b2 + n0);
        const float bb1 = (n0 + 1 < 71) ? __ldg(b2 + n0 + 1) : 0.f;
        #pragma unroll
        for (int mt = 0; mt < 5; mt++) {
            const int r = mt * 16 + (lane >> 2);
            sS[n0 * 88 + r]           += acc[s][mt][0] + bb0;
            sS[(n0 + 1) * 88 + r]     += acc[s][mt][1] + bb1;
            sS[n0 * 88 + r + 8]       += acc[s][mt][2] + bb0;
            sS[(n0 + 1) * 88 + r + 8] += acc[s][mt][3] + bb1;
        }
    }
}

// ---------------------------------------------------------------------------
// Attention core: ONE head per CTA, 256 threads. Grid = 4096.
// smem (17600 floats = 70400 B): sS [72][88] at +0; union U at +6336.
// Changes vs R9: warp-parallel softmax; epilogue -> fp16 row-major g_attnH.
// ---------------------------------------------------------------------------
__global__ void __launch_bounds__(256, 3) attn_kernel(
    const float* __restrict__ b1, const float* __restrict__ b2)
{
    extern __shared__ float smf[];
    float* sS = smf;          // 6336
    float* U  = smf + 6336;   // 11264

    const int tid  = threadIdx.x;
    const int lane = tid & 31;
    const int w    = tid >> 5;      // 0..7
    const int bh   = blockIdx.x;
    const int bidx = bh >> 3, hidx = bh & 7;

    // ---- load Q^T, K^T [dh][l] stride 88, zero-pad cols 71..87 ----
    {
        float* sQt = U;
        float* sKt = U + 5632;
        const float* Qg = g_Qt + (size_t)bh * HEAD_ELEMS;
        const float* Kg = g_Kt + (size_t)bh * HEAD_ELEMS;
        for (int i = tid; i < HEAD_ELEMS; i += 256) {
            int dh = i / 71, l = i - dh * 71;
            sQt[dh * 88 + l] = to_tf32(Qg[i]);
            sKt[dh * 88 + l] = to_tf32(Kg[i]);
        }
        for (int i = tid; i < 64 * 17; i += 256) {
            int dh = i / 17, c = 71 + (i - dh * 17);
            sQt[dh * 88 + c] = 0.f;
            sKt[dh * 88 + c] = 0.f;
        }
    }
    __syncthreads();

    if (w == 0) run_stage1<2>(sS, U, U + 5632, w, lane);
    else        run_stage1<1>(sS, U, U + 5632, w, lane);
    __syncthreads();

    run_stage2(U, sS, b1, w, lane);
    __syncthreads();

    if (w == 0) run_stage3<2>(sS, U, b2, w, lane);
    else        run_stage3<1>(sS, U, b2, w, lane);
    __syncthreads();

    // ---- V into U + warp-parallel softmax over sS columns ----
    {
        float* sV = U;           // [72][72]
        const float* Vg = g_V + (size_t)bh * HEAD_ELEMS;
        for (int i = tid; i < HEAD_ELEMS; i += 256) {
            int l = i >> 6, dh = i & 63;
            sV[l * 72 + dh] = to_tf32(Vg[i]);
        }
        if (tid < 72) sV[71 * 72 + tid] = 0.f;
    }
    __syncwarp();
    for (int col = w; col < 71; col += 8) {
        float v0 = sS[lane * 88 + col];
        float v1 = (lane + 32 < 71) ? sS[(lane + 32) * 88 + col] : -1e30f;
        float v2 = (lane < 7)       ? sS[(lane + 64) * 88 + col] : -1e30f;
        float m = fmaxf(v0, fmaxf(v1, v2));
        #pragma unroll
        for (int o = 16; o > 0; o >>= 1) m = fmaxf(m, __shfl_xor_sync(0xffffffffu, m, o));
        float e0 = __expf(v0 - m);
        float e1 = (lane + 32 < 71) ? __expf(v1 - m) : 0.f;
        float e2 = (lane < 7)       ? __expf(v2 - m) : 0.f;
        float s = e0 + e1 + e2;
        #pragma unroll
        for (int o = 16; o > 0; o >>= 1) s += __shfl_xor_sync(0xffffffffu, s, o);
        float inv = 1.f / s;
        sS[lane * 88 + col] = to_tf32(e0 * inv);
        if (lane + 32 < 71) sS[(lane + 32) * 88 + col] = to_tf32(e1 * inv);
        if (lane < 7)       sS[(lane + 64) * 88 + col] = to_tf32(e2 * inv);
    }
    __syncthreads();

    // ---- attn = P @ V -> g_attnH [m][512] fp16 ----
    {
        const float* sV = U;
        float acc[5][4] = {};
        #pragma unroll
        for (int ks = 0; ks < 9; ks++) {
            const int kk = ks * 8 + (lane & 3);
            unsigned bfr[2];
            const int n = w * 8 + (lane >> 2);
            bfr[0] = __float_as_uint(sV[kk * 72 + n]);
            bfr[1] = __float_as_uint(sV[(kk + 4) * 72 + n]);
            #pragma unroll
            for (int mt = 0; mt < 5; mt++) {
                unsigned afr[4];
                LDA(afr, sS, 88, mt, kk);
                mma_tf32(acc[mt], afr, bfr);
            }
        }
        const int n0 = w * 8 + 2 * (lane & 3);
        const int dcol = hidx * 64 + n0;
        #pragma unroll
        for (int mt = 0; mt < 5; mt++) {
            int r = mt * 16 + (lane >> 2);
            if (r < 71) {
                *(__half2*)&g_attnH[((size_t)(bidx * 71 + r)) * 512 + dcol] =
                    __floats2half2_rn(acc[mt][0], acc[mt][1]);
            }
            if (r + 8 < 71) {
                *(__half2*)&g_attnH[((size_t)(bidx * 71 + r + 8)) * 512 + dcol] =
                    __floats2half2_rn(acc[mt][2], acc[mt][3]);
            }
        }
    }
}

// ---------------------------------------------------------------------------
extern "C" void kernel_launch(void* const* d_in, const int* in_sizes, int n_in,
                              void* d_out, int out_size)
{
    const float* query = (const float*)d_in[0];
    const float* key   = (const float*)d_in[1];
    const float* value = (const float*)d_in[2];
    const float* Wq = (const float*)d_in[3];
    const float* bq = (const float*)d_in[4];
    const float* Wk = (const float*)d_in[5];
    const float* bk = (const float*)d_in[6];
    const float* Wv = (const float*)d_in[7];
    const float* bv = (const float*)d_in[8];
    const float* Wo = (const float*)d_in[9];
    const float* bo = (const float*)d_in[10];
    const float* sf_w1 = (const float*)d_in[11];
    const float* sf_b1 = (const float*)d_in[12];
    const float* sf_w2 = (const float*)d_in[13];
    const float* sf_b2 = (const float*)d_in[14];
    float* out = (float*)d_out;

    const int gemm_smem = 40960;                    // 2x2 buffers of [128][40] halfs
    cudaFuncSetAttribute(qkv_gemm_kernel, cudaFuncAttributeMaxDynamicSharedMemorySize, gemm_smem);
    cudaFuncSetAttribute(out_gemm_kernel, cudaFuncAttributeMaxDynamicSharedMemorySize, gemm_smem);
    const int attn_smem = 17600 * sizeof(float);    // 70400 B
    cudaFuncSetAttribute(attn_kernel, cudaFuncAttributeMaxDynamicSharedMemorySize, attn_smem);

    // 1) weight preps (fp16 transpose of big weights; tf32 pad of MLP weights)
    dim3 gw(16, 16, 4);
    wt16_kernel<<<gw, 256>>>(Wq, Wk, Wv, Wo);
    wprep_kernel<<<36, 256>>>(sf_w1, sf_w2);

    // 2) QKV projections (fp16 tensor cores, read inputs directly)
    dim3 g1(4, 284, 3);
    qkv_gemm_kernel<<<g1, 256, gemm_smem>>>(query, key, value, bq, bk, bv);

    // 3) attention core (1 head per CTA)
    attn_kernel<<<NHEADS, 256, attn_smem>>>(sf_b1, sf_b2);

    // 4) output projection (fp16 tensor cores)
    dim3 g3(4, 284);
    out_gemm_kernel<<<g3, 256, gemm_smem>>>(out, bo);
}

// round 11
// speedup vs baseline: 2.9902x; 1.2654x over previous
#include <cuda_runtime.h>
#include <cuda_fp16.h>
#include <math.h>

// Problem constants
#define BB   512
#define LL   71
#define DD   512
#define HH   8
#define DHH  64
#define MROWS (BB * LL)          // 36352 = 284*128
#define NHEADS (BB * HH)         // 4096
#define HEAD_ELEMS (LL * DHH)    // 4544

// ---------------------------------------------------------------------------
// Scratch (static device globals)
// ---------------------------------------------------------------------------
__device__ __half g_WT16[4][DD * DD];        // fp16 transposed weights [n][k]: q,k,v,o
__device__ __half g_Qh[NHEADS * HEAD_ELEMS]; // [bh][l][dh] fp16, pre-scaled by 1/8
__device__ __half g_Kh[NHEADS * HEAD_ELEMS]; // [bh][l][dh] fp16
__device__ __half g_Vth[NHEADS * HEAD_ELEMS];// [bh][dh][l] fp16 (transposed)
__device__ __half g_attnH[MROWS * DD];       // attn output [m][512] fp16 row-major
__device__ __half g_w1h[128 * 80];           // w1^T [ff][key] fp16, key 71..79 = 0
__device__ __half g_w2h[72 * 128];           // w2^T [key_out][ff] fp16, row 71 = 0

__device__ __forceinline__ void mma_f16(float* c, const unsigned* a, const unsigned* b) {
    asm volatile(
        "mma.sync.aligned.m16n8k16.row.col.f32.f16.f16.f32 "
        "{%0,%1,%2,%3}, {%4,%5,%6,%7}, {%8,%9}, {%0,%1,%2,%3};"
        : "+f"(c[0]), "+f"(c[1]), "+f"(c[2]), "+f"(c[3])
        : "r"(a[0]), "r"(a[1]), "r"(a[2]), "r"(a[3]), "r"(b[0]), "r"(b[1]));
}

__device__ __forceinline__ float gelu_exact(float x) {
    return 0.5f * x * (1.f + erff(x * 0.70710678118654752f));
}

// ---------------------------------------------------------------------------
// Weight transpose + fp16 cvt: W[k][n] fp32 -> g_WT16[z][n][k] fp16.
// ---------------------------------------------------------------------------
__global__ void __launch_bounds__(256) wt16_kernel(
    const float* __restrict__ w0, const float* __restrict__ w1,
    const float* __restrict__ w2, const float* __restrict__ w3)
{
    __shared__ float t[32][33];
    const float* in = (blockIdx.z == 0) ? w0 : (blockIdx.z == 1) ? w1
                    : (blockIdx.z == 2) ? w2 : w3;
    __half* out = g_WT16[blockIdx.z];
    const int k0 = blockIdx.x * 32, n0 = blockIdx.y * 32;
    const int tx = threadIdx.x & 31, ty = threadIdx.x >> 5;
    #pragma unroll
    for (int j = 0; j < 4; j++)
        t[ty + 8 * j][tx] = in[(size_t)(k0 + ty + 8 * j) * 512 + n0 + tx];
    __syncthreads();
    #pragma unroll
    for (int j = 0; j < 4; j++)
        out[(size_t)(n0 + ty + 8 * j) * 512 + k0 + tx] = __float2half_rn(t[tx][ty + 8 * j]);
}

// ---------------------------------------------------------------------------
// MLP weight transpose + pad + fp16 cvt.
// g_w1h[n*80+k] = w1[k][n] (k<71), else 0.   n in [0,128), k in [0,80)
// g_w2h[n*128+k] = w2[k][n] (n<71), else 0.  n in [0,72),  k in [0,128)
// ---------------------------------------------------------------------------
__global__ void __launch_bounds__(256) wprep_kernel(
    const float* __restrict__ w1, const float* __restrict__ w2)
{
    int i = blockIdx.x * 256 + threadIdx.x;
    if (i < 128 * 80) {
        int n = i / 80, k = i - n * 80;
        g_w1h[i] = (k < 71) ? __float2half_rn(w1[k * 128 + n]) : __half(0.f);
    }
    if (i < 72 * 128) {
        int n = i >> 7, k = i & 127;
        g_w2h[i] = (n < 71) ? __float2half_rn(w2[k * 71 + n]) : __half(0.f);
    }
}

// ---------------------------------------------------------------------------
// fp16 GEMM core: CTA 128x128, K=512, KC=32, double-buffered smem.
// A row-major [M][512] (fp32 or fp16); BT fp16 [n][k].
// ---------------------------------------------------------------------------
template<typename TA>
__device__ __forceinline__ void gemm_f16_ctile(
    const TA* __restrict__ A, const __half* __restrict__ BT,
    float (&c)[4][4][4])
{
    extern __shared__ __align__(16) __half smh[];
    __half* As = smh;            // [2][5120]
    __half* Bs = smh + 10240;    // [2][5120]

    const int tid  = threadIdx.x;
    const int lane = tid & 31;
    const int warp = tid >> 5;
    const int mBase = blockIdx.y * 128;
    const int nBase = blockIdx.x * 128;

    #pragma unroll
    for (int im = 0; im < 4; im++)
        #pragma unroll
        for (int in = 0; in < 4; in++)
            #pragma unroll
            for (int q = 0; q < 4; q++) c[im][in][q] = 0.f;

    float4 raf[4];
    uint4  rah[2];
    uint4  rbh[2];

    auto ldgA = [&](int kt) {
        if constexpr (sizeof(TA) == 4) {
            #pragma unroll
            for (int it = 0; it < 4; it++) {
                int idx = it * 256 + tid;
                int row = idx >> 3, c4 = idx & 7;
                raf[it] = *(const float4*)((const float*)A +
                    (size_t)(mBase + row) * 512 + kt * 32 + c4 * 4);
            }
        } else {
            #pragma unroll
            for (int it = 0; it < 2; it++) {
                int idx = it * 256 + tid;
                int row = idx >> 2, g = idx & 3;
                rah[it] = *(const uint4*)((const __half*)A +
                    (size_t)(mBase + row) * 512 + kt * 32 + g * 8);
            }
        }
    };
    auto ldgB = [&](int kt) {
        #pragma unroll
        for (int it = 0; it < 2; it++) {
            int idx = it * 256 + tid;
            int row = idx >> 2, g = idx & 3;
            rbh[it] = *(const uint4*)(BT + (size_t)(nBase + row) * 512 + kt * 32 + g * 8);
        }
    };
    auto stsA = [&](int buf) {
        if constexpr (sizeof(TA) == 4) {
            #pragma unroll
            for (int it = 0; it < 4; it++) {
                int idx = it * 256 + tid;
                int row = idx >> 3, c4 = idx & 7;
                __half2 h0 = __floats2half2_rn(raf[it].x, raf[it].y);
                __half2 h1 = __floats2half2_rn(raf[it].z, raf[it].w);
                *(__half2*)&As[buf * 5120 + row * 40 + c4 * 4]     = h0;
                *(__half2*)&As[buf * 5120 + row * 40 + c4 * 4 + 2] = h1;
            }
        } else {
            #pragma unroll
            for (int it = 0; it < 2; it++) {
                int idx = it * 256 + tid;
                int row = idx >> 2, g = idx & 3;
                *(uint4*)&As[buf * 5120 + row * 40 + g * 8] = rah[it];
            }
        }
    };
    auto stsB = [&](int buf) {
        #pragma unroll
        for (int it = 0; it < 2; it++) {
            int idx = it * 256 + tid;
            int row = idx >> 2, g = idx & 3;
            *(uint4*)&Bs[buf * 5120 + row * 40 + g * 8] = rbh[it];
        }
    };
    auto compute = [&](int buf) {
        const __half* Asb = As + buf * 5120;
        const __half* Bsb = Bs + buf * 5120;
        const int r0 = (warp & 1) * 64 + (lane >> 2);
        const int n0 = (warp >> 1) * 32 + (lane >> 2);
        #pragma unroll
        for (int ks = 0; ks < 2; ks++) {
            const int kb = ks * 16 + (lane & 3) * 2;
            unsigned a[4][4], b[4][2];
            #pragma unroll
            for (int mt = 0; mt < 4; mt++) {
                a[mt][0] = *(const unsigned*)&Asb[(r0 + mt * 16) * 40 + kb];
                a[mt][1] = *(const unsigned*)&Asb[(r0 + mt * 16 + 8) * 40 + kb];
                a[mt][2] = *(const unsigned*)&Asb[(r0 + mt * 16) * 40 + kb + 8];
                a[mt][3] = *(const unsigned*)&Asb[(r0 + mt * 16 + 8) * 40 + kb + 8];
            }
            #pragma unroll
            for (int nt = 0; nt < 4; nt++) {
                b[nt][0] = *(const unsigned*)&Bsb[(n0 + nt * 8) * 40 + kb];
                b[nt][1] = *(const unsigned*)&Bsb[(n0 + nt * 8) * 40 + kb + 8];
            }
            #pragma unroll
            for (int im = 0; im < 4; im++)
                #pragma unroll
                for (int in = 0; in < 4; in++)
                    mma_f16(c[im][in], a[im], b[in]);
        }
    };

    ldgA(0); ldgB(0);
    stsA(0); stsB(0);
    __syncthreads();
    #pragma unroll 1
    for (int kt = 0; kt < 16; kt++) {
        const int cur = kt & 1;
        if (kt < 15) { ldgA(kt + 1); ldgB(kt + 1); }
        compute(cur);
        if (kt < 15) { stsA(cur ^ 1); stsB(cur ^ 1); }
        __syncthreads();
    }
}

// ---------------------------------------------------------------------------
// QKV projection (fp16 mma): grid (4, 284, 3).
// Q/K -> fp16 natural [bh][l][dh]; V -> fp16 transposed [bh][dh][l].
// ---------------------------------------------------------------------------
__global__ void __launch_bounds__(256) qkv_gemm_kernel(
    const float* __restrict__ q_in, const float* __restrict__ k_in,
    const float* __restrict__ v_in,
    const float* __restrict__ bq, const float* __restrict__ bk,
    const float* __restrict__ bv)
{
    const float* A; const float* bias; __half* out; float scale;
    if (blockIdx.z == 0)      { A = q_in; bias = bq; out = g_Qh;  scale = 0.125f; }
    else if (blockIdx.z == 1) { A = k_in; bias = bk; out = g_Kh;  scale = 1.0f; }
    else                      { A = v_in; bias = bv; out = g_Vth; scale = 1.0f; }

    float c[4][4][4];
    gemm_f16_ctile<float>(A, g_WT16[blockIdx.z], c);

    const int lane = threadIdx.x & 31, warp = threadIdx.x >> 5;
    const int mBase = blockIdx.y * 128, nBase = blockIdx.x * 128;

    float bv2[4][2];
    #pragma unroll
    for (int in = 0; in < 4; in++) {
        int cg = nBase + (warp >> 1) * 32 + in * 8 + 2 * (lane & 3);
        bv2[in][0] = bias[cg]; bv2[in][1] = bias[cg + 1];
    }

    if (blockIdx.z <= 1) {
        // natural fp16 [bh][l][dh], half2 pairs
        #pragma unroll
        for (int im = 0; im < 4; im++) {
            int rg0 = mBase + (warp & 1) * 64 + im * 16 + (lane >> 2);
            int rg1 = rg0 + 8;
            int b0 = rg0 / 71, l0 = rg0 - b0 * 71;
            int b1 = rg1 / 71, l1 = rg1 - b1 * 71;
            #pragma unroll
            for (int in = 0; in < 4; in++) {
                int cg = nBase + (warp >> 1) * 32 + in * 8 + 2 * (lane & 3);
                int h = cg >> 6, dh = cg & 63;
                *(__half2*)&out[(((size_t)(b0 * 8 + h) * 71 + l0) << 6) + dh] =
                    __floats2half2_rn((c[im][in][0] + bv2[in][0]) * scale,
                                      (c[im][in][1] + bv2[in][1]) * scale);
                *(__half2*)&out[(((size_t)(b1 * 8 + h) * 71 + l1) << 6) + dh] =
                    __floats2half2_rn((c[im][in][2] + bv2[in][0]) * scale,
                                      (c[im][in][3] + bv2[in][1]) * scale);
            }
        }
    } else {
        // transposed fp16 [bh][dh][l]
        #pragma unroll
        for (int im = 0; im < 4; im++) {
            int rg0 = mBase + (warp & 1) * 64 + im * 16 + (lane >> 2);
            int rg1 = rg0 + 8;
            int b0 = rg0 / 71, l0 = rg0 - b0 * 71;
            int b1 = rg1 / 71, l1 = rg1 - b1 * 71;
            #pragma unroll
            for (int in = 0; in < 4; in++) {
                int cg = nBase + (warp >> 1) * 32 + in * 8 + 2 * (lane & 3);
                int h = cg >> 6, dh = cg & 63;
                size_t base0 = ((size_t)((b0 * 8 + h) * 64 + dh)) * 71 + l0;
                size_t base1 = ((size_t)((b1 * 8 + h) * 64 + dh)) * 71 + l1;
                out[base0]      = __float2half_rn(c[im][in][0] + bv2[in][0]);
                out[base0 + 71] = __float2half_rn(c[im][in][1] + bv2[in][1]);
                out[base1]      = __float2half_rn(c[im][in][2] + bv2[in][0]);
                out[base1 + 71] = __float2half_rn(c[im][in][3] + bv2[in][1]);
            }
        }
    }
}

// ---------------------------------------------------------------------------
// Output projection (fp16 mma, A = g_attnH): grid (4, 284).
// ---------------------------------------------------------------------------
__global__ void __launch_bounds__(256) out_gemm_kernel(
    float* __restrict__ out, const float* __restrict__ bo)
{
    float c[4][4][4];
    gemm_f16_ctile<__half>(g_attnH, g_WT16[3], c);

    const int lane = threadIdx.x & 31, warp = threadIdx.x >> 5;
    const int mBase = blockIdx.y * 128, nBase = blockIdx.x * 128;

    float bv2[4][2];
    #pragma unroll
    for (int in = 0; in < 4; in++) {
        int cg = nBase + (warp >> 1) * 32 + in * 8 + 2 * (lane & 3);
        bv2[in][0] = bo[cg]; bv2[in][1] = bo[cg + 1];
    }
    #pragma unroll
    for (int im = 0; im < 4; im++) {
        int rg0 = mBase + (warp & 1) * 64 + im * 16 + (lane >> 2);
        int rg1 = rg0 + 8;
        #pragma unroll
        for (int in = 0; in < 4; in++) {
            int cg = nBase + (warp >> 1) * 32 + in * 8 + 2 * (lane & 3);
            float2 v0 = make_float2(c[im][in][0] + bv2[in][0], c[im][in][1] + bv2[in][1]);
            float2 v1 = make_float2(c[im][in][2] + bv2[in][0], c[im][in][3] + bv2[in][1]);
            *(float2*)&out[(size_t)rg0 * 512 + cg] = v0;
            *(float2*)&out[(size_t)rg1 * 512 + cg] = v1;
        }
    }
}

// ---------------------------------------------------------------------------
// fp16 attention stages. All smem strides in halfs: 72 (≡4 words mod 32),
// 88 (≡12), 136 (≡4) — conflict-free for all fragment accesses.
// S: [80 q][88] fp16 row-major (cols 72..79 zero).
// ---------------------------------------------------------------------------

// Stage 1: S = Q @ K^T. A = sQ [80][72] (K=64); B = sK [72][72].
template<int NS>
__device__ __forceinline__ void f16_stage1(
    __half* __restrict__ sS, const __half* __restrict__ sQ,
    const __half* __restrict__ sK, int w, int lane)
{
    float acc[NS][5][4] = {};
    #pragma unroll
    for (int ks = 0; ks < 4; ks++) {
        const int kb = ks * 16 + (lane & 3) * 2;
        unsigned bfr[NS][2];
        #pragma unroll
        for (int s = 0; s < NS; s++) {
            const int n = (w + s * 8) * 8 + (lane >> 2);
            bfr[s][0] = *(const unsigned*)&sK[n * 72 + kb];
            bfr[s][1] = *(const unsigned*)&sK[n * 72 + kb + 8];
        }
        #pragma unroll
        for (int mt = 0; mt < 5; mt++) {
            const int r = mt * 16 + (lane >> 2);
            unsigned afr[4];
            afr[0] = *(const unsigned*)&sQ[r * 72 + kb];
            afr[1] = *(const unsigned*)&sQ[(r + 8) * 72 + kb];
            afr[2] = *(const unsigned*)&sQ[r * 72 + kb + 8];
            afr[3] = *(const unsigned*)&sQ[(r + 8) * 72 + kb + 8];
            #pragma unroll
            for (int s = 0; s < NS; s++) mma_f16(acc[s][mt], afr, bfr[s]);
        }
    }
    #pragma unroll
    for (int s = 0; s < NS; s++) {
        const int n0c = (w + s * 8) * 8 + 2 * (lane & 3);
        #pragma unroll
        for (int mt = 0; mt < 5; mt++) {
            const int r = mt * 16 + (lane >> 2);
            *(__half2*)&sS[r * 88 + n0c] =
                __floats2half2_rn(acc[s][mt][0], acc[s][mt][1]);
            *(__half2*)&sS[(r + 8) * 88 + n0c] =
                __floats2half2_rn(acc[s][mt][2], acc[s][mt][3]);
        }
    }
}

// Stage 2: H = gelu(S @ w1 + b1). A = sS [80][88] (K=80); B = g_w1h global.
__device__ __forceinline__ void f16_stage2(
    __half* __restrict__ sH, const __half* __restrict__ sS,
    const float* __restrict__ b1, int w, int lane)
{
    float acc[2][5][4] = {};
    #pragma unroll
    for (int ks = 0; ks < 5; ks++) {
        const int kb = ks * 16 + (lane & 3) * 2;
        unsigned bfr[2][2];
        #pragma unroll
        for (int s = 0; s < 2; s++) {
            const int n = (w + s * 8) * 8 + (lane >> 2);
            bfr[s][0] = __ldg((const unsigned*)&g_w1h[n * 80 + kb]);
            bfr[s][1] = __ldg((const unsigned*)&g_w1h[n * 80 + kb + 8]);
        }
        #pragma unroll
        for (int mt = 0; mt < 5; mt++) {
            const int r = mt * 16 + (lane >> 2);
            unsigned afr[4];
            afr[0] = *(const unsigned*)&sS[r * 88 + kb];
            afr[1] = *(const unsigned*)&sS[(r + 8) * 88 + kb];
            afr[2] = *(const unsigned*)&sS[r * 88 + kb + 8];
            afr[3] = *(const unsigned*)&sS[(r + 8) * 88 + kb + 8];
            mma_f16(acc[0][mt], afr, bfr[0]);
            mma_f16(acc[1][mt], afr, bfr[1]);
        }
    }
    #pragma unroll
    for (int s = 0; s < 2; s++) {
        const int n0c = (w + s * 8) * 8 + 2 * (lane & 3);
        const float bb0 = __ldg(b1 + n0c), bb1 = __ldg(b1 + n0c + 1);
        #pragma unroll
        for (int mt = 0; mt < 5; mt++) {
            const int r = mt * 16 + (lane >> 2);
            *(__half2*)&sH[r * 136 + n0c] =
                __floats2half2_rn(gelu_exact(acc[s][mt][0] + bb0),
                                  gelu_exact(acc[s][mt][1] + bb1));
            *(__half2*)&sH[(r + 8) * 136 + n0c] =
                __floats2half2_rn(gelu_exact(acc[s][mt][2] + bb0),
                                  gelu_exact(acc[s][mt][3] + bb1));
        }
    }
}

// Stage 3: S += H @ w2 + b2. A = sH [80][136] (K=128); B = g_w2h global.
template<int NS>
__device__ __forceinline__ void f16_stage3(
    __half* __restrict__ sS, const __half* __restrict__ sH,
    const float* __restrict__ b2, int w, int lane)
{
    float acc[NS][5][4] = {};
    #pragma unroll
    for (int ks = 0; ks < 8; ks++) {
        const int kb = ks * 16 + (lane & 3) * 2;
        unsigned bfr[NS][2];
        #pragma unroll
        for (int s = 0; s < NS; s++) {
            const int n = (w + s * 8) * 8 + (lane >> 2);
            bfr[s][0] = __ldg((const unsigned*)&g_w2h[n * 128 + kb]);
            bfr[s][1] = __ldg((const unsigned*)&g_w2h[n * 128 + kb + 8]);
        }
        #pragma unroll
        for (int mt = 0; mt < 5; mt++) {
            const int r = mt * 16 + (lane >> 2);
            unsigned afr[4];
            afr[0] = *(const unsigned*)&sH[r * 136 + kb];
            afr[1] = *(const unsigned*)&sH[(r + 8) * 136 + kb];
            afr[2] = *(const unsigned*)&sH[r * 136 + kb + 8];
            afr[3] = *(const unsigned*)&sH[(r + 8) * 136 + kb + 8];
            #pragma unroll
            for (int s = 0; s < NS; s++) mma_f16(acc[s][mt], afr, bfr[s]);
        }
    }
    #pragma unroll
    for (int s = 0; s < NS; s++) {
        const int n0c = (w + s * 8) * 8 + 2 * (lane & 3);
        const float bb0 = __ldg(b2 + n0c);
        const float bb1 = (n0c + 1 < 71) ? __ldg(b2 + n0c + 1) : 0.f;
        #pragma unroll
        for (int mt = 0; mt < 5; mt++) {
            const int r = mt * 16 + (lane >> 2);
            __half2 o0 = *(__half2*)&sS[r * 88 + n0c];
            __half2 o1 = *(__half2*)&sS[(r + 8) * 88 + n0c];
            *(__half2*)&sS[r * 88 + n0c] =
                __floats2half2_rn(__low2float(o0) + acc[s][mt][0] + bb0,
                                  __high2float(o0) + acc[s][mt][1] + bb1);
            *(__half2*)&sS[(r + 8) * 88 + n0c] =
                __floats2half2_rn(__low2float(o1) + acc[s][mt][2] + bb0,
                                  __high2float(o1) + acc[s][mt][3] + bb1);
        }
    }
}

// ---------------------------------------------------------------------------
// Attention core: ONE head per CTA, 256 threads, fp16 mma. Grid = 4096.
// smem halfs (17984 = 35968 B): sS [80][88] at 0; union U at 7040:
//   stage1: sQ [80][72] + sK [72][72] (10944); stage2-3: sH [80][136] (10880);
//   PV: sVt [64][88] (5632).
// ---------------------------------------------------------------------------
__global__ void __launch_bounds__(256, 4) attn_kernel(
    const float* __restrict__ b1, const float* __restrict__ b2)
{
    extern __shared__ __align__(16) __half smA[];
    __half* sS = smA;           // [80][88]
    __half* U  = smA + 7040;

    const int tid  = threadIdx.x;
    const int lane = tid & 31;
    const int w    = tid >> 5;      // 0..7
    const int bh   = blockIdx.x;
    const int bidx = bh >> 3, hidx = bh & 7;

    // ---- fills: Q [l][dh] -> sQ[80][72]; K -> sK[72][72]; zero pads ----
    {
        __half* sQ = U;
        __half* sK = U + 5760;
        const __half2* Qg = (const __half2*)(g_Qh + (size_t)bh * HEAD_ELEMS);
        const __half2* Kg = (const __half2*)(g_Kh + (size_t)bh * HEAD_ELEMS);
        for (int u = tid; u < 71 * 32; u += 256) {
            int l = u >> 5, d2 = (u & 31) << 1;
            *(__half2*)&sQ[l * 72 + d2] = Qg[u];
            *(__half2*)&sK[l * 72 + d2] = Kg[u];
        }
        // zero Q rows 71..79 (9*36 uints), K row 71 (36 uints)
        for (int i = tid; i < 9 * 36; i += 256) {
            int r = 71 + i / 36, c2 = (i % 36) << 1;
            *(unsigned*)&sQ[r * 72 + c2] = 0u;
        }
        if (tid < 36) *(unsigned*)&sK[71 * 72 + tid * 2] = 0u;
        // zero sS pad cols 72..79 (80 rows x 4 uints)
        for (int i = tid; i < 80 * 4; i += 256) {
            int r = i >> 2, c = 72 + ((i & 3) << 1);
            *(unsigned*)&sS[r * 88 + c] = 0u;
        }
    }
    __syncthreads();

    // ---- stage 1: S = Q @ K^T -> sS[q][key] fp16 ----
    if (w == 0) f16_stage1<2>(sS, U, U + 5760, w, lane);
    else        f16_stage1<1>(sS, U, U + 5760, w, lane);
    __syncthreads();

    // ---- stage 2: H = gelu(S @ w1 + b1) -> sH[q][ff] fp16 ----
    f16_stage2(U, sS, b1, w, lane);
    __syncthreads();

    // ---- stage 3: S += H @ w2 + b2 (in place, fp16) ----
    if (w == 0) f16_stage3<2>(sS, U, b2, w, lane);
    else        f16_stage3<1>(sS, U, b2, w, lane);
    __syncthreads();

    // ---- V^T fill into U + warp-per-row softmax over keys ----
    {
        __half* sVt = U;         // [64][88]
        const __half* Vg = g_Vth + (size_t)bh * HEAD_ELEMS;
        for (int i = tid; i < HEAD_ELEMS; i += 256) {
            int dh = i / 71, l = i - dh * 71;
            sVt[dh * 88 + l] = Vg[i];
        }
        for (int i = tid; i < 64 * 9; i += 256) {   // zero cols 71..79
            int dh = i / 9, c = 71 + (i - dh * 9);
            sVt[dh * 88 + c] = __half(0.f);
        }
    }
    __syncwarp();
    for (int q = w; q < 71; q += 8) {
        __half* row = sS + q * 88;
        float v0 = __half2float(row[lane]);
        float v1 = (lane + 32 < 71) ? __half2float(row[lane + 32]) : -1e30f;
        float v2 = (lane < 7)       ? __half2float(row[lane + 64]) : -1e30f;
        float m = fmaxf(v0, fmaxf(v1, v2));
        #pragma unroll
        for (int o = 16; o > 0; o >>= 1) m = fmaxf(m, __shfl_xor_sync(0xffffffffu, m, o));
        float e0 = __expf(v0 - m);
        float e1 = (lane + 32 < 71) ? __expf(v1 - m) : 0.f;
        float e2 = (lane < 7)       ? __expf(v2 - m) : 0.f;
        float s = e0 + e1 + e2;
        #pragma unroll
        for (int o = 16; o > 0; o >>= 1) s += __shfl_xor_sync(0xffffffffu, s, o);
        float inv = 1.f / s;
        row[lane] = __float2half_rn(e0 * inv);
        if (lane + 32 < 71) row[lane + 32] = __float2half_rn(e1 * inv);
        if (lane < 7)       row[lane + 64] = __float2half_rn(e2 * inv);
    }
    __syncthreads();

    // ---- PV: attn = P @ V -> g_attnH [m][512] fp16 ----
    {
        const __half* sVt = U;
        float acc[5][4] = {};
        #pragma unroll
        for (int ks = 0; ks < 5; ks++) {
            const int kb = ks * 16 + (lane & 3) * 2;
            unsigned bfr[2];
            const int n = w * 8 + (lane >> 2);
            bfr[0] = *(const unsigned*)&sVt[n * 88 + kb];
            bfr[1] = *(const unsigned*)&sVt[n * 88 + kb + 8];
            #pragma unroll
            for (int mt = 0; mt < 5; mt++) {
                const int r = mt * 16 + (lane >> 2);
                unsigned afr[4];
                afr[0] = *(const unsigned*)&sS[r * 88 + kb];
                afr[1] = *(const unsigned*)&sS[(r + 8) * 88 + kb];
                afr[2] = *(const unsigned*)&sS[r * 88 + kb + 8];
                afr[3] = *(const unsigned*)&sS[(r + 8) * 88 + kb + 8];
                mma_f16(acc[mt], afr, bfr);
            }
        }
        const int n0 = w * 8 + 2 * (lane & 3);
        const int dcol = hidx * 64 + n0;
        #pragma unroll
        for (int mt = 0; mt < 5; mt++) {
            int r = mt * 16 + (lane >> 2);
            if (r < 71) {
                *(__half2*)&g_attnH[((size_t)(bidx * 71 + r)) * 512 + dcol] =
                    __floats2half2_rn(acc[mt][0], acc[mt][1]);
            }
            if (r + 8 < 71) {
                *(__half2*)&g_attnH[((size_t)(bidx * 71 + r + 8)) * 512 + dcol] =
                    __floats2half2_rn(acc[mt][2], acc[mt][3]);
            }
        }
    }
}

// ---------------------------------------------------------------------------
extern "C" void kernel_launch(void* const* d_in, const int* in_sizes, int n_in,
                              void* d_out, int out_size)
{
    const float* query = (const float*)d_in[0];
    const float* key   = (const float*)d_in[1];
    const float* value = (const float*)d_in[2];
    const float* Wq = (const float*)d_in[3];
    const float* bq = (const float*)d_in[4];
    const float* Wk = (const float*)d_in[5];
    const float* bk = (const float*)d_in[6];
    const float* Wv = (const float*)d_in[7];
    const float* bv = (const float*)d_in[8];
    const float* Wo = (const float*)d_in[9];
    const float* bo = (const float*)d_in[10];
    const float* sf_w1 = (const float*)d_in[11];
    const float* sf_b1 = (const float*)d_in[12];
    const float* sf_w2 = (const float*)d_in[13];
    const float* sf_b2 = (const float*)d_in[14];
    float* out = (float*)d_out;

    const int gemm_smem = 40960;
    cudaFuncSetAttribute(qkv_gemm_kernel, cudaFuncAttributeMaxDynamicSharedMemorySize, gemm_smem);
    cudaFuncSetAttribute(out_gemm_kernel, cudaFuncAttributeMaxDynamicSharedMemorySize, gemm_smem);
    const int attn_smem = 17984 * 2;   // 35968 B
    cudaFuncSetAttribute(attn_kernel, cudaFuncAttributeMaxDynamicSharedMemorySize, attn_smem);

    // 1) weight preps
    dim3 gw(16, 16, 4);
    wt16_kernel<<<gw, 256>>>(Wq, Wk, Wv, Wo);
    wprep_kernel<<<40, 256>>>(sf_w1, sf_w2);

    // 2) QKV projections (fp16 tensor cores)
    dim3 g1(4, 284, 3);
    qkv_gemm_kernel<<<g1, 256, gemm_smem>>>(query, key, value, bq, bk, bv);

    // 3) attention core (fp16 mma, 1 head per CTA, 4 CTAs/SM)
    attn_kernel<<<NHEADS, 256, attn_smem>>>(sf_b1, sf_b2);

    // 4) output projection (fp16 tensor cores)
    dim3 g3(4, 284);
    out_gemm_kernel<<<g3, 256, gemm_smem>>>(out, bo);
}

// round 12
// speedup vs baseline: 3.1610x; 1.0571x over previous
#include <cuda_runtime.h>
#include <cuda_fp16.h>
#include <math.h>
#include <stdint.h>

// Problem constants
#define BB   512
#define LL   71
#define DD   512
#define HH   8
#define DHH  64
#define MROWS (BB * LL)          // 36352 = 284*128
#define NHEADS (BB * HH)         // 4096
#define HEAD_ELEMS (LL * DHH)    // 4544

// ---------------------------------------------------------------------------
// Scratch (static device globals)
// ---------------------------------------------------------------------------
__device__ __half g_WT16[4][DD * DD];        // fp16 transposed weights [n][k]: q,k,v,o
__device__ __half g_Qh[NHEADS * HEAD_ELEMS]; // [bh][l][dh] fp16, pre-scaled by 1/8
__device__ __half g_Kh[NHEADS * HEAD_ELEMS]; // [bh][l][dh] fp16
__device__ __half g_Vth[NHEADS * HEAD_ELEMS];// [bh][dh][l] fp16 (transposed)
__device__ __half g_attnH[MROWS * DD];       // attn output [m][512] fp16 row-major
__device__ __half g_w1h[128 * 80];           // w1^T [ff][key] fp16, key 71..79 = 0
__device__ __half g_w2h[72 * 128];           // w2^T [key_out][ff] fp16, row 71 = 0

__device__ __forceinline__ void mma_f16(float* c, const unsigned* a, const unsigned* b) {
    asm volatile(
        "mma.sync.aligned.m16n8k16.row.col.f32.f16.f16.f32 "
        "{%0,%1,%2,%3}, {%4,%5,%6,%7}, {%8,%9}, {%0,%1,%2,%3};"
        : "+f"(c[0]), "+f"(c[1]), "+f"(c[2]), "+f"(c[3])
        : "r"(a[0]), "r"(a[1]), "r"(a[2]), "r"(a[3]), "r"(b[0]), "r"(b[1]));
}

__device__ __forceinline__ void ldsm_x4(unsigned* r, uint32_t addr) {
    asm volatile("ldmatrix.sync.aligned.m8n8.x4.shared.b16 {%0,%1,%2,%3}, [%4];"
        : "=r"(r[0]), "=r"(r[1]), "=r"(r[2]), "=r"(r[3]) : "r"(addr));
}

__device__ __forceinline__ void ldsm_x2(unsigned* r, uint32_t addr) {
    asm volatile("ldmatrix.sync.aligned.m8n8.x2.shared.b16 {%0,%1}, [%2];"
        : "=r"(r[0]), "=r"(r[1]) : "r"(addr));
}

__device__ __forceinline__ uint32_t smem_u32(const void* p) {
    uint32_t a;
    asm("{ .reg .u64 t; cvta.to.shared.u64 t, %1; cvt.u32.u64 %0, t; }"
        : "=r"(a) : "l"(p));
    return a;
}

__device__ __forceinline__ float gelu_exact(float x) {
    return 0.5f * x * (1.f + erff(x * 0.70710678118654752f));
}

// ---------------------------------------------------------------------------
// Weight transpose + fp16 cvt: W[k][n] fp32 -> g_WT16[z][n][k] fp16.
// ---------------------------------------------------------------------------
__global__ void __launch_bounds__(256) wt16_kernel(
    const float* __restrict__ w0, const float* __restrict__ w1,
    const float* __restrict__ w2, const float* __restrict__ w3)
{
    __shared__ float t[32][33];
    const float* in = (blockIdx.z == 0) ? w0 : (blockIdx.z == 1) ? w1
                    : (blockIdx.z == 2) ? w2 : w3;
    __half* out = g_WT16[blockIdx.z];
    const int k0 = blockIdx.x * 32, n0 = blockIdx.y * 32;
    const int tx = threadIdx.x & 31, ty = threadIdx.x >> 5;
    #pragma unroll
    for (int j = 0; j < 4; j++)
        t[ty + 8 * j][tx] = in[(size_t)(k0 + ty + 8 * j) * 512 + n0 + tx];
    __syncthreads();
    #pragma unroll
    for (int j = 0; j < 4; j++)
        out[(size_t)(n0 + ty + 8 * j) * 512 + k0 + tx] = __float2half_rn(t[tx][ty + 8 * j]);
}

// ---------------------------------------------------------------------------
// MLP weight transpose + pad + fp16 cvt.
// ---------------------------------------------------------------------------
__global__ void __launch_bounds__(256) wprep_kernel(
    const float* __restrict__ w1, const float* __restrict__ w2)
{
    int i = blockIdx.x * 256 + threadIdx.x;
    if (i < 128 * 80) {
        int n = i / 80, k = i - n * 80;
        g_w1h[i] = (k < 71) ? __float2half_rn(w1[k * 128 + n]) : __half(0.f);
    }
    if (i < 72 * 128) {
        int n = i >> 7, k = i & 127;
        g_w2h[i] = (n < 71) ? __float2half_rn(w2[k * 71 + n]) : __half(0.f);
    }
}

// ---------------------------------------------------------------------------
// fp16 GEMM core: CTA 128x128, K=512, KC=32, double-buffered smem, LDSM.
// A row-major [M][512] (fp32 or fp16); BT fp16 [n][k].
// ---------------------------------------------------------------------------
template<typename TA>
__device__ __forceinline__ void gemm_f16_ctile(
    const TA* __restrict__ A, const __half* __restrict__ BT,
    float (&c)[4][4][4])
{
    extern __shared__ __align__(16) __half smh[];
    __half* As = smh;            // [2][5120]
    __half* Bs = smh + 10240;    // [2][5120]

    const int tid  = threadIdx.x;
    const int lane = tid & 31;
    const int warp = tid >> 5;
    const int mBase = blockIdx.y * 128;
    const int nBase = blockIdx.x * 128;
    const uint32_t smem_addr = smem_u32(smh);

    #pragma unroll
    for (int im = 0; im < 4; im++)
        #pragma unroll
        for (int in = 0; in < 4; in++)
            #pragma unroll
            for (int q = 0; q < 4; q++) c[im][in][q] = 0.f;

    float4 raf[4];
    uint4  rah[2];
    uint4  rbh[2];

    auto ldgA = [&](int kt) {
        if constexpr (sizeof(TA) == 4) {
            #pragma unroll
            for (int it = 0; it < 4; it++) {
                int idx = it * 256 + tid;
                int row = idx >> 3, c4 = idx & 7;
                raf[it] = *(const float4*)((const float*)A +
                    (size_t)(mBase + row) * 512 + kt * 32 + c4 * 4);
            }
        } else {
            #pragma unroll
            for (int it = 0; it < 2; it++) {
                int idx = it * 256 + tid;
                int row = idx >> 2, g = idx & 3;
                rah[it] = *(const uint4*)((const __half*)A +
                    (size_t)(mBase + row) * 512 + kt * 32 + g * 8);
            }
        }
    };
    auto ldgB = [&](int kt) {
        #pragma unroll
        for (int it = 0; it < 2; it++) {
            int idx = it * 256 + tid;
            int row = idx >> 2, g = idx & 3;
            rbh[it] = *(const uint4*)(BT + (size_t)(nBase + row) * 512 + kt * 32 + g * 8);
        }
    };
    auto stsA = [&](int buf) {
        if constexpr (sizeof(TA) == 4) {
            #pragma unroll
            for (int it = 0; it < 4; it++) {
                int idx = it * 256 + tid;
                int row = idx >> 3, c4 = idx & 7;
                __half2 h0 = __floats2half2_rn(raf[it].x, raf[it].y);
                __half2 h1 = __floats2half2_rn(raf[it].z, raf[it].w);
                *(__half2*)&As[buf * 5120 + row * 40 + c4 * 4]     = h0;
                *(__half2*)&As[buf * 5120 + row * 40 + c4 * 4 + 2] = h1;
            }
        } else {
            #pragma unroll
            for (int it = 0; it < 2; it++) {
                int idx = it * 256 + tid;
                int row = idx >> 2, g = idx & 3;
                *(uint4*)&As[buf * 5120 + row * 40 + g * 8] = rah[it];
            }
        }
    };
    auto stsB = [&](int buf) {
        #pragma unroll
        for (int it = 0; it < 2; it++) {
            int idx = it * 256 + tid;
            int row = idx >> 2, g = idx & 3;
            *(uint4*)&Bs[buf * 5120 + row * 40 + g * 8] = rbh[it];
        }
    };
    auto compute = [&](int buf) {
        const uint32_t abase = smem_addr + buf * 10240 +
            (((warp & 1) * 64 + (lane & 15)) * 40 + (lane >> 4) * 8) * 2;
        const uint32_t bbase = smem_addr + 20480 + buf * 10240 +
            (((warp >> 1) * 32 + (lane & 7)) * 40 + (lane >> 3) * 8) * 2;
        #pragma unroll
        for (int ks = 0; ks < 2; ks++) {
            unsigned a[4][4], b[4][2];
            #pragma unroll
            for (int mt = 0; mt < 4; mt++) ldsm_x4(a[mt], abase + mt * 1280 + ks * 32);
            #pragma unroll
            for (int nt = 0; nt < 4; nt++) ldsm_x2(b[nt], bbase + nt * 640 + ks * 32);
            #pragma unroll
            for (int im = 0; im < 4; im++)
                #pragma unroll
                for (int in = 0; in < 4; in++)
                    mma_f16(c[im][in], a[im], b[in]);
        }
    };

    ldgA(0); ldgB(0);
    stsA(0); stsB(0);
    __syncthreads();
    #pragma unroll 1
    for (int kt = 0; kt < 16; kt++) {
        const int cur = kt & 1;
        if (kt < 15) { ldgA(kt + 1); ldgB(kt + 1); }
        compute(cur);
        if (kt < 15) { stsA(cur ^ 1); stsB(cur ^ 1); }
        __syncthreads();
    }
}

// ---------------------------------------------------------------------------
// QKV projection (fp16 mma): grid (4, 284, 3).
// Q/K -> fp16 natural [bh][l][dh]; V -> fp16 transposed [bh][dh][l].
// ---------------------------------------------------------------------------
__global__ void __launch_bounds__(256) qkv_gemm_kernel(
    const float* __restrict__ q_in, const float* __restrict__ k_in,
    const float* __restrict__ v_in,
    const float* __restrict__ bq, const float* __restrict__ bk,
    const float* __restrict__ bv)
{
    const float* A; const float* bias; __half* out; float scale;
    if (blockIdx.z == 0)      { A = q_in; bias = bq; out = g_Qh;  scale = 0.125f; }
    else if (blockIdx.z == 1) { A = k_in; bias = bk; out = g_Kh;  scale = 1.0f; }
    else                      { A = v_in; bias = bv; out = g_Vth; scale = 1.0f; }

    float c[4][4][4];
    gemm_f16_ctile<float>(A, g_WT16[blockIdx.z], c);

    const int lane = threadIdx.x & 31, warp = threadIdx.x >> 5;
    const int mBase = blockIdx.y * 128, nBase = blockIdx.x * 128;

    float bv2[4][2];
    #pragma unroll
    for (int in = 0; in < 4; in++) {
        int cg = nBase + (warp >> 1) * 32 + in * 8 + 2 * (lane & 3);
        bv2[in][0] = bias[cg]; bv2[in][1] = bias[cg + 1];
    }

    if (blockIdx.z <= 1) {
        #pragma unroll
        for (int im = 0; im < 4; im++) {
            int rg0 = mBase + (warp & 1) * 64 + im * 16 + (lane >> 2);
            int rg1 = rg0 + 8;
            int b0 = rg0 / 71, l0 = rg0 - b0 * 71;
            int b1 = rg1 / 71, l1 = rg1 - b1 * 71;
            #pragma unroll
            for (int in = 0; in < 4; in++) {
                int cg = nBase + (warp >> 1) * 32 + in * 8 + 2 * (lane & 3);
                int h = cg >> 6, dh = cg & 63;
                *(__half2*)&out[(((size_t)(b0 * 8 + h) * 71 + l0) << 6) + dh] =
                    __floats2half2_rn((c[im][in][0] + bv2[in][0]) * scale,
                                      (c[im][in][1] + bv2[in][1]) * scale);
                *(__half2*)&out[(((size_t)(b1 * 8 + h) * 71 + l1) << 6) + dh] =
                    __floats2half2_rn((c[im][in][2] + bv2[in][0]) * scale,
                                      (c[im][in][3] + bv2[in][1]) * scale);
            }
        }
    } else {
        #pragma unroll
        for (int im = 0; im < 4; im++) {
            int rg0 = mBase + (warp & 1) * 64 + im * 16 + (lane >> 2);
            int rg1 = rg0 + 8;
            int b0 = rg0 / 71, l0 = rg0 - b0 * 71;
            int b1 = rg1 / 71, l1 = rg1 - b1 * 71;
            #pragma unroll
            for (int in = 0; in < 4; in++) {
                int cg = nBase + (warp >> 1) * 32 + in * 8 + 2 * (lane & 3);
                int h = cg >> 6, dh = cg & 63;
                size_t base0 = ((size_t)((b0 * 8 + h) * 64 + dh)) * 71 + l0;
                size_t base1 = ((size_t)((b1 * 8 + h) * 64 + dh)) * 71 + l1;
                out[base0]      = __float2half_rn(c[im][in][0] + bv2[in][0]);
                out[base0 + 71] = __float2half_rn(c[im][in][1] + bv2[in][1]);
                out[base1]      = __float2half_rn(c[im][in][2] + bv2[in][0]);
                out[base1 + 71] = __float2half_rn(c[im][in][3] + bv2[in][1]);
            }
        }
    }
}

// ---------------------------------------------------------------------------
// Output projection (fp16 mma, A = g_attnH): grid (4, 284).
// ---------------------------------------------------------------------------
__global__ void __launch_bounds__(256) out_gemm_kernel(
    float* __restrict__ out, const float* __restrict__ bo)
{
    float c[4][4][4];
    gemm_f16_ctile<__half>(g_attnH, g_WT16[3], c);

    const int lane = threadIdx.x & 31, warp = threadIdx.x >> 5;
    const int mBase = blockIdx.y * 128, nBase = blockIdx.x * 128;

    float bv2[4][2];
    #pragma unroll
    for (int in = 0; in < 4; in++) {
        int cg = nBase + (warp >> 1) * 32 + in * 8 + 2 * (lane & 3);
        bv2[in][0] = bo[cg]; bv2[in][1] = bo[cg + 1];
    }
    #pragma unroll
    for (int im = 0; im < 4; im++) {
        int rg0 = mBase + (warp & 1) * 64 + im * 16 + (lane >> 2);
        int rg1 = rg0 + 8;
        #pragma unroll
        for (int in = 0; in < 4; in++) {
            int cg = nBase + (warp >> 1) * 32 + in * 8 + 2 * (lane & 3);
            float2 v0 = make_float2(c[im][in][0] + bv2[in][0], c[im][in][1] + bv2[in][1]);
            float2 v1 = make_float2(c[im][in][2] + bv2[in][0], c[im][in][3] + bv2[in][1]);
            *(float2*)&out[(size_t)rg0 * 512 + cg] = v0;
            *(float2*)&out[(size_t)rg1 * 512 + cg] = v1;
        }
    }
}

// ---------------------------------------------------------------------------
// fp16 attention stages with LDSM fragment loads.
// S: [80 q][88] fp16 row-major (cols 72..79 zero).
// ---------------------------------------------------------------------------

// Stage 1: S = Q @ K^T. A = sQ [80][72] (K=64); B = sK [72][72].
template<int NS>
__device__ __forceinline__ void f16_stage1(
    __half* __restrict__ sS, const __half* __restrict__ sQ,
    const __half* __restrict__ sK, int w, int lane)
{
    float acc[NS][5][4] = {};
    const uint32_t qa = smem_u32(sQ) + ((lane & 15) * 72 + (lane >> 4) * 8) * 2;
    const uint32_t ka = smem_u32(sK) + ((w * 8 + (lane & 7)) * 72 + (lane >> 3) * 8) * 2;
    #pragma unroll
    for (int ks = 0; ks < 4; ks++) {
        unsigned bfr[NS][2];
        #pragma unroll
        for (int s = 0; s < NS; s++)
            ldsm_x2(bfr[s], ka + s * (64 * 72 * 2) + ks * 32);
        #pragma unroll
        for (int mt = 0; mt < 5; mt++) {
            unsigned afr[4];
            ldsm_x4(afr, qa + mt * (16 * 72 * 2) + ks * 32);
            #pragma unroll
            for (int s = 0; s < NS; s++) mma_f16(acc[s][mt], afr, bfr[s]);
        }
    }
    #pragma unroll
    for (int s = 0; s < NS; s++) {
        const int n0c = (w + s * 8) * 8 + 2 * (lane & 3);
        #pragma unroll
        for (int mt = 0; mt < 5; mt++) {
            const int r = mt * 16 + (lane >> 2);
            *(__half2*)&sS[r * 88 + n0c] =
                __floats2half2_rn(acc[s][mt][0], acc[s][mt][1]);
            *(__half2*)&sS[(r + 8) * 88 + n0c] =
                __floats2half2_rn(acc[s][mt][2], acc[s][mt][3]);
        }
    }
}

// Stage 2: H = gelu(S @ w1 + b1). A = sS [80][88] (K=80); B = g_w1h global.
__device__ __forceinline__ void f16_stage2(
    __half* __restrict__ sH, const __half* __restrict__ sS,
    const float* __restrict__ b1, int w, int lane)
{
    float acc[2][5][4] = {};
    const uint32_t sa = smem_u32(sS) + ((lane & 15) * 88 + (lane >> 4) * 8) * 2;
    #pragma unroll
    for (int ks = 0; ks < 5; ks++) {
        const int kb = ks * 16 + (lane & 3) * 2;
        unsigned bfr[2][2];
        #pragma unroll
        for (int s = 0; s < 2; s++) {
            const int n = (w + s * 8) * 8 + (lane >> 2);
            bfr[s][0] = __ldg((const unsigned*)&g_w1h[n * 80 + kb]);
            bfr[s][1] = __ldg((const unsigned*)&g_w1h[n * 80 + kb + 8]);
        }
        #pragma unroll
        for (int mt = 0; mt < 5; mt++) {
            unsigned afr[4];
            ldsm_x4(afr, sa + mt * (16 * 88 * 2) + ks * 32);
            mma_f16(acc[0][mt], afr, bfr[0]);
            mma_f16(acc[1][mt], afr, bfr[1]);
        }
    }
    #pragma unroll
    for (int s = 0; s < 2; s++) {
        const int n0c = (w + s * 8) * 8 + 2 * (lane & 3);
        const float bb0 = __ldg(b1 + n0c), bb1 = __ldg(b1 + n0c + 1);
        #pragma unroll
        for (int mt = 0; mt < 5; mt++) {
            const int r = mt * 16 + (lane >> 2);
            *(__half2*)&sH[r * 136 + n0c] =
                __floats2half2_rn(gelu_exact(acc[s][mt][0] + bb0),
                                  gelu_exact(acc[s][mt][1] + bb1));
            *(__half2*)&sH[(r + 8) * 136 + n0c] =
                __floats2half2_rn(gelu_exact(acc[s][mt][2] + bb0),
                                  gelu_exact(acc[s][mt][3] + bb1));
        }
    }
}

// Stage 3: S += H @ w2 + b2. A = sH [80][136] (K=128); B = g_w2h global.
template<int NS>
__device__ __forceinline__ void f16_stage3(
    __half* __restrict__ sS, const __half* __restrict__ sH,
    const float* __restrict__ b2, int w, int lane)
{
    float acc[NS][5][4] = {};
    const uint32_t ha = smem_u32(sH) + ((lane & 15) * 136 + (lane >> 4) * 8) * 2;
    #pragma unroll
    for (int ks = 0; ks < 8; ks++) {
        const int kb = ks * 16 + (lane & 3) * 2;
        unsigned bfr[NS][2];
        #pragma unroll
        for (int s = 0; s < NS; s++) {
            const int n = (w + s * 8) * 8 + (lane >> 2);
            bfr[s][0] = __ldg((const unsigned*)&g_w2h[n * 128 + kb]);
            bfr[s][1] = __ldg((const unsigned*)&g_w2h[n * 128 + kb + 8]);
        }
        #pragma unroll
        for (int mt = 0; mt < 5; mt++) {
            unsigned afr[4];
            ldsm_x4(afr, ha + mt * (16 * 136 * 2) + ks * 32);
            #pragma unroll
            for (int s = 0; s < NS; s++) mma_f16(acc[s][mt], afr, bfr[s]);
        }
    }
    #pragma unroll
    for (int s = 0; s < NS; s++) {
        const int n0c = (w + s * 8) * 8 + 2 * (lane & 3);
        const float bb0 = __ldg(b2 + n0c);
        const float bb1 = (n0c + 1 < 71) ? __ldg(b2 + n0c + 1) : 0.f;
        #pragma unroll
        for (int mt = 0; mt < 5; mt++) {
            const int r = mt * 16 + (lane >> 2);
            __half2 o0 = *(__half2*)&sS[r * 88 + n0c];
            __half2 o1 = *(__half2*)&sS[(r + 8) * 88 + n0c];
            *(__half2*)&sS[r * 88 + n0c] =
                __floats2half2_rn(__low2float(o0) + acc[s][mt][0] + bb0,
                                  __high2float(o0) + acc[s][mt][1] + bb1);
            *(__half2*)&sS[(r + 8) * 88 + n0c] =
                __floats2half2_rn(__low2float(o1) + acc[s][mt][2] + bb0,
                                  __high2float(o1) + acc[s][mt][3] + bb1);
        }
    }
}

// ---------------------------------------------------------------------------
// Attention core: ONE head per CTA, 256 threads, fp16 mma + LDSM. Grid 4096.
// smem halfs (17984 = 35968 B): sS [80][88] at 0; union U at 7040.
// ---------------------------------------------------------------------------
__global__ void __launch_bounds__(256, 4) attn_kernel(
    const float* __restrict__ b1, const float* __restrict__ b2)
{
    extern __shared__ __align__(16) __half smA[];
    __half* sS = smA;           // [80][88]
    __half* U  = smA + 7040;

    const int tid  = threadIdx.x;
    const int lane = tid & 31;
    const int w    = tid >> 5;      // 0..7
    const int bh   = blockIdx.x;
    const int bidx = bh >> 3, hidx = bh & 7;

    // ---- fills: Q [l][dh] -> sQ[80][72]; K -> sK[72][72]; zero pads ----
    {
        __half* sQ = U;
        __half* sK = U + 5760;
        const __half2* Qg = (const __half2*)(g_Qh + (size_t)bh * HEAD_ELEMS);
        const __half2* Kg = (const __half2*)(g_Kh + (size_t)bh * HEAD_ELEMS);
        for (int u = tid; u < 71 * 32; u += 256) {
            int l = u >> 5, d2 = (u & 31) << 1;
            *(__half2*)&sQ[l * 72 + d2] = Qg[u];
            *(__half2*)&sK[l * 72 + d2] = Kg[u];
        }
        for (int i = tid; i < 9 * 36; i += 256) {
            int r = 71 + i / 36, c2 = (i % 36) << 1;
            *(unsigned*)&sQ[r * 72 + c2] = 0u;
        }
        if (tid < 36) *(unsigned*)&sK[71 * 72 + tid * 2] = 0u;
        for (int i = tid; i < 80 * 4; i += 256) {
            int r = i >> 2, c = 72 + ((i & 3) << 1);
            *(unsigned*)&sS[r * 88 + c] = 0u;
        }
    }
    __syncthreads();

    if (w == 0) f16_stage1<2>(sS, U, U + 5760, w, lane);
    else        f16_stage1<1>(sS, U, U + 5760, w, lane);
    __syncthreads();

    f16_stage2(U, sS, b1, w, lane);
    __syncthreads();

    if (w == 0) f16_stage3<2>(sS, U, b2, w, lane);
    else        f16_stage3<1>(sS, U, b2, w, lane);
    __syncthreads();

    // ---- V^T fill into U + warp-per-row softmax over keys ----
    {
        __half* sVt = U;         // [64][88]
        const __half* Vg = g_Vth + (size_t)bh * HEAD_ELEMS;
        for (int i = tid; i < HEAD_ELEMS; i += 256) {
            int dh = i / 71, l = i - dh * 71;
            sVt[dh * 88 + l] = Vg[i];
        }
        for (int i = tid; i < 64 * 9; i += 256) {
            int dh = i / 9, c = 71 + (i - dh * 9);
            sVt[dh * 88 + c] = __half(0.f);
        }
    }
    __syncwarp();
    for (int q = w; q < 71; q += 8) {
        __half* row = sS + q * 88;
        float v0 = __half2float(row[lane]);
        float v1 = (lane + 32 < 71) ? __half2float(row[lane + 32]) : -1e30f;
        float v2 = (lane < 7)       ? __half2float(row[lane + 64]) : -1e30f;
        float m = fmaxf(v0, fmaxf(v1, v2));
        #pragma unroll
        for (int o = 16; o > 0; o >>= 1) m = fmaxf(m, __shfl_xor_sync(0xffffffffu, m, o));
        float e0 = __expf(v0 - m);
        float e1 = (lane + 32 < 71) ? __expf(v1 - m) : 0.f;
        float e2 = (lane < 7)       ? __expf(v2 - m) : 0.f;
        float s = e0 + e1 + e2;
        #pragma unroll
        for (int o = 16; o > 0; o >>= 1) s += __shfl_xor_sync(0xffffffffu, s, o);
        float inv = 1.f / s;
        row[lane] = __float2half_rn(e0 * inv);
        if (lane + 32 < 71) row[lane + 32] = __float2half_rn(e1 * inv);
        if (lane < 7)       row[lane + 64] = __float2half_rn(e2 * inv);
    }
    __syncthreads();

    // ---- PV: attn = P @ V -> g_attnH [m][512] fp16 ----
    {
        const __half* sVt = U;
        float acc[5][4] = {};
        const uint32_t pa = smem_u32(sS) + ((lane & 15) * 88 + (lane >> 4) * 8) * 2;
        const uint32_t va = smem_u32(sVt) + ((w * 8 + (lane & 7)) * 88 + (lane >> 3) * 8) * 2;
        #pragma unroll
        for (int ks = 0; ks < 5; ks++) {
            unsigned bfr[2];
            ldsm_x2(bfr, va + ks * 32);
            #pragma unroll
            for (int mt = 0; mt < 5; mt++) {
                unsigned afr[4];
                ldsm_x4(afr, pa + mt * (16 * 88 * 2) + ks * 32);
                mma_f16(acc[mt], afr, bfr);
            }
        }
        const int n0 = w * 8 + 2 * (lane & 3);
        const int dcol = hidx * 64 + n0;
        #pragma unroll
        for (int mt = 0; mt < 5; mt++) {
            int r = mt * 16 + (lane >> 2);
            if (r < 71) {
                *(__half2*)&g_attnH[((size_t)(bidx * 71 + r)) * 512 + dcol] =
                    __floats2half2_rn(acc[mt][0], acc[mt][1]);
            }
            if (r + 8 < 71) {
                *(__half2*)&g_attnH[((size_t)(bidx * 71 + r + 8)) * 512 + dcol] =
                    __floats2half2_rn(acc[mt][2], acc[mt][3]);
            }
        }
    }
}

// ---------------------------------------------------------------------------
extern "C" void kernel_launch(void* const* d_in, const int* in_sizes, int n_in,
                              void* d_out, int out_size)
{
    const float* query = (const float*)d_in[0];
    const float* key   = (const float*)d_in[1];
    const float* value = (const float*)d_in[2];
    const float* Wq = (const float*)d_in[3];
    const float* bq = (const float*)d_in[4];
    const float* Wk = (const float*)d_in[5];
    const float* bk = (const float*)d_in[6];
    const float* Wv = (const float*)d_in[7];
    const float* bv = (const float*)d_in[8];
    const float* Wo = (const float*)d_in[9];
    const float* bo = (const float*)d_in[10];
    const float* sf_w1 = (const float*)d_in[11];
    const float* sf_b1 = (const float*)d_in[12];
    const float* sf_w2 = (const float*)d_in[13];
    const float* sf_b2 = (const float*)d_in[14];
    float* out = (float*)d_out;

    const int gemm_smem = 40960;
    cudaFuncSetAttribute(qkv_gemm_kernel, cudaFuncAttributeMaxDynamicSharedMemorySize, gemm_smem);
    cudaFuncSetAttribute(out_gemm_kernel, cudaFuncAttributeMaxDynamicSharedMemorySize, gemm_smem);
    const int attn_smem = 17984 * 2;   // 35968 B
    cudaFuncSetAttribute(attn_kernel, cudaFuncAttributeMaxDynamicSharedMemorySize, attn_smem);

    // 1) weight preps
    dim3 gw(16, 16, 4);
    wt16_kernel<<<gw, 256>>>(Wq, Wk, Wv, Wo);
    wprep_kernel<<<40, 256>>>(sf_w1, sf_w2);

    // 2) QKV projections (fp16 tensor cores)
    dim3 g1(4, 284, 3);
    qkv_gemm_kernel<<<g1, 256, gemm_smem>>>(query, key, value, bq, bk, bv);

    // 3) attention core (fp16 mma + LDSM, 1 head per CTA)
    attn_kernel<<<NHEADS, 256, attn_smem>>>(sf_b1, sf_b2);

    // 4) output projection (fp16 tensor cores)
    dim3 g3(4, 284);
    out_gemm_kernel<<<g3, 256, gemm_smem>>>(out, bo);
}

// round 13
// speedup vs baseline: 3.1788x; 1.0057x over previous
#include <cuda_runtime.h>
#include <cuda_fp16.h>
#include <math.h>
#include <stdint.h>

// Problem constants
#define BB   512
#define LL   71
#define DD   512
#define HH   8
#define DHH  64
#define MROWS (BB * LL)          // 36352 = 284*128
#define NHEADS (BB * HH)         // 4096
#define HEAD_ELEMS (LL * DHH)    // 4544

// ---------------------------------------------------------------------------
// Scratch (static device globals)
// ---------------------------------------------------------------------------
__device__ __half g_WT16[4][DD * DD];        // fp16 transposed weights [n][k]: q,k,v,o
__device__ __half g_Qh[NHEADS * HEAD_ELEMS]; // [bh][l][dh] fp16, pre-scaled by 1/8
__device__ __half g_Kh[NHEADS * HEAD_ELEMS]; // [bh][l][dh] fp16
__device__ __half g_Vth[NHEADS * HEAD_ELEMS];// [bh][dh][l] fp16 (transposed)
__device__ __half g_attnH[MROWS * DD];       // attn output [m][512] fp16 row-major
__device__ __half g_w1h[128 * 80];           // w1^T [ff][key] fp16, key 71..79 = 0
__device__ __half g_w2h[72 * 128];           // w2^T [key_out][ff] fp16, row 71 = 0

__device__ __forceinline__ void mma_f16(float* c, const unsigned* a, const unsigned* b) {
    asm volatile(
        "mma.sync.aligned.m16n8k16.row.col.f32.f16.f16.f32 "
        "{%0,%1,%2,%3}, {%4,%5,%6,%7}, {%8,%9}, {%0,%1,%2,%3};"
        : "+f"(c[0]), "+f"(c[1]), "+f"(c[2]), "+f"(c[3])
        : "r"(a[0]), "r"(a[1]), "r"(a[2]), "r"(a[3]), "r"(b[0]), "r"(b[1]));
}

__device__ __forceinline__ void ldsm_x4(unsigned* r, uint32_t addr) {
    asm volatile("ldmatrix.sync.aligned.m8n8.x4.shared.b16 {%0,%1,%2,%3}, [%4];"
        : "=r"(r[0]), "=r"(r[1]), "=r"(r[2]), "=r"(r[3]) : "r"(addr));
}

__device__ __forceinline__ void ldsm_x2(unsigned* r, uint32_t addr) {
    asm volatile("ldmatrix.sync.aligned.m8n8.x2.shared.b16 {%0,%1}, [%2];"
        : "=r"(r[0]), "=r"(r[1]) : "r"(addr));
}

__device__ __forceinline__ uint32_t smem_u32(const void* p) {
    uint32_t a;
    asm("{ .reg .u64 t; cvta.to.shared.u64 t, %1; cvt.u32.u64 %0, t; }"
        : "=r"(a) : "l"(p));
    return a;
}

__device__ __forceinline__ float gelu_exact(float x) {
    return 0.5f * x * (1.f + erff(x * 0.70710678118654752f));
}

// ---------------------------------------------------------------------------
// Weight transpose + fp16 cvt: W[k][n] fp32 -> g_WT16[z][n][k] fp16.
// ---------------------------------------------------------------------------
__global__ void __launch_bounds__(256) wt16_kernel(
    const float* __restrict__ w0, const float* __restrict__ w1,
    const float* __restrict__ w2, const float* __restrict__ w3)
{
    __shared__ float t[32][33];
    const float* in = (blockIdx.z == 0) ? w0 : (blockIdx.z == 1) ? w1
                    : (blockIdx.z == 2) ? w2 : w3;
    __half* out = g_WT16[blockIdx.z];
    const int k0 = blockIdx.x * 32, n0 = blockIdx.y * 32;
    const int tx = threadIdx.x & 31, ty = threadIdx.x >> 5;
    #pragma unroll
    for (int j = 0; j < 4; j++)
        t[ty + 8 * j][tx] = in[(size_t)(k0 + ty + 8 * j) * 512 + n0 + tx];
    __syncthreads();
    #pragma unroll
    for (int j = 0; j < 4; j++)
        out[(size_t)(n0 + ty + 8 * j) * 512 + k0 + tx] = __float2half_rn(t[tx][ty + 8 * j]);
}

// ---------------------------------------------------------------------------
// MLP weight transpose + pad + fp16 cvt.
// ---------------------------------------------------------------------------
__global__ void __launch_bounds__(256) wprep_kernel(
    const float* __restrict__ w1, const float* __restrict__ w2)
{
    int i = blockIdx.x * 256 + threadIdx.x;
    if (i < 128 * 80) {
        int n = i / 80, k = i - n * 80;
        g_w1h[i] = (k < 71) ? __float2half_rn(w1[k * 128 + n]) : __half(0.f);
    }
    if (i < 72 * 128) {
        int n = i >> 7, k = i & 127;
        g_w2h[i] = (n < 71) ? __float2half_rn(w2[k * 71 + n]) : __half(0.f);
    }
}

// ---------------------------------------------------------------------------
// fp16 GEMM core: CTA 128x128, K=512, KC=32, double-buffered smem, LDSM.
// A row-major [M][512] (fp32 or fp16); BT fp16 [n][k].
// ---------------------------------------------------------------------------
template<typename TA>
__device__ __forceinline__ void gemm_f16_ctile(
    const TA* __restrict__ A, const __half* __restrict__ BT,
    float (&c)[4][4][4])
{
    extern __shared__ __align__(16) __half smh[];
    __half* As = smh;            // [2][5120]
    __half* Bs = smh + 10240;    // [2][5120]

    const int tid  = threadIdx.x;
    const int lane = tid & 31;
    const int warp = tid >> 5;
    const int mBase = blockIdx.y * 128;
    const int nBase = blockIdx.x * 128;
    const uint32_t smem_addr = smem_u32(smh);

    #pragma unroll
    for (int im = 0; im < 4; im++)
        #pragma unroll
        for (int in = 0; in < 4; in++)
            #pragma unroll
            for (int q = 0; q < 4; q++) c[im][in][q] = 0.f;

    float4 raf[4];
    uint4  rah[2];
    uint4  rbh[2];

    auto ldgA = [&](int kt) {
        if constexpr (sizeof(TA) == 4) {
            #pragma unroll
            for (int it = 0; it < 4; it++) {
                int idx = it * 256 + tid;
                int row = idx >> 3, c4 = idx & 7;
                raf[it] = *(const float4*)((const float*)A +
                    (size_t)(mBase + row) * 512 + kt * 32 + c4 * 4);
            }
        } else {
            #pragma unroll
            for (int it = 0; it < 2; it++) {
                int idx = it * 256 + tid;
                int row = idx >> 2, g = idx & 3;
                rah[it] = *(const uint4*)((const __half*)A +
                    (size_t)(mBase + row) * 512 + kt * 32 + g * 8);
            }
        }
    };
    auto ldgB = [&](int kt) {
        #pragma unroll
        for (int it = 0; it < 2; it++) {
            int idx = it * 256 + tid;
            int row = idx >> 2, g = idx & 3;
            rbh[it] = *(const uint4*)(BT + (size_t)(nBase + row) * 512 + kt * 32 + g * 8);
        }
    };
    auto stsA = [&](int buf) {
        if constexpr (sizeof(TA) == 4) {
            #pragma unroll
            for (int it = 0; it < 4; it++) {
                int idx = it * 256 + tid;
                int row = idx >> 3, c4 = idx & 7;
                __half2 h0 = __floats2half2_rn(raf[it].x, raf[it].y);
                __half2 h1 = __floats2half2_rn(raf[it].z, raf[it].w);
                *(__half2*)&As[buf * 5120 + row * 40 + c4 * 4]     = h0;
                *(__half2*)&As[buf * 5120 + row * 40 + c4 * 4 + 2] = h1;
            }
        } else {
            #pragma unroll
            for (int it = 0; it < 2; it++) {
                int idx = it * 256 + tid;
                int row = idx >> 2, g = idx & 3;
                *(uint4*)&As[buf * 5120 + row * 40 + g * 8] = rah[it];
            }
        }
    };
    auto stsB = [&](int buf) {
        #pragma unroll
        for (int it = 0; it < 2; it++) {
            int idx = it * 256 + tid;
            int row = idx >> 2, g = idx & 3;
            *(uint4*)&Bs[buf * 5120 + row * 40 + g * 8] = rbh[it];
        }
    };
    auto compute = [&](int buf) {
        const uint32_t abase = smem_addr + buf * 10240 +
            (((warp & 1) * 64 + (lane & 15)) * 40 + (lane >> 4) * 8) * 2;
        const uint32_t bbase = smem_addr + 20480 + buf * 10240 +
            (((warp >> 1) * 32 + (lane & 7)) * 40 + (lane >> 3) * 8) * 2;
        #pragma unroll
        for (int ks = 0; ks < 2; ks++) {
            unsigned a[4][4], b[4][2];
            #pragma unroll
            for (int mt = 0; mt < 4; mt++) ldsm_x4(a[mt], abase + mt * 1280 + ks * 32);
            #pragma unroll
            for (int nt = 0; nt < 4; nt++) ldsm_x2(b[nt], bbase + nt * 640 + ks * 32);
            #pragma unroll
            for (int im = 0; im < 4; im++)
                #pragma unroll
                for (int in = 0; in < 4; in++)
                    mma_f16(c[im][in], a[im], b[in]);
        }
    };

    ldgA(0); ldgB(0);
    stsA(0); stsB(0);
    __syncthreads();
    #pragma unroll 1
    for (int kt = 0; kt < 16; kt++) {
        const int cur = kt & 1;
        if (kt < 15) { ldgA(kt + 1); ldgB(kt + 1); }
        compute(cur);
        if (kt < 15) { stsA(cur ^ 1); stsB(cur ^ 1); }
        __syncthreads();
    }
}

// ---------------------------------------------------------------------------
// QKV projection (fp16 mma): grid (4, 284, 3).
// Q/K -> fp16 natural [bh][l][dh]; V -> fp16 transposed [bh][dh][l].
// ---------------------------------------------------------------------------
__global__ void __launch_bounds__(256) qkv_gemm_kernel(
    const float* __restrict__ q_in, const float* __restrict__ k_in,
    const float* __restrict__ v_in,
    const float* __restrict__ bq, const float* __restrict__ bk,
    const float* __restrict__ bv)
{
    const float* A; const float* bias; __half* out; float scale;
    if (blockIdx.z == 0)      { A = q_in; bias = bq; out = g_Qh;  scale = 0.125f; }
    else if (blockIdx.z == 1) { A = k_in; bias = bk; out = g_Kh;  scale = 1.0f; }
    else                      { A = v_in; bias = bv; out = g_Vth; scale = 1.0f; }

    float c[4][4][4];
    gemm_f16_ctile<float>(A, g_WT16[blockIdx.z], c);

    const int lane = threadIdx.x & 31, warp = threadIdx.x >> 5;
    const int mBase = blockIdx.y * 128, nBase = blockIdx.x * 128;

    float bv2[4][2];
    #pragma unroll
    for (int in = 0; in < 4; in++) {
        int cg = nBase + (warp >> 1) * 32 + in * 8 + 2 * (lane & 3);
        bv2[in][0] = bias[cg]; bv2[in][1] = bias[cg + 1];
    }

    if (blockIdx.z <= 1) {
        #pragma unroll
        for (int im = 0; im < 4; im++) {
            int rg0 = mBase + (warp & 1) * 64 + im * 16 + (lane >> 2);
            int rg1 = rg0 + 8;
            int b0 = rg0 / 71, l0 = rg0 - b0 * 71;
            int b1 = rg1 / 71, l1 = rg1 - b1 * 71;
            #pragma unroll
            for (int in = 0; in < 4; in++) {
                int cg = nBase + (warp >> 1) * 32 + in * 8 + 2 * (lane & 3);
                int h = cg >> 6, dh = cg & 63;
                *(__half2*)&out[(((size_t)(b0 * 8 + h) * 71 + l0) << 6) + dh] =
                    __floats2half2_rn((c[im][in][0] + bv2[in][0]) * scale,
                                      (c[im][in][1] + bv2[in][1]) * scale);
                *(__half2*)&out[(((size_t)(b1 * 8 + h) * 71 + l1) << 6) + dh] =
                    __floats2half2_rn((c[im][in][2] + bv2[in][0]) * scale,
                                      (c[im][in][3] + bv2[in][1]) * scale);
            }
        }
    } else {
        #pragma unroll
        for (int im = 0; im < 4; im++) {
            int rg0 = mBase + (warp & 1) * 64 + im * 16 + (lane >> 2);
            int rg1 = rg0 + 8;
            int b0 = rg0 / 71, l0 = rg0 - b0 * 71;
            int b1 = rg1 / 71, l1 = rg1 - b1 * 71;
            #pragma unroll
            for (int in = 0; in < 4; in++) {
                int cg = nBase + (warp >> 1) * 32 + in * 8 + 2 * (lane & 3);
                int h = cg >> 6, dh = cg & 63;
                size_t base0 = ((size_t)((b0 * 8 + h) * 64 + dh)) * 71 + l0;
                size_t base1 = ((size_t)((b1 * 8 + h) * 64 + dh)) * 71 + l1;
                out[base0]      = __float2half_rn(c[im][in][0] + bv2[in][0]);
                out[base0 + 71] = __float2half_rn(c[im][in][1] + bv2[in][1]);
                out[base1]      = __float2half_rn(c[im][in][2] + bv2[in][0]);
                out[base1 + 71] = __float2half_rn(c[im][in][3] + bv2[in][1]);
            }
        }
    }
}

// ---------------------------------------------------------------------------
// Output projection (fp16 mma, A = g_attnH): grid (4, 284).
// ---------------------------------------------------------------------------
__global__ void __launch_bounds__(256) out_gemm_kernel(
    float* __restrict__ out, const float* __restrict__ bo)
{
    float c[4][4][4];
    gemm_f16_ctile<__half>(g_attnH, g_WT16[3], c);

    const int lane = threadIdx.x & 31, warp = threadIdx.x >> 5;
    const int mBase = blockIdx.y * 128, nBase = blockIdx.x * 128;

    float bv2[4][2];
    #pragma unroll
    for (int in = 0; in < 4; in++) {
        int cg = nBase + (warp >> 1) * 32 + in * 8 + 2 * (lane & 3);
        bv2[in][0] = bo[cg]; bv2[in][1] = bo[cg + 1];
    }
    #pragma unroll
    for (int im = 0; im < 4; im++) {
        int rg0 = mBase + (warp & 1) * 64 + im * 16 + (lane >> 2);
        int rg1 = rg0 + 8;
        #pragma unroll
        for (int in = 0; in < 4; in++) {
            int cg = nBase + (warp >> 1) * 32 + in * 8 + 2 * (lane & 3);
            float2 v0 = make_float2(c[im][in][0] + bv2[in][0], c[im][in][1] + bv2[in][1]);
            float2 v1 = make_float2(c[im][in][2] + bv2[in][0], c[im][in][3] + bv2[in][1]);
            *(float2*)&out[(size_t)rg0 * 512 + cg] = v0;
            *(float2*)&out[(size_t)rg1 * 512 + cg] = v1;
        }
    }
}

// ---------------------------------------------------------------------------
// fp16 attention stages with LDSM + balanced remainder tile.
// N=72 = 9 n-tiles: each warp owns base tile w; warps 0..4 also own one
// m-tile (mt = w) of the remainder tile (n = 64..71).
// S: [80 q][88] fp16 row-major (cols 72..79 zero).
// ---------------------------------------------------------------------------

// Stage 1: S = Q @ K^T. A = sQ [80][72] (K=64); B = sK [72][72].
__device__ __forceinline__ void f16_stage1(
    __half* __restrict__ sS, const __half* __restrict__ sQ,
    const __half* __restrict__ sK, int w, int lane)
{
    float acc[5][4] = {};
    float accR[4] = {};
    const bool rem = (w < 5);
    const uint32_t qa = smem_u32(sQ) + ((lane & 15) * 72 + (lane >> 4) * 8) * 2;
    const uint32_t ka = smem_u32(sK) + ((w * 8 + (lane & 7)) * 72 + (lane >> 3) * 8) * 2;
    const uint32_t kaR = smem_u32(sK) + ((64 + (lane & 7)) * 72 + (lane >> 3) * 8) * 2;
    #pragma unroll
    for (int ks = 0; ks < 4; ks++) {
        unsigned bfr[2];
        ldsm_x2(bfr, ka + ks * 32);
        #pragma unroll
        for (int mt = 0; mt < 5; mt++) {
            unsigned afr[4];
            ldsm_x4(afr, qa + mt * (16 * 72 * 2) + ks * 32);
            mma_f16(acc[mt], afr, bfr);
        }
        if (rem) {
            unsigned bR[2], aR[4];
            ldsm_x2(bR, kaR + ks * 32);
            ldsm_x4(aR, qa + w * (16 * 72 * 2) + ks * 32);
            mma_f16(accR, aR, bR);
        }
    }
    {
        const int n0c = w * 8 + 2 * (lane & 3);
        #pragma unroll
        for (int mt = 0; mt < 5; mt++) {
            const int r = mt * 16 + (lane >> 2);
            *(__half2*)&sS[r * 88 + n0c] =
                __floats2half2_rn(acc[mt][0], acc[mt][1]);
            *(__half2*)&sS[(r + 8) * 88 + n0c] =
                __floats2half2_rn(acc[mt][2], acc[mt][3]);
        }
    }
    if (rem) {
        const int n0c = 64 + 2 * (lane & 3);
        const int r = w * 16 + (lane >> 2);
        *(__half2*)&sS[r * 88 + n0c] = __floats2half2_rn(accR[0], accR[1]);
        *(__half2*)&sS[(r + 8) * 88 + n0c] = __floats2half2_rn(accR[2], accR[3]);
    }
}

// Stage 2: H = gelu(S @ w1 + b1). A = sS [80][88] (K=80); B = g_w1h global.
// N=128 = 16 tiles / 8 warps — balanced, unchanged.
__device__ __forceinline__ void f16_stage2(
    __half* __restrict__ sH, const __half* __restrict__ sS,
    const float* __restrict__ b1, int w, int lane)
{
    float acc[2][5][4] = {};
    const uint32_t sa = smem_u32(sS) + ((lane & 15) * 88 + (lane >> 4) * 8) * 2;
    #pragma unroll
    for (int ks = 0; ks < 5; ks++) {
        const int kb = ks * 16 + (lane & 3) * 2;
        unsigned bfr[2][2];
        #pragma unroll
        for (int s = 0; s < 2; s++) {
            const int n = (w + s * 8) * 8 + (lane >> 2);
            bfr[s][0] = __ldg((const unsigned*)&g_w1h[n * 80 + kb]);
            bfr[s][1] = __ldg((const unsigned*)&g_w1h[n * 80 + kb + 8]);
        }
        #pragma unroll
        for (int mt = 0; mt < 5; mt++) {
            unsigned afr[4];
            ldsm_x4(afr, sa + mt * (16 * 88 * 2) + ks * 32);
            mma_f16(acc[0][mt], afr, bfr[0]);
            mma_f16(acc[1][mt], afr, bfr[1]);
        }
    }
    #pragma unroll
    for (int s = 0; s < 2; s++) {
        const int n0c = (w + s * 8) * 8 + 2 * (lane & 3);
        const float bb0 = __ldg(b1 + n0c), bb1 = __ldg(b1 + n0c + 1);
        #pragma unroll
        for (int mt = 0; mt < 5; mt++) {
            const int r = mt * 16 + (lane >> 2);
            *(__half2*)&sH[r * 136 + n0c] =
                __floats2half2_rn(gelu_exact(acc[s][mt][0] + bb0),
                                  gelu_exact(acc[s][mt][1] + bb1));
            *(__half2*)&sH[(r + 8) * 136 + n0c] =
                __floats2half2_rn(gelu_exact(acc[s][mt][2] + bb0),
                                  gelu_exact(acc[s][mt][3] + bb1));
        }
    }
}

// Stage 3: S += H @ w2 + b2. A = sH [80][136] (K=128); B = g_w2h global.
__device__ __forceinline__ void f16_stage3(
    __half* __restrict__ sS, const __half* __restrict__ sH,
    const float* __restrict__ b2, int w, int lane)
{
    float acc[5][4] = {};
    float accR[4] = {};
    const bool rem = (w < 5);
    const uint32_t ha = smem_u32(sH) + ((lane & 15) * 136 + (lane >> 4) * 8) * 2;
    const int nB  = w * 8 + (lane >> 2);
    const int nBR = 64 + (lane >> 2);
    #pragma unroll
    for (int ks = 0; ks < 8; ks++) {
        const int kb = ks * 16 + (lane & 3) * 2;
        unsigned bfr[2];
        bfr[0] = __ldg((const unsigned*)&g_w2h[nB * 128 + kb]);
        bfr[1] = __ldg((const unsigned*)&g_w2h[nB * 128 + kb + 8]);
        #pragma unroll
        for (int mt = 0; mt < 5; mt++) {
            unsigned afr[4];
            ldsm_x4(afr, ha + mt * (16 * 136 * 2) + ks * 32);
            mma_f16(acc[mt], afr, bfr);
        }
        if (rem) {
            unsigned bR[2], aR[4];
            bR[0] = __ldg((const unsigned*)&g_w2h[nBR * 128 + kb]);
            bR[1] = __ldg((const unsigned*)&g_w2h[nBR * 128 + kb + 8]);
            ldsm_x4(aR, ha + w * (16 * 136 * 2) + ks * 32);
            mma_f16(accR, aR, bR);
        }
    }
    {
        const int n0c = w * 8 + 2 * (lane & 3);
        const float bb0 = __ldg(b2 + n0c);
        const float bb1 = (n0c + 1 < 71) ? __ldg(b2 + n0c + 1) : 0.f;
        #pragma unroll
        for (int mt = 0; mt < 5; mt++) {
            const int r = mt * 16 + (lane >> 2);
            __half2 o0 = *(__half2*)&sS[r * 88 + n0c];
            __half2 o1 = *(__half2*)&sS[(r + 8) * 88 + n0c];
            *(__half2*)&sS[r * 88 + n0c] =
                __floats2half2_rn(__low2float(o0) + acc[mt][0] + bb0,
                                  __high2float(o0) + acc[mt][1] + bb1);
            *(__half2*)&sS[(r + 8) * 88 + n0c] =
                __floats2half2_rn(__low2float(o1) + acc[mt][2] + bb0,
                                  __high2float(o1) + acc[mt][3] + bb1);
        }
    }
    if (rem) {
        const int n0c = 64 + 2 * (lane & 3);
        const float bb0 = __ldg(b2 + n0c);
        const float bb1 = (n0c + 1 < 71) ? __ldg(b2 + n0c + 1) : 0.f;
        const int r = w * 16 + (lane >> 2);
        __half2 o0 = *(__half2*)&sS[r * 88 + n0c];
        __half2 o1 = *(__half2*)&sS[(r + 8) * 88 + n0c];
        *(__half2*)&sS[r * 88 + n0c] =
            __floats2half2_rn(__low2float(o0) + accR[0] + bb0,
                              __high2float(o0) + accR[1] + bb1);
        *(__half2*)&sS[(r + 8) * 88 + n0c] =
            __floats2half2_rn(__low2float(o1) + accR[2] + bb0,
                              __high2float(o1) + accR[3] + bb1);
    }
}

// ---------------------------------------------------------------------------
// Attention core: ONE head per CTA, 256 threads, fp16 mma + LDSM. Grid 4096.
// smem halfs (17984 = 35968 B): sS [80][88] at 0; union U at 7040.
// ---------------------------------------------------------------------------
__global__ void __launch_bounds__(256, 4) attn_kernel(
    const float* __restrict__ b1, const float* __restrict__ b2)
{
    extern __shared__ __align__(16) __half smA[];
    __half* sS = smA;           // [80][88]
    __half* U  = smA + 7040;

    const int tid  = threadIdx.x;
    const int lane = tid & 31;
    const int w    = tid >> 5;      // 0..7
    const int bh   = blockIdx.x;
    const int bidx = bh >> 3, hidx = bh & 7;

    // ---- fills: Q [l][dh] -> sQ[80][72]; K -> sK[72][72]; zero pads ----
    {
        __half* sQ = U;
        __half* sK = U + 5760;
        const __half2* Qg = (const __half2*)(g_Qh + (size_t)bh * HEAD_ELEMS);
        const __half2* Kg = (const __half2*)(g_Kh + (size_t)bh * HEAD_ELEMS);
        for (int u = tid; u < 71 * 32; u += 256) {
            int l = u >> 5, d2 = (u & 31) << 1;
            *(__half2*)&sQ[l * 72 + d2] = Qg[u];
            *(__half2*)&sK[l * 72 + d2] = Kg[u];
        }
        for (int i = tid; i < 9 * 36; i += 256) {
            int r = 71 + i / 36, c2 = (i % 36) << 1;
            *(unsigned*)&sQ[r * 72 + c2] = 0u;
        }
        if (tid < 36) *(unsigned*)&sK[71 * 72 + tid * 2] = 0u;
        for (int i = tid; i < 80 * 4; i += 256) {
            int r = i >> 2, c = 72 + ((i & 3) << 1);
            *(unsigned*)&sS[r * 88 + c] = 0u;
        }
    }
    __syncthreads();

    f16_stage1(sS, U, U + 5760, w, lane);
    __syncthreads();

    f16_stage2(U, sS, b1, w, lane);
    __syncthreads();

    f16_stage3(sS, U, b2, w, lane);
    __syncthreads();

    // ---- V^T fill into U + warp-per-row softmax over keys ----
    {
        __half* sVt = U;         // [64][88]
        const __half* Vg = g_Vth + (size_t)bh * HEAD_ELEMS;
        for (int i = tid; i < HEAD_ELEMS; i += 256) {
            int dh = i / 71, l = i - dh * 71;
            sVt[dh * 88 + l] = Vg[i];
        }
        for (int i = tid; i < 64 * 9; i += 256) {
            int dh = i / 9, c = 71 + (i - dh * 9);
            sVt[dh * 88 + c] = __half(0.f);
        }
    }
    __syncwarp();
    for (int q = w; q < 71; q += 8) {
        __half* row = sS + q * 88;
        float v0 = __half2float(row[lane]);
        float v1 = (lane + 32 < 71) ? __half2float(row[lane + 32]) : -1e30f;
        float v2 = (lane < 7)       ? __half2float(row[lane + 64]) : -1e30f;
        float m = fmaxf(v0, fmaxf(v1, v2));
        #pragma unroll
        for (int o = 16; o > 0; o >>= 1) m = fmaxf(m, __shfl_xor_sync(0xffffffffu, m, o));
        float e0 = __expf(v0 - m);
        float e1 = (lane + 32 < 71) ? __expf(v1 - m) : 0.f;
        float e2 = (lane < 7)       ? __expf(v2 - m) : 0.f;
        float s = e0 + e1 + e2;
        #pragma unroll
        for (int o = 16; o > 0; o >>= 1) s += __shfl_xor_sync(0xffffffffu, s, o);
        float inv = 1.f / s;
        row[lane] = __float2half_rn(e0 * inv);
        if (lane + 32 < 71) row[lane + 32] = __float2half_rn(e1 * inv);
        if (lane < 7)       row[lane + 64] = __float2half_rn(e2 * inv);
    }
    __syncthreads();

    // ---- PV: attn = P @ V -> g_attnH [m][512] fp16 ----
    {
        const __half* sVt = U;
        float acc[5][4] = {};
        const uint32_t pa = smem_u32(sS) + ((lane & 15) * 88 + (lane >> 4) * 8) * 2;
        const uint32_t va = smem_u32(sVt) + ((w * 8 + (lane & 7)) * 88 + (lane >> 3) * 8) * 2;
        #pragma unroll
        for (int ks = 0; ks < 5; ks++) {
            unsigned bfr[2];
            ldsm_x2(bfr, va + ks * 32);
            #pragma unroll
            for (int mt = 0; mt < 5; mt++) {
                unsigned afr[4];
                ldsm_x4(afr, pa + mt * (16 * 88 * 2) + ks * 32);
                mma_f16(acc[mt], afr, bfr);
            }
        }
        const int n0 = w * 8 + 2 * (lane & 3);
        const int dcol = hidx * 64 + n0;
        #pragma unroll
        for (int mt = 0; mt < 5; mt++) {
            int r = mt * 16 + (lane >> 2);
            if (r < 71) {
                *(__half2*)&g_attnH[((size_t)(bidx * 71 + r)) * 512 + dcol] =
                    __floats2half2_rn(acc[mt][0], acc[mt][1]);
            }
            if (r + 8 < 71) {
                *(__half2*)&g_attnH[((size_t)(bidx * 71 + r + 8)) * 512 + dcol] =
                    __floats2half2_rn(acc[mt][2], acc[mt][3]);
            }
        }
    }
}

// ---------------------------------------------------------------------------
extern "C" void kernel_launch(void* const* d_in, const int* in_sizes, int n_in,
                              void* d_out, int out_size)
{
    const float* query = (const float*)d_in[0];
    const float* key   = (const float*)d_in[1];
    const float* value = (const float*)d_in[2];
    const float* Wq = (const float*)d_in[3];
    const float* bq = (const float*)d_in[4];
    const float* Wk = (const float*)d_in[5];
    const float* bk = (const float*)d_in[6];
    const float* Wv = (const float*)d_in[7];
    const float* bv = (const float*)d_in[8];
    const float* Wo = (const float*)d_in[9];
    const float* bo = (const float*)d_in[10];
    const float* sf_w1 = (const float*)d_in[11];
    const float* sf_b1 = (const float*)d_in[12];
    const float* sf_w2 = (const float*)d_in[13];
    const float* sf_b2 = (const float*)d_in[14];
    float* out = (float*)d_out;

    const int gemm_smem = 40960;
    cudaFuncSetAttribute(qkv_gemm_kernel, cudaFuncAttributeMaxDynamicSharedMemorySize, gemm_smem);
    cudaFuncSetAttribute(out_gemm_kernel, cudaFuncAttributeMaxDynamicSharedMemorySize, gemm_smem);
    const int attn_smem = 17984 * 2;   // 35968 B
    cudaFuncSetAttribute(attn_kernel, cudaFuncAttributeMaxDynamicSharedMemorySize, attn_smem);

    // 1) weight preps
    dim3 gw(16, 16, 4);
    wt16_kernel<<<gw, 256>>>(Wq, Wk, Wv, Wo);
    wprep_kernel<<<40, 256>>>(sf_w1, sf_w2);

    // 2) QKV projections (fp16 tensor cores)
    dim3 g1(4, 284, 3);
    qkv_gemm_kernel<<<g1, 256, gemm_smem>>>(query, key, value, bq, bk, bv);

    // 3) attention core (fp16 mma + LDSM, balanced n-tiles)
    attn_kernel<<<NHEADS, 256, attn_smem>>>(sf_b1, sf_b2);

    // 4) output projection (fp16 tensor cores)
    dim3 g3(4, 284);
    out_gemm_kernel<<<g3, 256, gemm_smem>>>(out, bo);
}

// round 16
// speedup vs baseline: 3.2840x; 1.0331x over previous
#include <cuda_runtime.h>
#include <cuda_fp16.h>
#include <math.h>
#include <stdint.h>

// Problem constants
#define BB   512
#define LL   71
#define DD   512
#define HH   8
#define DHH  64
#define MROWS (BB * LL)          // 36352 = 284*128
#define NHEADS (BB * HH)         // 4096
#define HEAD_ELEMS (LL * DHH)    // 4544

// ---------------------------------------------------------------------------
// Scratch (static device globals)
// ---------------------------------------------------------------------------
__device__ __half g_WT16[4][DD * DD];        // fp16 transposed weights [n][k]: q,k,v,o
__device__ __half g_Qh[NHEADS * HEAD_ELEMS]; // [bh][l][dh] fp16, pre-scaled by 1/8
__device__ __half g_Kh[NHEADS * HEAD_ELEMS]; // [bh][l][dh] fp16
__device__ __half g_Vth[NHEADS * HEAD_ELEMS];// [bh][dh][l] fp16 (transposed)
__device__ __half g_attnH[MROWS * DD];       // attn output [m][512] fp16 row-major
// MLP weights pre-packed in mma B-fragment order: uint2 per (n-tile, kstep, lane)
__device__ uint2 g_w1f[16 * 5 * 32];         // w1: 16 n-tiles, 5 k-steps
__device__ uint2 g_w2f[9 * 8 * 32];          // w2: 9 n-tiles, 8 k-steps

__device__ __forceinline__ void mma_f16(float* c, const unsigned* a, const unsigned* b) {
    asm volatile(
        "mma.sync.aligned.m16n8k16.row.col.f32.f16.f16.f32 "
        "{%0,%1,%2,%3}, {%4,%5,%6,%7}, {%8,%9}, {%0,%1,%2,%3};"
        : "+f"(c[0]), "+f"(c[1]), "+f"(c[2]), "+f"(c[3])
        : "r"(a[0]), "r"(a[1]), "r"(a[2]), "r"(a[3]), "r"(b[0]), "r"(b[1]));
}

__device__ __forceinline__ void ldsm_x4(unsigned* r, uint32_t addr) {
    asm volatile("ldmatrix.sync.aligned.m8n8.x4.shared.b16 {%0,%1,%2,%3}, [%4];"
        : "=r"(r[0]), "=r"(r[1]), "=r"(r[2]), "=r"(r[3]) : "r"(addr));
}

__device__ __forceinline__ void ldsm_x2(unsigned* r, uint32_t addr) {
    asm volatile("ldmatrix.sync.aligned.m8n8.x2.shared.b16 {%0,%1}, [%2];"
        : "=r"(r[0]), "=r"(r[1]) : "r"(addr));
}

__device__ __forceinline__ uint32_t smem_u32(const void* p) {
    uint32_t a;
    asm("{ .reg .u64 t; cvta.to.shared.u64 t, %1; cvt.u32.u64 %0, t; }"
        : "=r"(a) : "l"(p));
    return a;
}

__device__ __forceinline__ unsigned pack_h2(float a, float b) {
    __half2 h = __floats2half2_rn(a, b);
    return *reinterpret_cast<unsigned*>(&h);
}

__device__ __forceinline__ float gelu_exact(float x) {
    return 0.5f * x * (1.f + erff(x * 0.70710678118654752f));
}

// ---------------------------------------------------------------------------
// Weight transpose + fp16 cvt: W[k][n] fp32 -> g_WT16[z][n][k] fp16.
// ---------------------------------------------------------------------------
__global__ void __launch_bounds__(256) wt16_kernel(
    const float* __restrict__ w0, const float* __restrict__ w1,
    const float* __restrict__ w2, const float* __restrict__ w3)
{
    __shared__ float t[32][33];
    const float* in = (blockIdx.z == 0) ? w0 : (blockIdx.z == 1) ? w1
                    : (blockIdx.z == 2) ? w2 : w3;
    __half* out = g_WT16[blockIdx.z];
    const int k0 = blockIdx.x * 32, n0 = blockIdx.y * 32;
    const int tx = threadIdx.x & 31, ty = threadIdx.x >> 5;
    #pragma unroll
    for (int j = 0; j < 4; j++)
        t[ty + 8 * j][tx] = in[(size_t)(k0 + ty + 8 * j) * 512 + n0 + tx];
    __syncthreads();
    #pragma unroll
    for (int j = 0; j < 4; j++)
        out[(size_t)(n0 + ty + 8 * j) * 512 + k0 + tx] = __float2half_rn(t[tx][ty + 8 * j]);
}

// ---------------------------------------------------------------------------
// MLP weight fragment packer.
// w1f[t][ks][lane] = B-fragment uint2 for n = t*8+(lane>>2), kb = ks*16+(lane&3)*2
//   .x = half2(w1[kb][n], w1[kb+1][n])  (k >= 71 -> 0)
//   .y = half2(w1[kb+8][n], w1[kb+9][n])
// w2f analogous from w2 [128][71]; n >= 71 -> 0.
// ---------------------------------------------------------------------------
__global__ void __launch_bounds__(256) wfrag_kernel(
    const float* __restrict__ w1, const float* __restrict__ w2)
{
    int e = blockIdx.x * 256 + threadIdx.x;
    if (e < 16 * 5 * 32) {
        int t = e / 160, r = e - t * 160;
        int ks = r >> 5, lane = r & 31;
        int n = t * 8 + (lane >> 2);
        int kb = ks * 16 + (lane & 3) * 2;
        float a0 = (kb     < 71) ? w1[(kb)     * 128 + n] : 0.f;
        float a1 = (kb + 1 < 71) ? w1[(kb + 1) * 128 + n] : 0.f;
        float a2 = (kb + 8 < 71) ? w1[(kb + 8) * 128 + n] : 0.f;
        float a3 = (kb + 9 < 71) ? w1[(kb + 9) * 128 + n] : 0.f;
        uint2 u;
        u.x = pack_h2(a0, a1);
        u.y = pack_h2(a2, a3);
        g_w1f[e] = u;
    }
    if (e < 9 * 8 * 32) {
        int t = e >> 8, r = e & 255;
        int ks = r >> 5, lane = r & 31;
        int n = t * 8 + (lane >> 2);
        int kb = ks * 16 + (lane & 3) * 2;
        float a0 = (n < 71) ? w2[(kb)     * 71 + n] : 0.f;
        float a1 = (n < 71) ? w2[(kb + 1) * 71 + n] : 0.f;
        float a2 = (n < 71) ? w2[(kb + 8) * 71 + n] : 0.f;
        float a3 = (n < 71) ? w2[(kb + 9) * 71 + n] : 0.f;
        uint2 u;
        u.x = pack_h2(a0, a1);
        u.y = pack_h2(a2, a3);
        g_w2f[e] = u;
    }
}

// ---------------------------------------------------------------------------
// fp16 GEMM core: CTA 128x128, K=512, KC=32, double-buffered smem, LDSM.
// A row-major [M][512] (fp32 or fp16); BT fp16 [n][k].
// ---------------------------------------------------------------------------
template<typename TA>
__device__ __forceinline__ void gemm_f16_ctile(
    const TA* __restrict__ A, const __half* __restrict__ BT,
    float (&c)[4][4][4])
{
    extern __shared__ __align__(16) __half smh[];
    __half* As = smh;            // [2][5120]
    __half* Bs = smh + 10240;    // [2][5120]

    const int tid  = threadIdx.x;
    const int lane = tid & 31;
    const int warp = tid >> 5;
    const int mBase = blockIdx.y * 128;
    const int nBase = blockIdx.x * 128;
    const uint32_t smem_addr = smem_u32(smh);

    #pragma unroll
    for (int im = 0; im < 4; im++)
        #pragma unroll
        for (int in = 0; in < 4; in++)
            #pragma unroll
            for (int q = 0; q < 4; q++) c[im][in][q] = 0.f;

    float4 raf[4];
    uint4  rah[2];
    uint4  rbh[2];

    auto ldgA = [&](int kt) {
        if constexpr (sizeof(TA) == 4) {
            #pragma unroll
            for (int it = 0; it < 4; it++) {
                int idx = it * 256 + tid;
                int row = idx >> 3, c4 = idx & 7;
                raf[it] = *(const float4*)((const float*)A +
                    (size_t)(mBase + row) * 512 + kt * 32 + c4 * 4);
            }
        } else {
            #pragma unroll
            for (int it = 0; it < 2; it++) {
                int idx = it * 256 + tid;
                int row = idx >> 2, g = idx & 3;
                rah[it] = *(const uint4*)((const __half*)A +
                    (size_t)(mBase + row) * 512 + kt * 32 + g * 8);
            }
        }
    };
    auto ldgB = [&](int kt) {
        #pragma unroll
        for (int it = 0; it < 2; it++) {
            int idx = it * 256 + tid;
            int row = idx >> 2, g = idx & 3;
            rbh[it] = *(const uint4*)(BT + (size_t)(nBase + row) * 512 + kt * 32 + g * 8);
        }
    };
    auto stsA = [&](int buf) {
        if constexpr (sizeof(TA) == 4) {
            #pragma unroll
            for (int it = 0; it < 4; it++) {
                int idx = it * 256 + tid;
                int row = idx >> 3, c4 = idx & 7;
                __half2 h0 = __floats2half2_rn(raf[it].x, raf[it].y);
                __half2 h1 = __floats2half2_rn(raf[it].z, raf[it].w);
                *(__half2*)&As[buf * 5120 + row * 40 + c4 * 4]     = h0;
                *(__half2*)&As[buf * 5120 + row * 40 + c4 * 4 + 2] = h1;
            }
        } else {
            #pragma unroll
            for (int it = 0; it < 2; it++) {
                int idx = it * 256 + tid;
                int row = idx >> 2, g = idx & 3;
                *(uint4*)&As[buf * 5120 + row * 40 + g * 8] = rah[it];
            }
        }
    };
    auto stsB = [&](int buf) {
        #pragma unroll
        for (int it = 0; it < 2; it++) {
            int idx = it * 256 + tid;
            int row = idx >> 2, g = idx & 3;
            *(uint4*)&Bs[buf * 5120 + row * 40 + g * 8] = rbh[it];
        }
    };
    auto compute = [&](int buf) {
        const uint32_t abase = smem_addr + buf * 10240 +
            (((warp & 1) * 64 + (lane & 15)) * 40 + (lane >> 4) * 8) * 2;
        const uint32_t bbase = smem_addr + 20480 + buf * 10240 +
            (((warp >> 1) * 32 + (lane & 7)) * 40 + (lane >> 3) * 8) * 2;
        #pragma unroll
        for (int ks = 0; ks < 2; ks++) {
            unsigned a[4][4], b[4][2];
            #pragma unroll
            for (int mt = 0; mt < 4; mt++) ldsm_x4(a[mt], abase + mt * 1280 + ks * 32);
            #pragma unroll
            for (int nt = 0; nt < 4; nt++) ldsm_x2(b[nt], bbase + nt * 640 + ks * 32);
            #pragma unroll
            for (int im = 0; im < 4; im++)
                #pragma unroll
                for (int in = 0; in < 4; in++)
                    mma_f16(c[im][in], a[im], b[in]);
        }
    };

    ldgA(0); ldgB(0);
    stsA(0); stsB(0);
    __syncthreads();
    #pragma unroll 1
    for (int kt = 0; kt < 16; kt++) {
        const int cur = kt & 1;
        if (kt < 15) { ldgA(kt + 1); ldgB(kt + 1); }
        compute(cur);
        if (kt < 15) { stsA(cur ^ 1); stsB(cur ^ 1); }
        __syncthreads();
    }
}

// ---------------------------------------------------------------------------
// QKV projection (fp16 mma): grid (4, 284, 3).
// Q/K -> fp16 natural [bh][l][dh]; V -> fp16 transposed [bh][dh][l].
// ---------------------------------------------------------------------------
__global__ void __launch_bounds__(256) qkv_gemm_kernel(
    const float* __restrict__ q_in, const float* __restrict__ k_in,
    const float* __restrict__ v_in,
    const float* __restrict__ bq, const float* __restrict__ bk,
    const float* __restrict__ bv)
{
    const float* A; const float* bias; __half* out; float scale;
    if (blockIdx.z == 0)      { A = q_in; bias = bq; out = g_Qh;  scale = 0.125f; }
    else if (blockIdx.z == 1) { A = k_in; bias = bk; out = g_Kh;  scale = 1.0f; }
    else                      { A = v_in; bias = bv; out = g_Vth; scale = 1.0f; }

    float c[4][4][4];
    gemm_f16_ctile<float>(A, g_WT16[blockIdx.z], c);

    const int lane = threadIdx.x & 31, warp = threadIdx.x >> 5;
    const int mBase = blockIdx.y * 128, nBase = blockIdx.x * 128;

    float bv2[4][2];
    #pragma unroll
    for (int in = 0; in < 4; in++) {
        int cg = nBase + (warp >> 1) * 32 + in * 8 + 2 * (lane & 3);
        bv2[in][0] = bias[cg]; bv2[in][1] = bias[cg + 1];
    }

    if (blockIdx.z <= 1) {
        #pragma unroll
        for (int im = 0; im < 4; im++) {
            int rg0 = mBase + (warp & 1) * 64 + im * 16 + (lane >> 2);
            int rg1 = rg0 + 8;
            int b0 = rg0 / 71, l0 = rg0 - b0 * 71;
            int b1 = rg1 / 71, l1 = rg1 - b1 * 71;
            #pragma unroll
            for (int in = 0; in < 4; in++) {
                int cg = nBase + (warp >> 1) * 32 + in * 8 + 2 * (lane & 3);
                int h = cg >> 6, dh = cg & 63;
                *(__half2*)&out[(((size_t)(b0 * 8 + h) * 71 + l0) << 6) + dh] =
                    __floats2half2_rn((c[im][in][0] + bv2[in][0]) * scale,
                                      (c[im][in][1] + bv2[in][1]) * scale);
                *(__half2*)&out[(((size_t)(b1 * 8 + h) * 71 + l1) << 6) + dh] =
                    __floats2half2_rn((c[im][in][2] + bv2[in][0]) * scale,
                                      (c[im][in][3] + bv2[in][1]) * scale);
            }
        }
    } else {
        #pragma unroll
        for (int im = 0; im < 4; im++) {
            int rg0 = mBase + (warp & 1) * 64 + im * 16 + (lane >> 2);
            int rg1 = rg0 + 8;
            int b0 = rg0 / 71, l0 = rg0 - b0 * 71;
            int b1 = rg1 / 71, l1 = rg1 - b1 * 71;
            #pragma unroll
            for (int in = 0; in < 4; in++) {
                int cg = nBase + (warp >> 1) * 32 + in * 8 + 2 * (lane & 3);
                int h = cg >> 6, dh = cg & 63;
                size_t base0 = ((size_t)((b0 * 8 + h) * 64 + dh)) * 71 + l0;
                size_t base1 = ((size_t)((b1 * 8 + h) * 64 + dh)) * 71 + l1;
                out[base0]      = __float2half_rn(c[im][in][0] + bv2[in][0]);
                out[base0 + 71] = __float2half_rn(c[im][in][1] + bv2[in][1]);
                out[base1]      = __float2half_rn(c[im][in][2] + bv2[in][0]);
                out[base1 + 71] = __float2half_rn(c[im][in][3] + bv2[in][1]);
            }
        }
    }
}

// ---------------------------------------------------------------------------
// Output projection (fp16 mma, A = g_attnH): grid (4, 284).
// ---------------------------------------------------------------------------
__global__ void __launch_bounds__(256) out_gemm_kernel(
    float* __restrict__ out, const float* __restrict__ bo)
{
    float c[4][4][4];
    gemm_f16_ctile<__half>(g_attnH, g_WT16[3], c);

    const int lane = threadIdx.x & 31, warp = threadIdx.x >> 5;
    const int mBase = blockIdx.y * 128, nBase = blockIdx.x * 128;

    float bv2[4][2];
    #pragma unroll
    for (int in = 0; in < 4; in++) {
        int cg = nBase + (warp >> 1) * 32 + in * 8 + 2 * (lane & 3);
        bv2[in][0] = bo[cg]; bv2[in][1] = bo[cg + 1];
    }
    #pragma unroll
    for (int im = 0; im < 4; im++) {
        int rg0 = mBase + (warp & 1) * 64 + im * 16 + (lane >> 2);
        int rg1 = rg0 + 8;
        #pragma unroll
        for (int in = 0; in < 4; in++) {
            int cg = nBase + (warp >> 1) * 32 + in * 8 + 2 * (lane & 3);
            float2 v0 = make_float2(c[im][in][0] + bv2[in][0], c[im][in][1] + bv2[in][1]);
            float2 v1 = make_float2(c[im][in][2] + bv2[in][0], c[im][in][3] + bv2[in][1]);
            *(float2*)&out[(size_t)rg0 * 512 + cg] = v0;
            *(float2*)&out[(size_t)rg1 * 512 + cg] = v1;
        }
    }
}

// ---------------------------------------------------------------------------
// fp16 attention stages; weights via fragment-packed coalesced uint2 LDG.
// N=72 = 9 n-tiles: each warp owns base tile w; warps 0..4 also own one
// m-tile (mt = w) of the remainder tile (n = 64..71).
// S: [80 q][88] fp16 row-major (cols 72..79 zero).
// ---------------------------------------------------------------------------

// Stage 1: S = Q @ K^T. A = sQ [80][72] (K=64); B = sK [72][72].
__device__ __forceinline__ void f16_stage1(
    __half* __restrict__ sS, const __half* __restrict__ sQ,
    const __half* __restrict__ sK, int w, int lane)
{
    float acc[5][4] = {};
    float accR[4] = {};
    const bool rem = (w < 5);
    const uint32_t qa = smem_u32(sQ) + ((lane & 15) * 72 + (lane >> 4) * 8) * 2;
    const uint32_t ka = smem_u32(sK) + ((w * 8 + (lane & 7)) * 72 + (lane >> 3) * 8) * 2;
    const uint32_t kaR = smem_u32(sK) + ((64 + (lane & 7)) * 72 + (lane >> 3) * 8) * 2;
    #pragma unroll
    for (int ks = 0; ks < 4; ks++) {
        unsigned bfr[2];
        ldsm_x2(bfr, ka + ks * 32);
        #pragma unroll
        for (int mt = 0; mt < 5; mt++) {
            unsigned afr[4];
            ldsm_x4(afr, qa + mt * (16 * 72 * 2) + ks * 32);
            mma_f16(acc[mt], afr, bfr);
        }
        if (rem) {
            unsigned bR[2], aR[4];
            ldsm_x2(bR, kaR + ks * 32);
            ldsm_x4(aR, qa + w * (16 * 72 * 2) + ks * 32);
            mma_f16(accR, aR, bR);
        }
    }
    {
        const int n0c = w * 8 + 2 * (lane & 3);
        #pragma unroll
        for (int mt = 0; mt < 5; mt++) {
            const int r = mt * 16 + (lane >> 2);
            *(__half2*)&sS[r * 88 + n0c] =
                __floats2half2_rn(acc[mt][0], acc[mt][1]);
            *(__half2*)&sS[(r + 8) * 88 + n0c] =
                __floats2half2_rn(acc[mt][2], acc[mt][3]);
        }
    }
    if (rem) {
        const int n0c = 64 + 2 * (lane & 3);
        const int r = w * 16 + (lane >> 2);
        *(__half2*)&sS[r * 88 + n0c] = __floats2half2_rn(accR[0], accR[1]);
        *(__half2*)&sS[(r + 8) * 88 + n0c] = __floats2half2_rn(accR[2], accR[3]);
    }
}

// Stage 2: H = gelu(S @ w1 + b1). A = sS [80][88] (K=80); B = g_w1f frags.
__device__ __forceinline__ void f16_stage2(
    __half* __restrict__ sH, const __half* __restrict__ sS,
    const float* __restrict__ b1, int w, int lane)
{
    float acc[2][5][4] = {};
    const uint32_t sa = smem_u32(sS) + ((lane & 15) * 88 + (lane >> 4) * 8) * 2;
    const uint2* w1f0 = g_w1f + (size_t)w * 160 + lane;
    const uint2* w1f1 = g_w1f + (size_t)(w + 8) * 160 + lane;
    #pragma unroll
    for (int ks = 0; ks < 5; ks++) {
        unsigned bfr[2][2];
        uint2 u0 = __ldg(w1f0 + ks * 32);
        uint2 u1 = __ldg(w1f1 + ks * 32);
        bfr[0][0] = u0.x; bfr[0][1] = u0.y;
        bfr[1][0] = u1.x; bfr[1][1] = u1.y;
        #pragma unroll
        for (int mt = 0; mt < 5; mt++) {
            unsigned afr[4];
            ldsm_x4(afr, sa + mt * (16 * 88 * 2) + ks * 32);
            mma_f16(acc[0][mt], afr, bfr[0]);
            mma_f16(acc[1][mt], afr, bfr[1]);
        }
    }
    #pragma unroll
    for (int s = 0; s < 2; s++) {
        const int n0c = (w + s * 8) * 8 + 2 * (lane & 3);
        const float bb0 = __ldg(b1 + n0c), bb1 = __ldg(b1 + n0c + 1);
        #pragma unroll
        for (int mt = 0; mt < 5; mt++) {
            const int r = mt * 16 + (lane >> 2);
            *(__half2*)&sH[r * 136 + n0c] =
                __floats2half2_rn(gelu_exact(acc[s][mt][0] + bb0),
                                  gelu_exact(acc[s][mt][1] + bb1));
            *(__half2*)&sH[(r + 8) * 136 + n0c] =
                __floats2half2_rn(gelu_exact(acc[s][mt][2] + bb0),
                                  gelu_exact(acc[s][mt][3] + bb1));
        }
    }
}

// Stage 3: S += H @ w2 + b2. A = sH [80][136] (K=128); B = g_w2f frags.
__device__ __forceinline__ void f16_stage3(
    __half* __restrict__ sS, const __half* __restrict__ sH,
    const float* __restrict__ b2, int w, int lane)
{
    float acc[5][4] = {};
    float accR[4] = {};
    const bool rem = (w < 5);
    const uint32_t ha = smem_u32(sH) + ((lane & 15) * 136 + (lane >> 4) * 8) * 2;
    const uint2* w2f  = g_w2f + (size_t)w * 256 + lane;
    const uint2* w2fR = g_w2f + (size_t)8 * 256 + lane;
    #pragma unroll
    for (int ks = 0; ks < 8; ks++) {
        unsigned bfr[2];
        uint2 u = __ldg(w2f + ks * 32);
        bfr[0] = u.x; bfr[1] = u.y;
        #pragma unroll
        for (int mt = 0; mt < 5; mt++) {
            unsigned afr[4];
            ldsm_x4(afr, ha + mt * (16 * 136 * 2) + ks * 32);
            mma_f16(acc[mt], afr, bfr);
        }
        if (rem) {
            unsigned bR[2], aR[4];
            uint2 uR = __ldg(w2fR + ks * 32);
            bR[0] = uR.x; bR[1] = uR.y;
            ldsm_x4(aR, ha + w * (16 * 136 * 2) + ks * 32);
            mma_f16(accR, aR, bR);
        }
    }
    {
        const int n0c = w * 8 + 2 * (lane & 3);
        const float bb0 = __ldg(b2 + n0c);
        const float bb1 = (n0c + 1 < 71) ? __ldg(b2 + n0c + 1) : 0.f;
        #pragma unroll
        for (int mt = 0; mt < 5; mt++) {
            const int r = mt * 16 + (lane >> 2);
            __half2 o0 = *(__half2*)&sS[r * 88 + n0c];
            __half2 o1 = *(__half2*)&sS[(r + 8) * 88 + n0c];
            *(__half2*)&sS[r * 88 + n0c] =
                __floats2half2_rn(__low2float(o0) + acc[mt][0] + bb0,
                                  __high2float(o0) + acc[mt][1] + bb1);
            *(__half2*)&sS[(r + 8) * 88 + n0c] =
                __floats2half2_rn(__low2float(o1) + acc[mt][2] + bb0,
                                  __high2float(o1) + acc[mt][3] + bb1);
        }
    }
    if (rem) {
        const int n0c = 64 + 2 * (lane & 3);
        const float bb0 = __ldg(b2 + n0c);
        const float bb1 = (n0c + 1 < 71) ? __ldg(b2 + n0c + 1) : 0.f;
        const int r = w * 16 + (lane >> 2);
        __half2 o0 = *(__half2*)&sS[r * 88 + n0c];
        __half2 o1 = *(__half2*)&sS[(r + 8) * 88 + n0c];
        *(__half2*)&sS[r * 88 + n0c] =
            __floats2half2_rn(__low2float(o0) + accR[0] + bb0,
                              __high2float(o0) + accR[1] + bb1);
        *(__half2*)&sS[(r + 8) * 88 + n0c] =
            __floats2half2_rn(__low2float(o1) + accR[2] + bb0,
                              __high2float(o1) + accR[3] + bb1);
    }
}

// ---------------------------------------------------------------------------
// Attention core: ONE head per CTA, 256 threads, fp16 mma + LDSM. Grid 4096.
// smem halfs (17984 = 35968 B): sS [80][88] at 0; union U at 7040.
// ---------------------------------------------------------------------------
__global__ void __launch_bounds__(256, 4) attn_kernel(
    const float* __restrict__ b1, const float* __restrict__ b2)
{
    extern __shared__ __align__(16) __half smA[];
    __half* sS = smA;           // [80][88]
    __half* U  = smA + 7040;

    const int tid  = threadIdx.x;
    const int lane = tid & 31;
    const int w    = tid >> 5;      // 0..7
    const int bh   = blockIdx.x;
    const int bidx = bh >> 3, hidx = bh & 7;

    // ---- fills: Q [l][dh] -> sQ[80][72]; K -> sK[72][72]; zero pads ----
    {
        __half* sQ = U;
        __half* sK = U + 5760;
        const __half2* Qg = (const __half2*)(g_Qh + (size_t)bh * HEAD_ELEMS);
        const __half2* Kg = (const __half2*)(g_Kh + (size_t)bh * HEAD_ELEMS);
        for (int u = tid; u < 71 * 32; u += 256) {
            int l = u >> 5, d2 = (u & 31) << 1;
            *(__half2*)&sQ[l * 72 + d2] = Qg[u];
            *(__half2*)&sK[l * 72 + d2] = Kg[u];
        }
        for (int i = tid; i < 9 * 36; i += 256) {
            int r = 71 + i / 36, c2 = (i % 36) << 1;
            *(unsigned*)&sQ[r * 72 + c2] = 0u;
        }
        if (tid < 36) *(unsigned*)&sK[71 * 72 + tid * 2] = 0u;
        for (int i = tid; i < 80 * 4; i += 256) {
            int r = i >> 2, c = 72 + ((i & 3) << 1);
            *(unsigned*)&sS[r * 88 + c] = 0u;
        }
    }
    __syncthreads();

    f16_stage1(sS, U, U + 5760, w, lane);
    __syncthreads();

    f16_stage2(U, sS, b1, w, lane);
    __syncthreads();

    f16_stage3(sS, U, b2, w, lane);
    __syncthreads();

    // ---- V^T fill into U + warp-per-row softmax over keys ----
    {
        __half* sVt = U;         // [64][88]
        const __half* Vg = g_Vth + (size_t)bh * HEAD_ELEMS;
        for (int i = tid; i < HEAD_ELEMS; i += 256) {
            int dh = i / 71, l = i - dh * 71;
            sVt[dh * 88 + l] = Vg[i];
        }
        for (int i = tid; i < 64 * 9; i += 256) {
            int dh = i / 9, c = 71 + (i - dh * 9);
            sVt[dh * 88 + c] = __half(0.f);
        }
    }
    __syncwarp();
    for (int q = w; q < 71; q += 8) {
        __half* row = sS + q * 88;
        float v0 = __half2float(row[lane]);
        float v1 = (lane + 32 < 71) ? __half2float(row[lane + 32]) : -1e30f;
        float v2 = (lane < 7)       ? __half2float(row[lane + 64]) : -1e30f;
        float m = fmaxf(v0, fmaxf(v1, v2));
        #pragma unroll
        for (int o = 16; o > 0; o >>= 1) m = fmaxf(m, __shfl_xor_sync(0xffffffffu, m, o));
        float e0 = __expf(v0 - m);
        float e1 = (lane + 32 < 71) ? __expf(v1 - m) : 0.f;
        float e2 = (lane < 7)       ? __expf(v2 - m) : 0.f;
        float s = e0 + e1 + e2;
        #pragma unroll
        for (int o = 16; o > 0; o >>= 1) s += __shfl_xor_sync(0xffffffffu, s, o);
        float inv = 1.f / s;
        row[lane] = __float2half_rn(e0 * inv);
        if (lane + 32 < 71) row[lane + 32] = __float2half_rn(e1 * inv);
        if (lane < 7)       row[lane + 64] = __float2half_rn(e2 * inv);
    }
    __syncthreads();

    // ---- PV: attn = P @ V -> g_attnH [m][512] fp16 ----
    {
        const __half* sVt = U;
        float acc[5][4] = {};
        const uint32_t pa = smem_u32(sS) + ((lane & 15) * 88 + (lane >> 4) * 8) * 2;
        const uint32_t va = smem_u32(sVt) + ((w * 8 + (lane & 7)) * 88 + (lane >> 3) * 8) * 2;
        #pragma unroll
        for (int ks = 0; ks < 5; ks++) {
            unsigned bfr[2];
            ldsm_x2(bfr, va + ks * 32);
            #pragma unroll
            for (int mt = 0; mt < 5; mt++) {
                unsigned afr[4];
                ldsm_x4(afr, pa + mt * (16 * 88 * 2) + ks * 32);
                mma_f16(acc[mt], afr, bfr);
            }
        }
        const int n0 = w * 8 + 2 * (lane & 3);
        const int dcol = hidx * 64 + n0;
        #pragma unroll
        for (int mt = 0; mt < 5; mt++) {
            int r = mt * 16 + (lane >> 2);
            if (r < 71) {
                *(__half2*)&g_attnH[((size_t)(bidx * 71 + r)) * 512 + dcol] =
                    __floats2half2_rn(acc[mt][0], acc[mt][1]);
            }
            if (r + 8 < 71) {
                *(__half2*)&g_attnH[((size_t)(bidx * 71 + r + 8)) * 512 + dcol] =
                    __floats2half2_rn(acc[mt][2], acc[mt][3]);
            }
        }
    }
}

// ---------------------------------------------------------------------------
extern "C" void kernel_launch(void* const* d_in, const int* in_sizes, int n_in,
                              void* d_out, int out_size)
{
    const float* query = (const float*)d_in[0];
    const float* key   = (const float*)d_in[1];
    const float* value = (const float*)d_in[2];
    const float* Wq = (const float*)d_in[3];
    const float* bq = (const float*)d_in[4];
    const float* Wk = (const float*)d_in[5];
    const float* bk = (const float*)d_in[6];
    const float* Wv = (const float*)d_in[7];
    const float* bv = (const float*)d_in[8];
    const float* Wo = (const float*)d_in[9];
    const float* bo = (const float*)d_in[10];
    const float* sf_w1 = (const float*)d_in[11];
    const float* sf_b1 = (const float*)d_in[12];
    const float* sf_w2 = (const float*)d_in[13];
    const float* sf_b2 = (const float*)d_in[14];
    float* out = (float*)d_out;

    const int gemm_smem = 40960;
    cudaFuncSetAttribute(qkv_gemm_kernel, cudaFuncAttributeMaxDynamicSharedMemorySize, gemm_smem);
    cudaFuncSetAttribute(out_gemm_kernel, cudaFuncAttributeMaxDynamicSharedMemorySize, gemm_smem);
    const int attn_smem = 17984 * 2;   // 35968 B
    cudaFuncSetAttribute(attn_kernel, cudaFuncAttributeMaxDynamicSharedMemorySize, attn_smem);

    // 1) weight preps (big-weight transpose + MLP fragment pack)
    dim3 gw(16, 16, 4);
    wt16_kernel<<<gw, 256>>>(Wq, Wk, Wv, Wo);
    wfrag_kernel<<<10, 256>>>(sf_w1, sf_w2);

    // 2) QKV projections (fp16 tensor cores)
    dim3 g1(4, 284, 3);
    qkv_gemm_kernel<<<g1, 256, gemm_smem>>>(query, key, value, bq, bk, bv);

    // 3) attention core (fp16 mma + LDSM + fragment-packed weights)
    attn_kernel<<<NHEADS, 256, attn_smem>>>(sf_b1, sf_b2);

    // 4) output projection (fp16 tensor cores)
    dim3 g3(4, 284);
    out_gemm_kernel<<<g3, 256, gemm_smem>>>(out, bo);
}

// round 17
// speedup vs baseline: 3.7421x; 1.1395x over previous
#include <cuda_runtime.h>
#include <cuda_fp16.h>
#include <math.h>
#include <stdint.h>

// Problem constants
#define BB   512
#define LL   71
#define DD   512
#define HH   8
#define DHH  64
#define MROWS (BB * LL)          // 36352 = 284*128
#define NHEADS (BB * HH)         // 4096
#define HEAD_ELEMS (LL * DHH)    // 4544
#define VT_ELEMS (64 * 72)       // 4608 (V^T padded rows of 72)

// ---------------------------------------------------------------------------
// Scratch (static device globals)
// ---------------------------------------------------------------------------
__device__ __half g_WT16[4][DD * DD];        // fp16 transposed weights [n][k]: q,k,v,o
__device__ __half g_Qh[NHEADS * HEAD_ELEMS]; // [bh][l][dh] fp16, pre-scaled by 1/8
__device__ __half g_Kh[NHEADS * HEAD_ELEMS]; // [bh][l][dh] fp16
__device__ __half g_Vth[NHEADS * VT_ELEMS];  // [bh][dh][72] fp16 (transposed, col 71 = 0)
__device__ __half g_attnH[MROWS * DD];       // attn output [m][512] fp16 row-major
// MLP weights pre-packed in mma B-fragment order: uint2 per (n-tile, kstep, lane)
__device__ uint2 g_w1f[16 * 5 * 32];         // w1: 16 n-tiles, 5 k-steps
__device__ uint2 g_w2f[9 * 8 * 32];          // w2: 9 n-tiles, 8 k-steps

__device__ __forceinline__ void mma_f16(float* c, const unsigned* a, const unsigned* b) {
    asm volatile(
        "mma.sync.aligned.m16n8k16.row.col.f32.f16.f16.f32 "
        "{%0,%1,%2,%3}, {%4,%5,%6,%7}, {%8,%9}, {%0,%1,%2,%3};"
        : "+f"(c[0]), "+f"(c[1]), "+f"(c[2]), "+f"(c[3])
        : "r"(a[0]), "r"(a[1]), "r"(a[2]), "r"(a[3]), "r"(b[0]), "r"(b[1]));
}

__device__ __forceinline__ void ldsm_x4(unsigned* r, uint32_t addr) {
    asm volatile("ldmatrix.sync.aligned.m8n8.x4.shared.b16 {%0,%1,%2,%3}, [%4];"
        : "=r"(r[0]), "=r"(r[1]), "=r"(r[2]), "=r"(r[3]) : "r"(addr));
}

__device__ __forceinline__ void ldsm_x2(unsigned* r, uint32_t addr) {
    asm volatile("ldmatrix.sync.aligned.m8n8.x2.shared.b16 {%0,%1}, [%2];"
        : "=r"(r[0]), "=r"(r[1]) : "r"(addr));
}

__device__ __forceinline__ uint32_t smem_u32(const void* p) {
    uint32_t a;
    asm("{ .reg .u64 t; cvta.to.shared.u64 t, %1; cvt.u32.u64 %0, t; }"
        : "=r"(a) : "l"(p));
    return a;
}

__device__ __forceinline__ unsigned pack_h2(float a, float b) {
    __half2 h = __floats2half2_rn(a, b);
    return *reinterpret_cast<unsigned*>(&h);
}

__device__ __forceinline__ float gelu_exact(float x) {
    return 0.5f * x * (1.f + erff(x * 0.70710678118654752f));
}

// ---------------------------------------------------------------------------
// Weight transpose + fp16 cvt: W[k][n] fp32 -> g_WT16[z][n][k] fp16.
// ---------------------------------------------------------------------------
__global__ void __launch_bounds__(256) wt16_kernel(
    const float* __restrict__ w0, const float* __restrict__ w1,
    const float* __restrict__ w2, const float* __restrict__ w3)
{
    __shared__ float t[32][33];
    const float* in = (blockIdx.z == 0) ? w0 : (blockIdx.z == 1) ? w1
                    : (blockIdx.z == 2) ? w2 : w3;
    __half* out = g_WT16[blockIdx.z];
    const int k0 = blockIdx.x * 32, n0 = blockIdx.y * 32;
    const int tx = threadIdx.x & 31, ty = threadIdx.x >> 5;
    #pragma unroll
    for (int j = 0; j < 4; j++)
        t[ty + 8 * j][tx] = in[(size_t)(k0 + ty + 8 * j) * 512 + n0 + tx];
    __syncthreads();
    #pragma unroll
    for (int j = 0; j < 4; j++)
        out[(size_t)(n0 + ty + 8 * j) * 512 + k0 + tx] = __float2half_rn(t[tx][ty + 8 * j]);
}

// ---------------------------------------------------------------------------
// MLP weight fragment packer (bit-identical values to prior rounds).
// ---------------------------------------------------------------------------
__global__ void __launch_bounds__(256) wfrag_kernel(
    const float* __restrict__ w1, const float* __restrict__ w2)
{
    int e = blockIdx.x * 256 + threadIdx.x;
    if (e < 16 * 5 * 32) {
        int t = e / 160, r = e - t * 160;
        int ks = r >> 5, lane = r & 31;
        int n = t * 8 + (lane >> 2);
        int kb = ks * 16 + (lane & 3) * 2;
        float a0 = (kb     < 71) ? w1[(kb)     * 128 + n] : 0.f;
        float a1 = (kb + 1 < 71) ? w1[(kb + 1) * 128 + n] : 0.f;
        float a2 = (kb + 8 < 71) ? w1[(kb + 8) * 128 + n] : 0.f;
        float a3 = (kb + 9 < 71) ? w1[(kb + 9) * 128 + n] : 0.f;
        uint2 u;
        u.x = pack_h2(a0, a1);
        u.y = pack_h2(a2, a3);
        g_w1f[e] = u;
    }
    if (e < 9 * 8 * 32) {
        int t = e >> 8, r = e & 255;
        int ks = r >> 5, lane = r & 31;
        int n = t * 8 + (lane >> 2);
        int kb = ks * 16 + (lane & 3) * 2;
        float a0 = (n < 71) ? w2[(kb)     * 71 + n] : 0.f;
        float a1 = (n < 71) ? w2[(kb + 1) * 71 + n] : 0.f;
        float a2 = (n < 71) ? w2[(kb + 8) * 71 + n] : 0.f;
        float a3 = (n < 71) ? w2[(kb + 9) * 71 + n] : 0.f;
        uint2 u;
        u.x = pack_h2(a0, a1);
        u.y = pack_h2(a2, a3);
        g_w2f[e] = u;
    }
}

// ---------------------------------------------------------------------------
// fp16 GEMM core: CTA 128x128, K=512, KC=32, double-buffered smem, LDSM.
// A row-major [M][512] (fp32 or fp16); BT fp16 [n][k].
// ---------------------------------------------------------------------------
template<typename TA>
__device__ __forceinline__ void gemm_f16_ctile(
    const TA* __restrict__ A, const __half* __restrict__ BT,
    float (&c)[4][4][4])
{
    extern __shared__ __align__(16) __half smh[];
    __half* As = smh;            // [2][5120]
    __half* Bs = smh + 10240;    // [2][5120]

    const int tid  = threadIdx.x;
    const int lane = tid & 31;
    const int warp = tid >> 5;
    const int mBase = blockIdx.y * 128;
    const int nBase = blockIdx.x * 128;
    const uint32_t smem_addr = smem_u32(smh);

    #pragma unroll
    for (int im = 0; im < 4; im++)
        #pragma unroll
        for (int in = 0; in < 4; in++)
            #pragma unroll
            for (int q = 0; q < 4; q++) c[im][in][q] = 0.f;

    float4 raf[4];
    uint4  rah[2];
    uint4  rbh[2];

    auto ldgA = [&](int kt) {
        if constexpr (sizeof(TA) == 4) {
            #pragma unroll
            for (int it = 0; it < 4; it++) {
                int idx = it * 256 + tid;
                int row = idx >> 3, c4 = idx & 7;
                raf[it] = *(const float4*)((const float*)A +
                    (size_t)(mBase + row) * 512 + kt * 32 + c4 * 4);
            }
        } else {
            #pragma unroll
            for (int it = 0; it < 2; it++) {
                int idx = it * 256 + tid;
                int row = idx >> 2, g = idx & 3;
                rah[it] = *(const uint4*)((const __half*)A +
                    (size_t)(mBase + row) * 512 + kt * 32 + g * 8);
            }
        }
    };
    auto ldgB = [&](int kt) {
        #pragma unroll
        for (int it = 0; it < 2; it++) {
            int idx = it * 256 + tid;
            int row = idx >> 2, g = idx & 3;
            rbh[it] = *(const uint4*)(BT + (size_t)(nBase + row) * 512 + kt * 32 + g * 8);
        }
    };
    auto stsA = [&](int buf) {
        if constexpr (sizeof(TA) == 4) {
            #pragma unroll
            for (int it = 0; it < 4; it++) {
                int idx = it * 256 + tid;
                int row = idx >> 3, c4 = idx & 7;
                __half2 h0 = __floats2half2_rn(raf[it].x, raf[it].y);
                __half2 h1 = __floats2half2_rn(raf[it].z, raf[it].w);
                *(__half2*)&As[buf * 5120 + row * 40 + c4 * 4]     = h0;
                *(__half2*)&As[buf * 5120 + row * 40 + c4 * 4 + 2] = h1;
            }
        } else {
            #pragma unroll
            for (int it = 0; it < 2; it++) {
                int idx = it * 256 + tid;
                int row = idx >> 2, g = idx & 3;
                *(uint4*)&As[buf * 5120 + row * 40 + g * 8] = rah[it];
            }
        }
    };
    auto stsB = [&](int buf) {
        #pragma unroll
        for (int it = 0; it < 2; it++) {
            int idx = it * 256 + tid;
            int row = idx >> 2, g = idx & 3;
            *(uint4*)&Bs[buf * 5120 + row * 40 + g * 8] = rbh[it];
        }
    };
    auto compute = [&](int buf) {
        const uint32_t abase = smem_addr + buf * 10240 +
            (((warp & 1) * 64 + (lane & 15)) * 40 + (lane >> 4) * 8) * 2;
        const uint32_t bbase = smem_addr + 20480 + buf * 10240 +
            (((warp >> 1) * 32 + (lane & 7)) * 40 + (lane >> 3) * 8) * 2;
        #pragma unroll
        for (int ks = 0; ks < 2; ks++) {
            unsigned a[4][4], b[4][2];
            #pragma unroll
            for (int mt = 0; mt < 4; mt++) ldsm_x4(a[mt], abase + mt * 1280 + ks * 32);
            #pragma unroll
            for (int nt = 0; nt < 4; nt++) ldsm_x2(b[nt], bbase + nt * 640 + ks * 32);
            #pragma unroll
            for (int im = 0; im < 4; im++)
                #pragma unroll
                for (int in = 0; in < 4; in++)
                    mma_f16(c[im][in], a[im], b[in]);
        }
    };

    ldgA(0); ldgB(0);
    stsA(0); stsB(0);
    __syncthreads();
    #pragma unroll 1
    for (int kt = 0; kt < 16; kt++) {
        const int cur = kt & 1;
        if (kt < 15) { ldgA(kt + 1); ldgB(kt + 1); }
        compute(cur);
        if (kt < 15) { stsA(cur ^ 1); stsB(cur ^ 1); }
        __syncthreads();
    }
}

// ---------------------------------------------------------------------------
// QKV projection (fp16 mma): grid (4, 284, 3).
// Epilogue: stage biased C tile into smem, then coalesced stores.
// Q/K -> fp16 [bh][l][dh] (contiguous 128B runs); V -> [bh][dh][72] padded.
// ---------------------------------------------------------------------------
__global__ void __launch_bounds__(256) qkv_gemm_kernel(
    const float* __restrict__ q_in, const float* __restrict__ k_in,
    const float* __restrict__ v_in,
    const float* __restrict__ bq, const float* __restrict__ bk,
    const float* __restrict__ bv)
{
    extern __shared__ __align__(16) __half sC[];
    const float* A; const float* bias; __half* out; float scale;
    if (blockIdx.z == 0)      { A = q_in; bias = bq; out = g_Qh;  scale = 0.125f; }
    else if (blockIdx.z == 1) { A = k_in; bias = bk; out = g_Kh;  scale = 1.0f; }
    else                      { A = v_in; bias = bv; out = g_Vth; scale = 1.0f; }

    float c[4][4][4];
    gemm_f16_ctile<float>(A, g_WT16[blockIdx.z], c);

    const int tid = threadIdx.x;
    const int lane = tid & 31, warp = tid >> 5;
    const int mBase = blockIdx.y * 128, nBase = blockIdx.x * 128;

    float bv2[4][2];
    #pragma unroll
    for (int in = 0; in < 4; in++) {
        int cg = nBase + (warp >> 1) * 32 + in * 8 + 2 * (lane & 3);
        bv2[in][0] = bias[cg]; bv2[in][1] = bias[cg + 1];
    }

    // stage (c + bias) * scale into sC [128][136] fp16 (conflict-free half2 STS)
    #pragma unroll
    for (int im = 0; im < 4; im++) {
        const int r0 = (warp & 1) * 64 + im * 16 + (lane >> 2);
        #pragma unroll
        for (int in = 0; in < 4; in++) {
            const int cg = (warp >> 1) * 32 + in * 8 + 2 * (lane & 3);
            *(__half2*)&sC[r0 * 136 + cg] = __floats2half2_rn(
                (c[im][in][0] + bv2[in][0]) * scale,
                (c[im][in][1] + bv2[in][1]) * scale);
            *(__half2*)&sC[(r0 + 8) * 136 + cg] = __floats2half2_rn(
                (c[im][in][2] + bv2[in][0]) * scale,
                (c[im][in][3] + bv2[in][1]) * scale);
        }
    }
    __syncthreads();

    if (blockIdx.z <= 1) {
        // Q/K: 128 rows x 2 head-segments, each 64 halfs = 8 uint4 contiguous
        #pragma unroll
        for (int it = 0; it < 8; it++) {
            int idx = it * 256 + tid;
            int seg = idx >> 3, j = idx & 7;
            int row = seg >> 1, hc = seg & 1;
            int m = mBase + row;
            int b = m / 71, l = m - b * 71;
            int h = (nBase >> 6) + hc;
            uint4 v = *(uint4*)&sC[row * 136 + hc * 64 + j * 8];
            *(uint4*)&out[(((size_t)(b * 8 + h) * 71 + l) << 6) + j * 8] = v;
        }
    } else {
        // V transposed: dest row (bh, dh) stride 72; lane -> l contiguous.
        const int mrow = tid & 127;
        const int m = mBase + mrow;
        const int b = m / 71, l = m - b * 71;
        #pragma unroll 8
        for (int it = 0; it < 64; it++) {
            int col = it * 2 + (tid >> 7);
            int gcol = nBase + col;
            int h = gcol >> 6, dh = gcol & 63;
            __half v = sC[mrow * 136 + col];
            size_t d = ((size_t)((b * 8 + h) * 64 + dh)) * 72 + l;
            out[d] = v;
            if (l == 70) out[d + 1] = __half(0.f);   // zero pad col 71
        }
    }
}

// ---------------------------------------------------------------------------
// Output projection (fp16 mma, A = g_attnH): grid (4, 284).
// ---------------------------------------------------------------------------
__global__ void __launch_bounds__(256) out_gemm_kernel(
    float* __restrict__ out, const float* __restrict__ bo)
{
    float c[4][4][4];
    gemm_f16_ctile<__half>(g_attnH, g_WT16[3], c);

    const int lane = threadIdx.x & 31, warp = threadIdx.x >> 5;
    const int mBase = blockIdx.y * 128, nBase = blockIdx.x * 128;

    float bv2[4][2];
    #pragma unroll
    for (int in = 0; in < 4; in++) {
        int cg = nBase + (warp >> 1) * 32 + in * 8 + 2 * (lane & 3);
        bv2[in][0] = bo[cg]; bv2[in][1] = bo[cg + 1];
    }
    #pragma unroll
    for (int im = 0; im < 4; im++) {
        int rg0 = mBase + (warp & 1) * 64 + im * 16 + (lane >> 2);
        int rg1 = rg0 + 8;
        #pragma unroll
        for (int in = 0; in < 4; in++) {
            int cg = nBase + (warp >> 1) * 32 + in * 8 + 2 * (lane & 3);
            float2 v0 = make_float2(c[im][in][0] + bv2[in][0], c[im][in][1] + bv2[in][1]);
            float2 v1 = make_float2(c[im][in][2] + bv2[in][0], c[im][in][3] + bv2[in][1]);
            *(float2*)&out[(size_t)rg0 * 512 + cg] = v0;
            *(float2*)&out[(size_t)rg1 * 512 + cg] = v1;
        }
    }
}

// ---------------------------------------------------------------------------
// fp16 attention stages (unchanged math from R16; bit-identical results).
// ---------------------------------------------------------------------------
__device__ __forceinline__ void f16_stage1(
    __half* __restrict__ sS, const __half* __restrict__ sQ,
    const __half* __restrict__ sK, int w, int lane)
{
    float acc[5][4] = {};
    float accR[4] = {};
    const bool rem = (w < 5);
    const uint32_t qa = smem_u32(sQ) + ((lane & 15) * 72 + (lane >> 4) * 8) * 2;
    const uint32_t ka = smem_u32(sK) + ((w * 8 + (lane & 7)) * 72 + (lane >> 3) * 8) * 2;
    const uint32_t kaR = smem_u32(sK) + ((64 + (lane & 7)) * 72 + (lane >> 3) * 8) * 2;
    #pragma unroll
    for (int ks = 0; ks < 4; ks++) {
        unsigned bfr[2];
        ldsm_x2(bfr, ka + ks * 32);
        #pragma unroll
        for (int mt = 0; mt < 5; mt++) {
            unsigned afr[4];
            ldsm_x4(afr, qa + mt * (16 * 72 * 2) + ks * 32);
            mma_f16(acc[mt], afr, bfr);
        }
        if (rem) {
            unsigned bR[2], aR[4];
            ldsm_x2(bR, kaR + ks * 32);
            ldsm_x4(aR, qa + w * (16 * 72 * 2) + ks * 32);
            mma_f16(accR, aR, bR);
        }
    }
    {
        const int n0c = w * 8 + 2 * (lane & 3);
        #pragma unroll
        for (int mt = 0; mt < 5; mt++) {
            const int r = mt * 16 + (lane >> 2);
            *(__half2*)&sS[r * 88 + n0c] =
                __floats2half2_rn(acc[mt][0], acc[mt][1]);
            *(__half2*)&sS[(r + 8) * 88 + n0c] =
                __floats2half2_rn(acc[mt][2], acc[mt][3]);
        }
    }
    if (rem) {
        const int n0c = 64 + 2 * (lane & 3);
        const int r = w * 16 + (lane >> 2);
        *(__half2*)&sS[r * 88 + n0c] = __floats2half2_rn(accR[0], accR[1]);
        *(__half2*)&sS[(r + 8) * 88 + n0c] = __floats2half2_rn(accR[2], accR[3]);
    }
}

__device__ __forceinline__ void f16_stage2(
    __half* __restrict__ sH, const __half* __restrict__ sS,
    const float* __restrict__ b1, int w, int lane)
{
    float acc[2][5][4] = {};
    const uint32_t sa = smem_u32(sS) + ((lane & 15) * 88 + (lane >> 4) * 8) * 2;
    const uint2* w1f0 = g_w1f + (size_t)w * 160 + lane;
    const uint2* w1f1 = g_w1f + (size_t)(w + 8) * 160 + lane;
    #pragma unroll
    for (int ks = 0; ks < 5; ks++) {
        unsigned bfr[2][2];
        uint2 u0 = __ldg(w1f0 + ks * 32);
        uint2 u1 = __ldg(w1f1 + ks * 32);
        bfr[0][0] = u0.x; bfr[0][1] = u0.y;
        bfr[1][0] = u1.x; bfr[1][1] = u1.y;
        #pragma unroll
        for (int mt = 0; mt < 5; mt++) {
            unsigned afr[4];
            ldsm_x4(afr, sa + mt * (16 * 88 * 2) + ks * 32);
            mma_f16(acc[0][mt], afr, bfr[0]);
            mma_f16(acc[1][mt], afr, bfr[1]);
        }
    }
    #pragma unroll
    for (int s = 0; s < 2; s++) {
        const int n0c = (w + s * 8) * 8 + 2 * (lane & 3);
        const float bb0 = __ldg(b1 + n0c), bb1 = __ldg(b1 + n0c + 1);
        #pragma unroll
        for (int mt = 0; mt < 5; mt++) {
            const int r = mt * 16 + (lane >> 2);
            *(__half2*)&sH[r * 136 + n0c] =
                __floats2half2_rn(gelu_exact(acc[s][mt][0] + bb0),
                                  gelu_exact(acc[s][mt][1] + bb1));
            *(__half2*)&sH[(r + 8) * 136 + n0c] =
                __floats2half2_rn(gelu_exact(acc[s][mt][2] + bb0),
                                  gelu_exact(acc[s][mt][3] + bb1));
        }
    }
}

__device__ __forceinline__ void f16_stage3(
    __half* __restrict__ sS, const __half* __restrict__ sH,
    const float* __restrict__ b2, int w, int lane)
{
    float acc[5][4] = {};
    float accR[4] = {};
    const bool rem = (w < 5);
    const uint32_t ha = smem_u32(sH) + ((lane & 15) * 136 + (lane >> 4) * 8) * 2;
    const uint2* w2f  = g_w2f + (size_t)w * 256 + lane;
    const uint2* w2fR = g_w2f + (size_t)8 * 256 + lane;
    #pragma unroll
    for (int ks = 0; ks < 8; ks++) {
        unsigned bfr[2];
        uint2 u = __ldg(w2f + ks * 32);
        bfr[0] = u.x; bfr[1] = u.y;
        #pragma unroll
        for (int mt = 0; mt < 5; mt++) {
            unsigned afr[4];
            ldsm_x4(afr, ha + mt * (16 * 136 * 2) + ks * 32);
            mma_f16(acc[mt], afr, bfr);
        }
        if (rem) {
            unsigned bR[2], aR[4];
            uint2 uR = __ldg(w2fR + ks * 32);
            bR[0] = uR.x; bR[1] = uR.y;
            ldsm_x4(aR, ha + w * (16 * 136 * 2) + ks * 32);
            mma_f16(accR, aR, bR);
        }
    }
    {
        const int n0c = w * 8 + 2 * (lane & 3);
        const float bb0 = __ldg(b2 + n0c);
        const float bb1 = (n0c + 1 < 71) ? __ldg(b2 + n0c + 1) : 0.f;
        #pragma unroll
        for (int mt = 0; mt < 5; mt++) {
            const int r = mt * 16 + (lane >> 2);
            __half2 o0 = *(__half2*)&sS[r * 88 + n0c];
            __half2 o1 = *(__half2*)&sS[(r + 8) * 88 + n0c];
            *(__half2*)&sS[r * 88 + n0c] =
                __floats2half2_rn(__low2float(o0) + acc[mt][0] + bb0,
                                  __high2float(o0) + acc[mt][1] + bb1);
            *(__half2*)&sS[(r + 8) * 88 + n0c] =
                __floats2half2_rn(__low2float(o1) + acc[mt][2] + bb0,
                                  __high2float(o1) + acc[mt][3] + bb1);
        }
    }
    if (rem) {
        const int n0c = 64 + 2 * (lane & 3);
        const float bb0 = __ldg(b2 + n0c);
        const float bb1 = (n0c + 1 < 71) ? __ldg(b2 + n0c + 1) : 0.f;
        const int r = w * 16 + (lane >> 2);
        __half2 o0 = *(__half2*)&sS[r * 88 + n0c];
        __half2 o1 = *(__half2*)&sS[(r + 8) * 88 + n0c];
        *(__half2*)&sS[r * 88 + n0c] =
            __floats2half2_rn(__low2float(o0) + accR[0] + bb0,
                              __high2float(o0) + accR[1] + bb1);
        *(__half2*)&sS[(r + 8) * 88 + n0c] =
            __floats2half2_rn(__low2float(o1) + accR[2] + bb0,
                              __high2float(o1) + accR[3] + bb1);
    }
}

// ---------------------------------------------------------------------------
// Attention core: ONE head per CTA, 256 threads, fp16 mma + LDSM. Grid 4096.
// smem halfs (23616 = 47232 B): sS [80][88] at 0; U at 7040 (sQ+sK / sH);
// sVt [64][88] at 17984 (dedicated, filled up-front).
// ---------------------------------------------------------------------------
__global__ void __launch_bounds__(256, 4) attn_kernel(
    const float* __restrict__ b1, const float* __restrict__ b2)
{
    extern __shared__ __align__(16) __half smA[];
    __half* sS  = smA;            // [80][88]
    __half* U   = smA + 7040;     // sQ [80][72] + sK [72][72] | sH [80][136]
    __half* sVt = smA + 17984;    // [64][88]

    const int tid  = threadIdx.x;
    const int lane = tid & 31;
    const int w    = tid >> 5;      // 0..7
    const int bh   = blockIdx.x;
    const int bidx = bh >> 3, hidx = bh & 7;

    // ---- vectorized fills: Q, K, V^T + zero pads ----
    {
        __half* sQ = U;
        __half* sK = U + 5760;
        const uint4* Qg = (const uint4*)(g_Qh + (size_t)bh * HEAD_ELEMS);
        const uint4* Kg = (const uint4*)(g_Kh + (size_t)bh * HEAD_ELEMS);
        const uint4* Vg = (const uint4*)(g_Vth + (size_t)bh * VT_ELEMS);
        for (int i = tid; i < 568; i += 256) {        // 71 rows x 8 uint4
            int rr = i >> 3, g = i & 7;
            *(uint4*)&sQ[rr * 72 + g * 8] = Qg[i];
            *(uint4*)&sK[rr * 72 + g * 8] = Kg[i];
        }
        for (int i = tid; i < 576; i += 256) {        // 64 rows x 9 uint4
            int dh = i / 9, g = i - dh * 9;
            *(uint4*)&sVt[dh * 88 + g * 8] = Vg[i];
        }
        for (int i = tid; i < 324; i += 256) {        // sQ rows 71..79 zero
            int r = 71 + i / 36, c2 = (i % 36) * 2;
            *(unsigned*)&sQ[r * 72 + c2] = 0u;
        }
        if (tid < 36) *(unsigned*)&sK[71 * 72 + tid * 2] = 0u;   // sK row 71
        if (tid < 256) {                              // sVt cols 72..79 zero
            int dh = tid >> 2, cc = 72 + ((tid & 3) << 1);
            *(unsigned*)&sVt[dh * 88 + cc] = 0u;
        }
        for (int i = tid; i < 320; i += 256) {        // sS cols 72..79 zero
            int r = i >> 2, cc = 72 + ((i & 3) << 1);
            *(unsigned*)&sS[r * 88 + cc] = 0u;
        }
    }
    __syncthreads();

    f16_stage1(sS, U, U + 5760, w, lane);
    __syncthreads();

    f16_stage2(U, sS, b1, w, lane);
    __syncthreads();

    f16_stage3(sS, U, b2, w, lane);
    __syncthreads();

    // ---- warp-per-row softmax over keys (V already resident) ----
    for (int q = w; q < 71; q += 8) {
        __half* row = sS + q * 88;
        float v0 = __half2float(row[lane]);
        float v1 = (lane + 32 < 71) ? __half2float(row[lane + 32]) : -1e30f;
        float v2 = (lane < 7)       ? __half2float(row[lane + 64]) : -1e30f;
        float m = fmaxf(v0, fmaxf(v1, v2));
        #pragma unroll
        for (int o = 16; o > 0; o >>= 1) m = fmaxf(m, __shfl_xor_sync(0xffffffffu, m, o));
        float e0 = __expf(v0 - m);
        float e1 = (lane + 32 < 71) ? __expf(v1 - m) : 0.f;
        float e2 = (lane < 7)       ? __expf(v2 - m) : 0.f;
        float s = e0 + e1 + e2;
        #pragma unroll
        for (int o = 16; o > 0; o >>= 1) s += __shfl_xor_sync(0xffffffffu, s, o);
        float inv = 1.f / s;
        row[lane] = __float2half_rn(e0 * inv);
        if (lane + 32 < 71) row[lane + 32] = __float2half_rn(e1 * inv);
        if (lane < 7)       row[lane + 64] = __float2half_rn(e2 * inv);
    }
    __syncthreads();

    // ---- PV: attn = P @ V -> g_attnH [m][512] fp16 ----
    {
        float acc[5][4] = {};
        const uint32_t pa = smem_u32(sS) + ((lane & 15) * 88 + (lane >> 4) * 8) * 2;
        const uint32_t va = smem_u32(sVt) + ((w * 8 + (lane & 7)) * 88 + (lane >> 3) * 8) * 2;
        #pragma unroll
        for (int ks = 0; ks < 5; ks++) {
            unsigned bfr[2];
            ldsm_x2(bfr, va + ks * 32);
            #pragma unroll
            for (int mt = 0; mt < 5; mt++) {
                unsigned afr[4];
                ldsm_x4(afr, pa + mt * (16 * 88 * 2) + ks * 32);
                mma_f16(acc[mt], afr, bfr);
            }
        }
        const int n0 = w * 8 + 2 * (lane & 3);
        const int dcol = hidx * 64 + n0;
        #pragma unroll
        for (int mt = 0; mt < 5; mt++) {
            int r = mt * 16 + (lane >> 2);
            if (r < 71) {
                *(__half2*)&g_attnH[((size_t)(bidx * 71 + r)) * 512 + dcol] =
                    __floats2half2_rn(acc[mt][0], acc[mt][1]);
            }
            if (r + 8 < 71) {
                *(__half2*)&g_attnH[((size_t)(bidx * 71 + r + 8)) * 512 + dcol] =
                    __floats2half2_rn(acc[mt][2], acc[mt][3]);
            }
        }
    }
}

// ---------------------------------------------------------------------------
extern "C" void kernel_launch(void* const* d_in, const int* in_sizes, int n_in,
                              void* d_out, int out_size)
{
    const float* query = (const float*)d_in[0];
    const float* key   = (const float*)d_in[1];
    const float* value = (const float*)d_in[2];
    const float* Wq = (const float*)d_in[3];
    const float* bq = (const float*)d_in[4];
    const float* Wk = (const float*)d_in[5];
    const float* bk = (const float*)d_in[6];
    const float* Wv = (const float*)d_in[7];
    const float* bv = (const float*)d_in[8];
    const float* Wo = (const float*)d_in[9];
    const float* bo = (const float*)d_in[10];
    const float* sf_w1 = (const float*)d_in[11];
    const float* sf_b1 = (const float*)d_in[12];
    const float* sf_w2 = (const float*)d_in[13];
    const float* sf_b2 = (const float*)d_in[14];
    float* out = (float*)d_out;

    const int gemm_smem = 40960;
    cudaFuncSetAttribute(qkv_gemm_kernel, cudaFuncAttributeMaxDynamicSharedMemorySize, gemm_smem);
    cudaFuncSetAttribute(out_gemm_kernel, cudaFuncAttributeMaxDynamicSharedMemorySize, gemm_smem);
    const int attn_smem = 23616 * 2;   // 47232 B
    cudaFuncSetAttribute(attn_kernel, cudaFuncAttributeMaxDynamicSharedMemorySize, attn_smem);

    // 1) weight preps (big-weight transpose + MLP fragment pack)
    dim3 gw(16, 16, 4);
    wt16_kernel<<<gw, 256>>>(Wq, Wk, Wv, Wo);
    wfrag_kernel<<<10, 256>>>(sf_w1, sf_w2);

    // 2) QKV projections (fp16 tensor cores, staged coalesced epilogues)
    dim3 g1(4, 284, 3);
    qkv_gemm_kernel<<<g1, 256, gemm_smem>>>(query, key, value, bq, bk, bv);

    // 3) attention core (fp16 mma + LDSM, V resident up-front)
    attn_kernel<<<NHEADS, 256, attn_smem>>>(sf_b1, sf_b2);

    // 4) output projection (fp16 tensor cores)
    dim3 g3(4, 284);
    out_gemm_kernel<<<g3, 256, gemm_smem>>>(out, bo);
}